// round 1
// baseline (speedup 1.0000x reference)
#include <cuda_runtime.h>
#include <cuda_bf16.h>
#include <math.h>

// ---------------- problem constants ----------------
#define BB   1
#define NN   4096
#define BSZ  64          // block size (BS)
#define HH   12
#define DHH  64
#define DD   768         // H*DH
#define LL   4
#define FFD  3072
#define MM   64          // N/BS
#define RR   3
#define NEGV (-10000.0f)

// ---------------- device scratch (no allocs allowed) ----------------
__device__ float g_x [NN * DD];
__device__ float g_t [NN * DD];   // embed raw / residual temp
__device__ float g_q [NN * DD];
__device__ float g_k [NN * DD];
__device__ float g_v [NN * DD];
__device__ float g_a [NN * DD];
__device__ float g_f1[NN * FFD];
__device__ int   g_klist [HH * MM * 64];
__device__ int   g_kcount[HH * MM];

// ---------------- helpers ----------------
__device__ __forceinline__ float block_reduce(float val, bool is_max, float* rbuf) {
    int lane = threadIdx.x & 31;
    int w    = threadIdx.x >> 5;
    #pragma unroll
    for (int o = 16; o; o >>= 1) {
        float other = __shfl_xor_sync(0xffffffffu, val, o);
        val = is_max ? fmaxf(val, other) : (val + other);
    }
    if (lane == 0) rbuf[w] = val;
    __syncthreads();
    if (threadIdx.x == 0) {
        int nw = (blockDim.x + 31) >> 5;
        float r = rbuf[0];
        for (int i = 1; i < nw; i++) r = is_max ? fmaxf(r, rbuf[i]) : (r + rbuf[i]);
        rbuf[0] = r;
    }
    __syncthreads();
    float res = rbuf[0];
    __syncthreads();
    return res;
}

// ---------------- embedding ----------------
__global__ void embed_kernel(const int* __restrict__ ids,
                             const float* __restrict__ ew,
                             const float* __restrict__ ep,
                             float* __restrict__ out) {
    int t = blockIdx.x;
    int id = ids[t];
    const float* wr = ew + (size_t)id * DD;
    const float* pr = ep + (size_t)t * DD;
    float* o = out + (size_t)t * DD;
    for (int d = threadIdx.x; d < DD; d += blockDim.x)
        o[d] = wr[d] + pr[d];
}

// ---------------- layernorm (optionally with residual add) ----------------
__global__ void ln_kernel(const float* __restrict__ A,
                          const float* __restrict__ Bres,  // may be null
                          const float* __restrict__ g,
                          const float* __restrict__ b,
                          float* __restrict__ out) {
    __shared__ float s[DD];
    __shared__ float rbuf[8];
    int t = blockIdx.x;
    int tid = threadIdx.x;
    const float* ar = A + (size_t)t * DD;
    const float* br = Bres ? (Bres + (size_t)t * DD) : nullptr;
    float lsum = 0.f;
    for (int d = tid; d < DD; d += blockDim.x) {
        float v = ar[d];
        if (br) v += br[d];
        s[d] = v;
        lsum += v;
    }
    float mu = block_reduce(lsum, false, rbuf) * (1.0f / DD);
    float lvar = 0.f;
    for (int d = tid; d < DD; d += blockDim.x) {
        float dv = s[d] - mu;
        lvar += dv * dv;
    }
    float var = block_reduce(lvar, false, rbuf) * (1.0f / DD);
    float inv = rsqrtf(var + 1e-5f);
    float* o = out + (size_t)t * DD;
    for (int d = tid; d < DD; d += blockDim.x)
        o[d] = (s[d] - mu) * inv * g[d] + b[d];
}

// ---------------- GEMM: C = A(M x K) @ W(K x N) + bias, optional exact GELU ----
// tiles: 64x64x16, 256 threads, 4x4 per thread
__global__ void gemm_kernel(const float* __restrict__ A,
                            const float* __restrict__ W,
                            const float* __restrict__ bias,
                            float* __restrict__ C,
                            int Nd, int K, int act) {
    __shared__ float As[16][64];
    __shared__ float Bs[16][64];
    int tid = threadIdx.x;
    int tx = tid & 15;
    int ty = tid >> 4;
    int m0 = blockIdx.y * 64;
    int n0 = blockIdx.x * 64;

    float acc[4][4] = {};
    for (int k0 = 0; k0 < K; k0 += 16) {
        #pragma unroll
        for (int i = 0; i < 4; i++) {
            int idx = tid + i * 256;
            int m  = idx >> 4, kk = idx & 15;
            As[kk][m] = A[(size_t)(m0 + m) * K + (k0 + kk)];
            int kk2 = idx >> 6, n = idx & 63;
            Bs[kk2][n] = W[(size_t)(k0 + kk2) * Nd + (n0 + n)];
        }
        __syncthreads();
        #pragma unroll
        for (int kk = 0; kk < 16; kk++) {
            float a[4], b[4];
            #pragma unroll
            for (int i = 0; i < 4; i++) a[i] = As[kk][ty * 4 + i];
            #pragma unroll
            for (int j = 0; j < 4; j++) b[j] = Bs[kk][tx * 4 + j];
            #pragma unroll
            for (int i = 0; i < 4; i++)
                #pragma unroll
                for (int j = 0; j < 4; j++)
                    acc[i][j] += a[i] * b[j];
        }
        __syncthreads();
    }
    #pragma unroll
    for (int i = 0; i < 4; i++) {
        int row = m0 + ty * 4 + i;
        #pragma unroll
        for (int j = 0; j < 4; j++) {
            int col = n0 + tx * 4 + j;
            float val = acc[i][j] + bias[col];
            if (act) val = 0.5f * val * (1.0f + erff(val * 0.70710678118654752f));
            C[(size_t)row * Nd + col] = val;
        }
    }
}

// ---------------- key-block list builder ----------------
// entry = block_idx | (flag << 8); flag=1 -> mask is mask_q*mask_k (band/rand),
// flag=0 -> mask is mask_k only (static / full-row / first / last).
__global__ void build_klist(const int* __restrict__ rand_attn,
                            int* __restrict__ klist,
                            int* __restrict__ kcount) {
    int idx = blockIdx.x * blockDim.x + threadIdx.x;
    if (idx >= HH * MM) return;
    int h  = idx / MM;
    int qb = idx % MM;
    int* lst = klist + idx * 64;
    int c = 0;
    if (qb == 0 || qb == MM - 1) {
        for (int j = 0; j < MM; j++) lst[c++] = j;            // full row
    } else if (qb == 1) {
        lst[c++] = 0; lst[c++] = 1; lst[c++] = 2; lst[c++] = MM - 1;
        const int* rr = rand_attn + ((size_t)h * (MM - 2) + 0) * RR;
        for (int r = 0; r < RR; r++) lst[c++] = rr[r] | 256;
    } else if (qb == MM - 2) {
        lst[c++] = 0; lst[c++] = MM - 3; lst[c++] = MM - 2; lst[c++] = MM - 1;
        const int* rr = rand_attn + ((size_t)h * (MM - 2) + (MM - 3)) * RR;
        for (int r = 0; r < RR; r++) lst[c++] = rr[r] | 256;
    } else {
        lst[c++] = 0;                                          // first block (key-mask only)
        lst[c++] = (qb - 1) | 256;                             // band (product mask)
        lst[c++] = qb | 256;
        lst[c++] = (qb + 1) | 256;
        const int* rr = rand_attn + ((size_t)h * (MM - 2) + (qb - 1)) * RR;
        for (int r = 0; r < RR; r++) lst[c++] = rr[r] | 256;   // random (product mask)
        lst[c++] = MM - 1;                                     // last block (key-mask only)
    }
    kcount[idx] = c;
}

// ---------------- sparse attention ----------------
// one CTA per (query, qblock, head); 128 threads
__global__ void attn_kernel(const float* __restrict__ q,
                            const float* __restrict__ k,
                            const float* __restrict__ v,
                            const float* __restrict__ mask,
                            const int* __restrict__ klist,
                            const int* __restrict__ kcount,
                            float* __restrict__ out) {
    __shared__ float sc[MM * BSZ];   // up to 4096 scores
    __shared__ float qv[DHH];
    __shared__ int   ents[64];
    __shared__ float rbuf[8];
    __shared__ float obuf[DHH];

    int h  = blockIdx.z;
    int qb = blockIdx.y;
    int qi = blockIdx.x;
    int tid = threadIdx.x;
    int qt = qb * BSZ + qi;
    int lid = h * MM + qb;
    int cnt = kcount[lid];

    if (tid < DHH) qv[tid] = q[(size_t)qt * DD + h * DHH + tid];
    if (tid < cnt) ents[tid] = klist[lid * 64 + tid];
    __syncthreads();

    float maskq = mask[qt];
    int nk = cnt * BSZ;

    // phase 1: scores
    float lmax = -1e30f;
    for (int s = tid; s < nk; s += blockDim.x) {
        int e  = ents[s >> 6];
        int kb = e & 0xff;
        int fl = e >> 8;
        int kt = kb * BSZ + (s & 63);
        const float* kr = k + (size_t)kt * DD + h * DHH;
        float dot = 0.f;
        #pragma unroll
        for (int d = 0; d < DHH; d++) dot += qv[d] * kr[d];
        float mk  = mask[kt];
        float eff = fl ? (maskq * mk) : mk;
        float sv  = dot * 0.125f + (1.0f - eff) * NEGV;
        sc[s] = sv;
        lmax = fmaxf(lmax, sv);
    }
    float mx = block_reduce(lmax, true, rbuf);

    // phase 2: exp + sum
    float lsum = 0.f;
    for (int s = tid; s < nk; s += blockDim.x) {
        float p = expf(sc[s] - mx);
        sc[s] = p;
        lsum += p;
    }
    float sum = block_reduce(lsum, false, rbuf);

    // phase 3: P @ V  (two halves of the key range, combined through smem)
    int d    = tid & 63;
    int half = tid >> 6;
    float acc = 0.f;
    for (int s = half; s < nk; s += 2) {
        int e  = ents[s >> 6];
        int kb = e & 0xff;
        int kt = kb * BSZ + (s & 63);
        acc += sc[s] * v[(size_t)kt * DD + h * DHH + d];
    }
    if (half) obuf[d] = acc;
    __syncthreads();
    if (!half) {
        float o = (acc + obuf[d]) * (maskq / sum);
        out[(size_t)qt * DD + h * DHH + d] = o;
    }
}

// ---------------- host orchestration ----------------
extern "C" void kernel_launch(void* const* d_in, const int* in_sizes, int n_in,
                              void* d_out, int out_size) {
    (void)in_sizes; (void)n_in;
    const int*   ids      = (const int*)  d_in[0];
    const float* mask     = (const float*)d_in[1];
    const int*   rand_attn= (const int*)  d_in[2];
    const float* emb_word = (const float*)d_in[3];
    const float* emb_pos  = (const float*)d_in[4];
    const float* eln_g    = (const float*)d_in[5];
    const float* eln_b    = (const float*)d_in[6];
    const float* Wq = (const float*)d_in[7];  const float* bq = (const float*)d_in[8];
    const float* Wk = (const float*)d_in[9];  const float* bk = (const float*)d_in[10];
    const float* Wv = (const float*)d_in[11]; const float* bv = (const float*)d_in[12];
    const float* Wo = (const float*)d_in[13]; const float* bo = (const float*)d_in[14];
    const float* ln1g = (const float*)d_in[15]; const float* ln1b = (const float*)d_in[16];
    const float* W1 = (const float*)d_in[17]; const float* b1 = (const float*)d_in[18];
    const float* W2 = (const float*)d_in[19]; const float* b2 = (const float*)d_in[20];
    const float* ln2g = (const float*)d_in[21]; const float* ln2b = (const float*)d_in[22];
    float* outp = (float*)d_out;
    (void)out_size;

    float *px, *pt, *pq, *pk, *pv, *pa, *pf1;
    int *pkl, *pkc;
    cudaGetSymbolAddress((void**)&px,  g_x);
    cudaGetSymbolAddress((void**)&pt,  g_t);
    cudaGetSymbolAddress((void**)&pq,  g_q);
    cudaGetSymbolAddress((void**)&pk,  g_k);
    cudaGetSymbolAddress((void**)&pv,  g_v);
    cudaGetSymbolAddress((void**)&pa,  g_a);
    cudaGetSymbolAddress((void**)&pf1, g_f1);
    cudaGetSymbolAddress((void**)&pkl, g_klist);
    cudaGetSymbolAddress((void**)&pkc, g_kcount);

    // embedding + LN
    embed_kernel<<<NN, 256>>>(ids, emb_word, emb_pos, pt);
    ln_kernel<<<NN, 256>>>(pt, nullptr, eln_g, eln_b, px);

    // key lists (depends only on rand_attn)
    build_klist<<<(HH * MM + 127) / 128, 128>>>(rand_attn, pkl, pkc);

    dim3 gProj(DD / 64, NN / 64);     // 12 x 64
    dim3 gF1(FFD / 64, NN / 64);      // 48 x 64
    dim3 gAttn(BSZ, MM, HH);          // 64 x 64 x 12

    for (int i = 0; i < LL; i++) {
        const float* wq = Wq + (size_t)i * DD * DD;
        const float* wk = Wk + (size_t)i * DD * DD;
        const float* wv = Wv + (size_t)i * DD * DD;
        const float* wo = Wo + (size_t)i * DD * DD;
        const float* w1 = W1 + (size_t)i * DD * FFD;
        const float* w2 = W2 + (size_t)i * FFD * DD;

        gemm_kernel<<<gProj, 256>>>(px, wq, bq + (size_t)i * DD, pq, DD, DD, 0);
        gemm_kernel<<<gProj, 256>>>(px, wk, bk + (size_t)i * DD, pk, DD, DD, 0);
        gemm_kernel<<<gProj, 256>>>(px, wv, bv + (size_t)i * DD, pv, DD, DD, 0);

        attn_kernel<<<gAttn, 128>>>(pq, pk, pv, mask, pkl, pkc, pa);

        gemm_kernel<<<gProj, 256>>>(pa, wo, bo + (size_t)i * DD, pt, DD, DD, 0);
        ln_kernel<<<NN, 256>>>(px, pt, ln1g + (size_t)i * DD, ln1b + (size_t)i * DD, px);

        gemm_kernel<<<gF1, 256>>>(px, w1, b1 + (size_t)i * FFD, pf1, FFD, DD, 1);
        gemm_kernel<<<gProj, 256>>>(pf1, w2, b2 + (size_t)i * DD, pt, DD, FFD, 0);

        float* lnout = (i == LL - 1) ? outp : px;
        ln_kernel<<<NN, 256>>>(px, pt, ln2g + (size_t)i * DD, ln2b + (size_t)i * DD, lnout);
    }
}

// round 2
// speedup vs baseline: 2.8493x; 2.8493x over previous
#include <cuda_runtime.h>
#include <cuda_bf16.h>
#include <math.h>

// ---------------- problem constants ----------------
#define NN   4096
#define BSZ  64
#define HH   12
#define DHH  64
#define DD   768
#define LL   4
#define FFD  3072
#define MM   64
#define RR   3
#define NEGV (-10000.0f)
#define APAD 65

// ---------------- device scratch ----------------
__device__ float g_x [NN * DD];
__device__ float g_t [NN * DD];
__device__ float g_q [NN * DD];
__device__ float g_k [NN * DD];
__device__ float g_v [NN * DD];
__device__ float g_a [NN * DD];
__device__ float g_f1[NN * FFD];
__device__ int   g_klist [HH * MM * 64];
__device__ int   g_kcount[HH * MM];

// ---------------- helpers ----------------
__device__ __forceinline__ float block_reduce(float val, bool is_max, float* rbuf) {
    int lane = threadIdx.x & 31;
    int w    = threadIdx.x >> 5;
    #pragma unroll
    for (int o = 16; o; o >>= 1) {
        float other = __shfl_xor_sync(0xffffffffu, val, o);
        val = is_max ? fmaxf(val, other) : (val + other);
    }
    if (lane == 0) rbuf[w] = val;
    __syncthreads();
    if (threadIdx.x == 0) {
        int nw = (blockDim.x + 31) >> 5;
        float r = rbuf[0];
        for (int i = 1; i < nw; i++) r = is_max ? fmaxf(r, rbuf[i]) : (r + rbuf[i]);
        rbuf[0] = r;
    }
    __syncthreads();
    float res = rbuf[0];
    __syncthreads();
    return res;
}

// ---------------- embedding ----------------
__global__ void embed_kernel(const int* __restrict__ ids,
                             const float* __restrict__ ew,
                             const float* __restrict__ ep,
                             float* __restrict__ out) {
    int t = blockIdx.x;
    int id = ids[t];
    const float* wr = ew + (size_t)id * DD;
    const float* pr = ep + (size_t)t * DD;
    float* o = out + (size_t)t * DD;
    for (int d = threadIdx.x; d < DD; d += blockDim.x)
        o[d] = wr[d] + pr[d];
}

// ---------------- layernorm (optional residual) ----------------
__global__ void ln_kernel(const float* __restrict__ A,
                          const float* __restrict__ Bres,
                          const float* __restrict__ g,
                          const float* __restrict__ b,
                          float* __restrict__ out) {
    __shared__ float s[DD];
    __shared__ float rbuf[8];
    int t = blockIdx.x;
    int tid = threadIdx.x;
    const float* ar = A + (size_t)t * DD;
    const float* br = Bres ? (Bres + (size_t)t * DD) : nullptr;
    float lsum = 0.f;
    for (int d = tid; d < DD; d += blockDim.x) {
        float v = ar[d];
        if (br) v += br[d];
        s[d] = v;
        lsum += v;
    }
    float mu = block_reduce(lsum, false, rbuf) * (1.0f / DD);
    float lvar = 0.f;
    for (int d = tid; d < DD; d += blockDim.x) {
        float dv = s[d] - mu;
        lvar += dv * dv;
    }
    float var = block_reduce(lvar, false, rbuf) * (1.0f / DD);
    float inv = rsqrtf(var + 1e-5f);
    float* o = out + (size_t)t * DD;
    for (int d = tid; d < DD; d += blockDim.x)
        o[d] = (s[d] - mu) * inv * g[d] + b[d];
}

// ---------------- GEMM 128x128x16, 256 threads, 8x8 micro-tile ----------------
__global__ __launch_bounds__(256, 2)
void gemm128(const float* __restrict__ A, const float* __restrict__ W,
             const float* __restrict__ bias, float* __restrict__ C,
             int Nd, int K, int act) {
    __shared__ float As[128][17];
    __shared__ float Bs[16][128];
    int tid = threadIdx.x;
    int tx = tid & 15, ty = tid >> 4;
    int m0 = blockIdx.y * 128, n0 = blockIdx.x * 128;

    float acc[8][8];
    #pragma unroll
    for (int i = 0; i < 8; i++)
        #pragma unroll
        for (int j = 0; j < 8; j++) acc[i][j] = 0.f;

    for (int k0 = 0; k0 < K; k0 += 16) {
        #pragma unroll
        for (int i = 0; i < 2; i++) {
            int idx = tid + i * 256;
            int row = idx >> 2, kq = (idx & 3) << 2;
            float4 va = *(const float4*)(A + (size_t)(m0 + row) * K + k0 + kq);
            As[row][kq + 0] = va.x; As[row][kq + 1] = va.y;
            As[row][kq + 2] = va.z; As[row][kq + 3] = va.w;
        }
        #pragma unroll
        for (int i = 0; i < 2; i++) {
            int idx = tid + i * 256;
            int kk = idx >> 5, nq = (idx & 31) << 2;
            *(float4*)&Bs[kk][nq] =
                *(const float4*)(W + (size_t)(k0 + kk) * Nd + n0 + nq);
        }
        __syncthreads();
        #pragma unroll
        for (int kk = 0; kk < 16; kk++) {
            float a[8], b[8];
            #pragma unroll
            for (int i = 0; i < 8; i++) a[i] = As[ty * 8 + i][kk];
            float4 b0 = *(const float4*)&Bs[kk][tx * 8];
            float4 b1 = *(const float4*)&Bs[kk][tx * 8 + 4];
            b[0] = b0.x; b[1] = b0.y; b[2] = b0.z; b[3] = b0.w;
            b[4] = b1.x; b[5] = b1.y; b[6] = b1.z; b[7] = b1.w;
            #pragma unroll
            for (int i = 0; i < 8; i++)
                #pragma unroll
                for (int j = 0; j < 8; j++)
                    acc[i][j] += a[i] * b[j];
        }
        __syncthreads();
    }
    #pragma unroll
    for (int i = 0; i < 8; i++) {
        int row = m0 + ty * 8 + i;
        #pragma unroll
        for (int j = 0; j < 8; j++) {
            int col = n0 + tx * 8 + j;
            float val = acc[i][j] + bias[col];
            if (act) val = 0.5f * val * (1.0f + erff(val * 0.70710678118654752f));
            C[(size_t)row * Nd + col] = val;
        }
    }
}

// ---------------- key-block list builder ----------------
__global__ void build_klist(const int* __restrict__ rand_attn,
                            int* __restrict__ klist,
                            int* __restrict__ kcount) {
    int idx = blockIdx.x * blockDim.x + threadIdx.x;
    if (idx >= HH * MM) return;
    int h  = idx / MM;
    int qb = idx % MM;
    int* lst = klist + idx * 64;
    int c = 0;
    if (qb == 0 || qb == MM - 1) {
        for (int j = 0; j < MM; j++) lst[c++] = j;
    } else if (qb == 1) {
        lst[c++] = 0; lst[c++] = 1; lst[c++] = 2; lst[c++] = MM - 1;
        const int* rr = rand_attn + ((size_t)h * (MM - 2) + 0) * RR;
        for (int r = 0; r < RR; r++) lst[c++] = rr[r] | 256;
    } else if (qb == MM - 2) {
        lst[c++] = 0; lst[c++] = MM - 3; lst[c++] = MM - 2; lst[c++] = MM - 1;
        const int* rr = rand_attn + ((size_t)h * (MM - 2) + (MM - 3)) * RR;
        for (int r = 0; r < RR; r++) lst[c++] = rr[r] | 256;
    } else {
        lst[c++] = 0;
        lst[c++] = (qb - 1) | 256;
        lst[c++] = qb | 256;
        lst[c++] = (qb + 1) | 256;
        const int* rr = rand_attn + ((size_t)h * (MM - 2) + (qb - 1)) * RR;
        for (int r = 0; r < RR; r++) lst[c++] = rr[r] | 256;
        lst[c++] = MM - 1;
    }
    kcount[idx] = c;
}

// ---------------- flash-style block-sparse attention ----------------
// one CTA per (qblock, head), 256 threads. Online softmax over key blocks.
__global__ __launch_bounds__(256)
void attn_flash(const float* __restrict__ q, const float* __restrict__ k,
                const float* __restrict__ v, const float* __restrict__ mask,
                const int* __restrict__ klist, const int* __restrict__ kcount,
                float* __restrict__ out) {
    extern __shared__ float sm[];
    float* Qs = sm;                    // 64 x APAD
    float* Ks = Qs + 64 * APAD;        // 64 x APAD
    float* Vs = Ks + 64 * APAD;        // 64 x 64
    float* Ss = Vs + 64 * 64;          // 64 x APAD
    float* mq = Ss + 64 * APAD;        // 64
    float* mk = mq + 64;               // 64
    int*   ents = (int*)(mk + 64);     // 64

    int qb = blockIdx.x, h = blockIdx.y;
    int tid = threadIdx.x;
    int lid = h * MM + qb;
    int cnt = kcount[lid];

    if (tid < 64) {
        ents[tid] = klist[lid * 64 + tid];
        mq[tid]   = mask[qb * 64 + tid];
    }
    for (int idx = tid; idx < 64 * 64; idx += 256) {
        int r = idx >> 6, d = idx & 63;
        Qs[r * APAD + d] = q[(size_t)(qb * 64 + r) * DD + h * DHH + d];
    }
    __syncthreads();

    int qown = tid >> 2;
    int seg  = (tid & 3) << 4;
    int ty = tid >> 4, tx = tid & 15;
    float m_run = -1e30f, l_run = 0.f;
    float o[16];
    #pragma unroll
    for (int i = 0; i < 16; i++) o[i] = 0.f;
    float maskq = mq[qown];

    for (int b = 0; b < cnt; b++) {
        int e  = ents[b];
        int kb = e & 0xff;
        int fl = e >> 8;
        for (int idx = tid; idx < 64 * 64; idx += 256) {
            int r = idx >> 6, d = idx & 63;
            size_t gofs = (size_t)(kb * 64 + r) * DD + h * DHH + d;
            Ks[r * APAD + d] = k[gofs];
            Vs[r * 64 + d]   = v[gofs];
        }
        if (tid < 64) mk[tid] = mask[kb * 64 + tid];
        __syncthreads();

        // S = Q K^T (4x4 per thread)
        float acc[4][4];
        #pragma unroll
        for (int i = 0; i < 4; i++)
            #pragma unroll
            for (int j = 0; j < 4; j++) acc[i][j] = 0.f;
        #pragma unroll 8
        for (int kk = 0; kk < 64; kk++) {
            float a[4], bb[4];
            #pragma unroll
            for (int i = 0; i < 4; i++) a[i]  = Qs[(ty * 4 + i) * APAD + kk];
            #pragma unroll
            for (int j = 0; j < 4; j++) bb[j] = Ks[(tx * 4 + j) * APAD + kk];
            #pragma unroll
            for (int i = 0; i < 4; i++)
                #pragma unroll
                for (int j = 0; j < 4; j++)
                    acc[i][j] += a[i] * bb[j];
        }
        #pragma unroll
        for (int i = 0; i < 4; i++) {
            int qq = ty * 4 + i;
            float mqv = mq[qq];
            #pragma unroll
            for (int j = 0; j < 4; j++) {
                int ss = tx * 4 + j;
                float mkv = mk[ss];
                float eff = fl ? (mqv * mkv) : mkv;
                Ss[qq * APAD + ss] = acc[i][j] * 0.125f + (1.0f - eff) * NEGV;
            }
        }
        __syncthreads();

        // online softmax for row qown, segment seg..seg+15
        float lm = -1e30f;
        #pragma unroll
        for (int j = 0; j < 16; j++) lm = fmaxf(lm, Ss[qown * APAD + seg + j]);
        lm = fmaxf(lm, __shfl_xor_sync(0xffffffffu, lm, 1));
        lm = fmaxf(lm, __shfl_xor_sync(0xffffffffu, lm, 2));
        float m_new = fmaxf(m_run, lm);
        float scale = expf(m_run - m_new);
        float lsum = 0.f;
        #pragma unroll
        for (int j = 0; j < 16; j++) {
            float p = expf(Ss[qown * APAD + seg + j] - m_new);
            Ss[qown * APAD + seg + j] = p;
            lsum += p;
        }
        lsum += __shfl_xor_sync(0xffffffffu, lsum, 1);
        lsum += __shfl_xor_sync(0xffffffffu, lsum, 2);
        l_run = l_run * scale + lsum;
        m_run = m_new;
        #pragma unroll
        for (int i = 0; i < 16; i++) o[i] *= scale;
        __syncwarp();

        // O += P V
        #pragma unroll 4
        for (int s = 0; s < 64; s++) {
            float p = Ss[qown * APAD + s];
            const float4* vr = (const float4*)(Vs + s * 64 + seg);
            float4 v0 = vr[0], v1 = vr[1], v2 = vr[2], v3 = vr[3];
            o[0]  += p * v0.x; o[1]  += p * v0.y; o[2]  += p * v0.z; o[3]  += p * v0.w;
            o[4]  += p * v1.x; o[5]  += p * v1.y; o[6]  += p * v1.z; o[7]  += p * v1.w;
            o[8]  += p * v2.x; o[9]  += p * v2.y; o[10] += p * v2.z; o[11] += p * v2.w;
            o[12] += p * v3.x; o[13] += p * v3.y; o[14] += p * v3.z; o[15] += p * v3.w;
        }
        __syncthreads();
    }

    float inv = maskq / l_run;
    #pragma unroll
    for (int j = 0; j < 16; j++)
        out[(size_t)(qb * 64 + qown) * DD + h * DHH + seg + j] = o[j] * inv;
}

// ---------------- host orchestration ----------------
extern "C" void kernel_launch(void* const* d_in, const int* in_sizes, int n_in,
                              void* d_out, int out_size) {
    (void)in_sizes; (void)n_in; (void)out_size;
    const int*   ids      = (const int*)  d_in[0];
    const float* mask     = (const float*)d_in[1];
    const int*   rand_attn= (const int*)  d_in[2];
    const float* emb_word = (const float*)d_in[3];
    const float* emb_pos  = (const float*)d_in[4];
    const float* eln_g    = (const float*)d_in[5];
    const float* eln_b    = (const float*)d_in[6];
    const float* Wq = (const float*)d_in[7];  const float* bq = (const float*)d_in[8];
    const float* Wk = (const float*)d_in[9];  const float* bk = (const float*)d_in[10];
    const float* Wv = (const float*)d_in[11]; const float* bv = (const float*)d_in[12];
    const float* Wo = (const float*)d_in[13]; const float* bo = (const float*)d_in[14];
    const float* ln1g = (const float*)d_in[15]; const float* ln1b = (const float*)d_in[16];
    const float* W1 = (const float*)d_in[17]; const float* b1 = (const float*)d_in[18];
    const float* W2 = (const float*)d_in[19]; const float* b2 = (const float*)d_in[20];
    const float* ln2g = (const float*)d_in[21]; const float* ln2b = (const float*)d_in[22];
    float* outp = (float*)d_out;

    float *px, *pt, *pq, *pk, *pv, *pa, *pf1;
    int *pkl, *pkc;
    cudaGetSymbolAddress((void**)&px,  g_x);
    cudaGetSymbolAddress((void**)&pt,  g_t);
    cudaGetSymbolAddress((void**)&pq,  g_q);
    cudaGetSymbolAddress((void**)&pk,  g_k);
    cudaGetSymbolAddress((void**)&pv,  g_v);
    cudaGetSymbolAddress((void**)&pa,  g_a);
    cudaGetSymbolAddress((void**)&pf1, g_f1);
    cudaGetSymbolAddress((void**)&pkl, g_klist);
    cudaGetSymbolAddress((void**)&pkc, g_kcount);

    const int ATTN_SMEM = (3 * 64 * APAD + 64 * 64 + 128 + 64) * 4;
    cudaFuncSetAttribute(attn_flash, cudaFuncAttributeMaxDynamicSharedMemorySize, ATTN_SMEM);

    embed_kernel<<<NN, 256>>>(ids, emb_word, emb_pos, pt);
    ln_kernel<<<NN, 256>>>(pt, nullptr, eln_g, eln_b, px);
    build_klist<<<(HH * MM + 127) / 128, 128>>>(rand_attn, pkl, pkc);

    dim3 gProj(DD / 128, NN / 128);   // 6 x 32
    dim3 gF1(FFD / 128, NN / 128);    // 24 x 32
    dim3 gAttn(MM, HH);               // 64 x 12

    for (int i = 0; i < LL; i++) {
        const float* wq = Wq + (size_t)i * DD * DD;
        const float* wk = Wk + (size_t)i * DD * DD;
        const float* wv = Wv + (size_t)i * DD * DD;
        const float* wo = Wo + (size_t)i * DD * DD;
        const float* w1 = W1 + (size_t)i * DD * FFD;
        const float* w2 = W2 + (size_t)i * FFD * DD;

        gemm128<<<gProj, 256>>>(px, wq, bq + (size_t)i * DD, pq, DD, DD, 0);
        gemm128<<<gProj, 256>>>(px, wk, bk + (size_t)i * DD, pk, DD, DD, 0);
        gemm128<<<gProj, 256>>>(px, wv, bv + (size_t)i * DD, pv, DD, DD, 0);

        attn_flash<<<gAttn, 256, ATTN_SMEM>>>(pq, pk, pv, mask, pkl, pkc, pa);

        gemm128<<<gProj, 256>>>(pa, wo, bo + (size_t)i * DD, pt, DD, DD, 0);
        ln_kernel<<<NN, 256>>>(px, pt, ln1g + (size_t)i * DD, ln1b + (size_t)i * DD, px);

        gemm128<<<gF1, 256>>>(px, w1, b1 + (size_t)i * FFD, pf1, FFD, DD, 1);
        gemm128<<<gProj, 256>>>(pf1, w2, b2 + (size_t)i * DD, pt, DD, FFD, 0);

        float* lnout = (i == LL - 1) ? outp : px;
        ln_kernel<<<NN, 256>>>(px, pt, ln2g + (size_t)i * DD, ln2b + (size_t)i * DD, lnout);
    }
}

// round 4
// speedup vs baseline: 4.1361x; 1.4516x over previous
#include <cuda_runtime.h>
#include <cuda_bf16.h>
#include <math.h>
#include <stdint.h>

// ---------------- problem constants ----------------
#define NN   4096
#define BSZ  64
#define HH   12
#define DHH  64
#define DD   768
#define LL   4
#define FFD  3072
#define MM   64
#define RR   3
#define NEGV (-10000.0f)
#define APAD 65

// ---------------- device scratch ----------------
__device__ float g_x [NN * DD];
__device__ float g_t [NN * DD];
__device__ float g_q [NN * DD];
__device__ float g_k [NN * DD];
__device__ float g_v [NN * DD];
__device__ float g_a [NN * DD];
__device__ float g_f1[NN * FFD];
__device__ int   g_klist [HH * MM * 64];
__device__ int   g_kcount[HH * MM];
// transposed bf16 hi/lo weights per layer: [wq,wk,wv,wo (768x768), w1T(3072x768), w2T(768x3072)]
#define WPL 7077888ULL
__device__ __nv_bfloat16 g_wTh[LL * WPL];
__device__ __nv_bfloat16 g_wTl[LL * WPL];

// ---------------- helpers ----------------
__device__ __forceinline__ float block_reduce(float val, bool is_max, float* rbuf) {
    int lane = threadIdx.x & 31;
    int w    = threadIdx.x >> 5;
    #pragma unroll
    for (int o = 16; o; o >>= 1) {
        float other = __shfl_xor_sync(0xffffffffu, val, o);
        val = is_max ? fmaxf(val, other) : (val + other);
    }
    if (lane == 0) rbuf[w] = val;
    __syncthreads();
    if (threadIdx.x == 0) {
        int nw = (blockDim.x + 31) >> 5;
        float r = rbuf[0];
        for (int i = 1; i < nw; i++) r = is_max ? fmaxf(r, rbuf[i]) : (r + rbuf[i]);
        rbuf[0] = r;
    }
    __syncthreads();
    float res = rbuf[0];
    __syncthreads();
    return res;
}

__device__ __forceinline__ void mma_bf16(float* c, const uint32_t* a, const uint32_t* b) {
    asm volatile(
        "mma.sync.aligned.m16n8k16.row.col.f32.bf16.bf16.f32 "
        "{%0,%1,%2,%3}, {%4,%5,%6,%7}, {%8,%9}, {%0,%1,%2,%3};"
        : "+f"(c[0]), "+f"(c[1]), "+f"(c[2]), "+f"(c[3])
        : "r"(a[0]), "r"(a[1]), "r"(a[2]), "r"(a[3]), "r"(b[0]), "r"(b[1]));
}

// ---------------- embedding ----------------
__global__ void embed_kernel(const int* __restrict__ ids,
                             const float* __restrict__ ew,
                             const float* __restrict__ ep,
                             float* __restrict__ out) {
    int t = blockIdx.x;
    int id = ids[t];
    const float* wr = ew + (size_t)id * DD;
    const float* pr = ep + (size_t)t * DD;
    float* o = out + (size_t)t * DD;
    for (int d = threadIdx.x; d < DD; d += blockDim.x)
        o[d] = wr[d] + pr[d];
}

// ---------------- layernorm (optional residual) ----------------
__global__ void ln_kernel(const float* __restrict__ A,
                          const float* __restrict__ Bres,
                          const float* __restrict__ g,
                          const float* __restrict__ b,
                          float* __restrict__ out) {
    __shared__ float s[DD];
    __shared__ float rbuf[8];
    int t = blockIdx.x;
    int tid = threadIdx.x;
    const float* ar = A + (size_t)t * DD;
    const float* br = Bres ? (Bres + (size_t)t * DD) : nullptr;
    float lsum = 0.f;
    for (int d = tid; d < DD; d += blockDim.x) {
        float v = ar[d];
        if (br) v += br[d];
        s[d] = v;
        lsum += v;
    }
    float mu = block_reduce(lsum, false, rbuf) * (1.0f / DD);
    float lvar = 0.f;
    for (int d = tid; d < DD; d += blockDim.x) {
        float dv = s[d] - mu;
        lvar += dv * dv;
    }
    float var = block_reduce(lvar, false, rbuf) * (1.0f / DD);
    float inv = rsqrtf(var + 1e-5f);
    float* o = out + (size_t)t * DD;
    for (int d = tid; d < DD; d += blockDim.x)
        o[d] = (s[d] - mu) * inv * g[d] + b[d];
}

// ---------------- weight transpose + bf16 hi/lo split ----------------
__global__ void wtrans(const float* __restrict__ W,
                       __nv_bfloat16* __restrict__ oh,
                       __nv_bfloat16* __restrict__ ol,
                       int K, int N) {
    __shared__ float sm[32][33];
    int n0 = blockIdx.x * 32, k0 = blockIdx.y * 32;
    int tx = threadIdx.x & 31, ty = threadIdx.x >> 5;
    #pragma unroll
    for (int j = 0; j < 4; j++) {
        int kk = ty + j * 8;
        sm[kk][tx] = W[(size_t)(k0 + kk) * N + n0 + tx];
    }
    __syncthreads();
    #pragma unroll
    for (int j = 0; j < 4; j++) {
        int nn = ty + j * 8;
        float v = sm[tx][nn];
        __nv_bfloat16 h = __float2bfloat16(v);
        float r = v - __bfloat162float(h);
        size_t o = (size_t)(n0 + nn) * K + k0 + tx;
        oh[o] = h;
        ol[o] = __float2bfloat16(r);
    }
}

// ---------------- HMMA GEMM: C = A(MxK fp32) @ W(KxN) + bias ----------------
// W pre-transposed [N,K] bf16 hi/lo. 128x128 tile, k-chunk 32, bf16 3-split,
// double-buffered smem, mma.sync.m16n8k16, fp32 accumulators.
#define RS      40                 // smem row stride (bf16 elems): 32 + 8 pad
#define TILE_E  (128 * RS)         // elems per tile
#define STAGE_E (4 * TILE_E)       // Ah, Al, Bh, Bl
#define GEMM_SMEM (2 * STAGE_E * 2)  // bytes (2 stages, bf16)

__global__ __launch_bounds__(256)
void gemm_mma(const float* __restrict__ A,
              const __nv_bfloat16* __restrict__ BTh,
              const __nv_bfloat16* __restrict__ BTl,
              const float* __restrict__ bias,
              float* __restrict__ C,
              int Nd, int K, int act) {
    extern __shared__ __nv_bfloat16 smem[];
    int tid = threadIdx.x;
    int m0 = blockIdx.y * 128, n0 = blockIdx.x * 128;
    int w = tid >> 5, lane = tid & 31;
    int wm = w & 1, wn = w >> 1;
    int gid = lane >> 2, tig = lane & 3;

    float acc[4][4][4];
    #pragma unroll
    for (int i = 0; i < 4; i++)
        #pragma unroll
        for (int j = 0; j < 4; j++)
            #pragma unroll
            for (int r = 0; r < 4; r++) acc[i][j][r] = 0.f;

    int nchunk = K >> 5;

    // ---- loader: chunk c into stage s ----
    auto load_chunk = [&](int c, int s) {
        __nv_bfloat16* Ah = smem + s * STAGE_E;
        __nv_bfloat16* Al = Ah + TILE_E;
        __nv_bfloat16* Bh = Ah + 2 * TILE_E;
        __nv_bfloat16* Bl = Ah + 3 * TILE_E;
        int k0 = c << 5;
        const float* Abase = A + (size_t)m0 * K + k0;
        #pragma unroll
        for (int i = 0; i < 4; i++) {
            int linear = tid + i * 256;       // float4 idx: 128 rows x 8
            int row = linear >> 3;
            int k4  = (linear & 7) << 2;
            float4 va = *(const float4*)(Abase + (size_t)row * K + k4);
            __nv_bfloat162 h01 = __floats2bfloat162_rn(va.x, va.y);
            __nv_bfloat162 h23 = __floats2bfloat162_rn(va.z, va.w);
            float rx = va.x - __bfloat162float(h01.x);
            float ry = va.y - __bfloat162float(h01.y);
            float rz = va.z - __bfloat162float(h23.x);
            float rw = va.w - __bfloat162float(h23.y);
            __nv_bfloat162 l01 = __floats2bfloat162_rn(rx, ry);
            __nv_bfloat162 l23 = __floats2bfloat162_rn(rz, rw);
            uint2 hv, lv;
            hv.x = *(uint32_t*)&h01; hv.y = *(uint32_t*)&h23;
            lv.x = *(uint32_t*)&l01; lv.y = *(uint32_t*)&l23;
            *(uint2*)(Ah + row * RS + k4) = hv;
            *(uint2*)(Al + row * RS + k4) = lv;
        }
        const __nv_bfloat16* Bhg = BTh + (size_t)n0 * K + k0;
        const __nv_bfloat16* Blg = BTl + (size_t)n0 * K + k0;
        #pragma unroll
        for (int i = 0; i < 4; i++) {
            int linear = tid + i * 256;       // uint2(4bf16) idx: 128 rows x 8
            int row = linear >> 3;
            int k4  = (linear & 7) << 2;
            size_t go = (size_t)row * K + k4;
            *(uint2*)(Bh + row * RS + k4) = *(const uint2*)(Bhg + go);
            *(uint2*)(Bl + row * RS + k4) = *(const uint2*)(Blg + go);
        }
    };

    load_chunk(0, 0);
    __syncthreads();

    for (int c = 0; c < nchunk; c++) {
        if (c + 1 < nchunk) load_chunk(c + 1, (c + 1) & 1);

        const __nv_bfloat16* Ah = smem + (c & 1) * STAGE_E;
        const __nv_bfloat16* Al = Ah + TILE_E;
        const __nv_bfloat16* Bh = Ah + 2 * TILE_E;
        const __nv_bfloat16* Bl = Ah + 3 * TILE_E;

        #pragma unroll
        for (int ks = 0; ks < 32; ks += 16) {
            uint32_t a_h[4][4], a_l[4][4], b_h[4][2], b_l[4][2];
            int cb = ks + tig * 2;
            #pragma unroll
            for (int i = 0; i < 4; i++) {
                int r = wm * 64 + i * 16 + gid;
                a_h[i][0] = *(const uint32_t*)(Ah + r * RS + cb);
                a_h[i][1] = *(const uint32_t*)(Ah + (r + 8) * RS + cb);
                a_h[i][2] = *(const uint32_t*)(Ah + r * RS + cb + 8);
                a_h[i][3] = *(const uint32_t*)(Ah + (r + 8) * RS + cb + 8);
                a_l[i][0] = *(const uint32_t*)(Al + r * RS + cb);
                a_l[i][1] = *(const uint32_t*)(Al + (r + 8) * RS + cb);
                a_l[i][2] = *(const uint32_t*)(Al + r * RS + cb + 8);
                a_l[i][3] = *(const uint32_t*)(Al + (r + 8) * RS + cb + 8);
            }
            #pragma unroll
            for (int j = 0; j < 4; j++) {
                int nr = wn * 32 + j * 8 + gid;
                b_h[j][0] = *(const uint32_t*)(Bh + nr * RS + cb);
                b_h[j][1] = *(const uint32_t*)(Bh + nr * RS + cb + 8);
                b_l[j][0] = *(const uint32_t*)(Bl + nr * RS + cb);
                b_l[j][1] = *(const uint32_t*)(Bl + nr * RS + cb + 8);
            }
            #pragma unroll
            for (int i = 0; i < 4; i++)
                #pragma unroll
                for (int j = 0; j < 4; j++) {
                    mma_bf16(acc[i][j], a_h[i], b_h[j]);
                    mma_bf16(acc[i][j], a_h[i], b_l[j]);
                    mma_bf16(acc[i][j], a_l[i], b_h[j]);
                }
        }
        __syncthreads();
    }

    // epilogue: direct global stores (float2 per row-pair)
    #pragma unroll
    for (int i = 0; i < 4; i++) {
        int row = m0 + wm * 64 + i * 16 + gid;
        #pragma unroll
        for (int j = 0; j < 4; j++) {
            int col = n0 + wn * 32 + j * 8 + tig * 2;
            float b0 = bias[col], b1 = bias[col + 1];
            float v0 = acc[i][j][0] + b0;
            float v1 = acc[i][j][1] + b1;
            float v2 = acc[i][j][2] + b0;
            float v3 = acc[i][j][3] + b1;
            if (act) {
                v0 = 0.5f * v0 * (1.0f + erff(v0 * 0.70710678118654752f));
                v1 = 0.5f * v1 * (1.0f + erff(v1 * 0.70710678118654752f));
                v2 = 0.5f * v2 * (1.0f + erff(v2 * 0.70710678118654752f));
                v3 = 0.5f * v3 * (1.0f + erff(v3 * 0.70710678118654752f));
            }
            *(float2*)(C + (size_t)row * Nd + col)       = make_float2(v0, v1);
            *(float2*)(C + (size_t)(row + 8) * Nd + col) = make_float2(v2, v3);
        }
    }
}

// ---------------- key-block list builder ----------------
__global__ void build_klist(const int* __restrict__ rand_attn,
                            int* __restrict__ klist,
                            int* __restrict__ kcount) {
    int idx = blockIdx.x * blockDim.x + threadIdx.x;
    if (idx >= HH * MM) return;
    int h  = idx / MM;
    int qb = idx % MM;
    int* lst = klist + idx * 64;
    int c = 0;
    if (qb == 0 || qb == MM - 1) {
        for (int j = 0; j < MM; j++) lst[c++] = j;
    } else if (qb == 1) {
        lst[c++] = 0; lst[c++] = 1; lst[c++] = 2; lst[c++] = MM - 1;
        const int* rr = rand_attn + ((size_t)h * (MM - 2) + 0) * RR;
        for (int r = 0; r < RR; r++) lst[c++] = rr[r] | 256;
    } else if (qb == MM - 2) {
        lst[c++] = 0; lst[c++] = MM - 3; lst[c++] = MM - 2; lst[c++] = MM - 1;
        const int* rr = rand_attn + ((size_t)h * (MM - 2) + (MM - 3)) * RR;
        for (int r = 0; r < RR; r++) lst[c++] = rr[r] | 256;
    } else {
        lst[c++] = 0;
        lst[c++] = (qb - 1) | 256;
        lst[c++] = qb | 256;
        lst[c++] = (qb + 1) | 256;
        const int* rr = rand_attn + ((size_t)h * (MM - 2) + (qb - 1)) * RR;
        for (int r = 0; r < RR; r++) lst[c++] = rr[r] | 256;
        lst[c++] = MM - 1;
    }
    kcount[idx] = c;
}

// ---------------- flash-style block-sparse attention ----------------
__global__ __launch_bounds__(256)
void attn_flash(const float* __restrict__ q, const float* __restrict__ k,
                const float* __restrict__ v, const float* __restrict__ mask,
                const int* __restrict__ klist, const int* __restrict__ kcount,
                float* __restrict__ out) {
    extern __shared__ float sm[];
    float* Qs = sm;
    float* Ks = Qs + 64 * APAD;
    float* Vs = Ks + 64 * APAD;
    float* Ss = Vs + 64 * 64;
    float* mq = Ss + 64 * APAD;
    float* mk = mq + 64;
    int*   ents = (int*)(mk + 64);

    int qb = blockIdx.x, h = blockIdx.y;
    int tid = threadIdx.x;
    int lid = h * MM + qb;
    int cnt = kcount[lid];

    if (tid < 64) {
        ents[tid] = klist[lid * 64 + tid];
        mq[tid]   = mask[qb * 64 + tid];
    }
    for (int idx = tid; idx < 64 * 64; idx += 256) {
        int r = idx >> 6, d = idx & 63;
        Qs[r * APAD + d] = q[(size_t)(qb * 64 + r) * DD + h * DHH + d];
    }
    __syncthreads();

    int qown = tid >> 2;
    int seg  = (tid & 3) << 4;
    int ty = tid >> 4, tx = tid & 15;
    float m_run = -1e30f, l_run = 0.f;
    float o[16];
    #pragma unroll
    for (int i = 0; i < 16; i++) o[i] = 0.f;
    float maskq = mq[qown];

    for (int b = 0; b < cnt; b++) {
        int e  = ents[b];
        int kb = e & 0xff;
        int fl = e >> 8;
        for (int idx = tid; idx < 64 * 64; idx += 256) {
            int r = idx >> 6, d = idx & 63;
            size_t gofs = (size_t)(kb * 64 + r) * DD + h * DHH + d;
            Ks[r * APAD + d] = k[gofs];
            Vs[r * 64 + d]   = v[gofs];
        }
        if (tid < 64) mk[tid] = mask[kb * 64 + tid];
        __syncthreads();

        float acc[4][4];
        #pragma unroll
        for (int i = 0; i < 4; i++)
            #pragma unroll
            for (int j = 0; j < 4; j++) acc[i][j] = 0.f;
        #pragma unroll 8
        for (int kk = 0; kk < 64; kk++) {
            float a[4], bb[4];
            #pragma unroll
            for (int i = 0; i < 4; i++) a[i]  = Qs[(ty * 4 + i) * APAD + kk];
            #pragma unroll
            for (int j = 0; j < 4; j++) bb[j] = Ks[(tx * 4 + j) * APAD + kk];
            #pragma unroll
            for (int i = 0; i < 4; i++)
                #pragma unroll
                for (int j = 0; j < 4; j++)
                    acc[i][j] += a[i] * bb[j];
        }
        #pragma unroll
        for (int i = 0; i < 4; i++) {
            int qq = ty * 4 + i;
            float mqv = mq[qq];
            #pragma unroll
            for (int j = 0; j < 4; j++) {
                int ss = tx * 4 + j;
                float mkv = mk[ss];
                float eff = fl ? (mqv * mkv) : mkv;
                Ss[qq * APAD + ss] = acc[i][j] * 0.125f + (1.0f - eff) * NEGV;
            }
        }
        __syncthreads();

        float lm = -1e30f;
        #pragma unroll
        for (int j = 0; j < 16; j++) lm = fmaxf(lm, Ss[qown * APAD + seg + j]);
        lm = fmaxf(lm, __shfl_xor_sync(0xffffffffu, lm, 1));
        lm = fmaxf(lm, __shfl_xor_sync(0xffffffffu, lm, 2));
        float m_new = fmaxf(m_run, lm);
        float scale = expf(m_run - m_new);
        float lsum = 0.f;
        #pragma unroll
        for (int j = 0; j < 16; j++) {
            float p = expf(Ss[qown * APAD + seg + j] - m_new);
            Ss[qown * APAD + seg + j] = p;
            lsum += p;
        }
        lsum += __shfl_xor_sync(0xffffffffu, lsum, 1);
        lsum += __shfl_xor_sync(0xffffffffu, lsum, 2);
        l_run = l_run * scale + lsum;
        m_run = m_new;
        #pragma unroll
        for (int i = 0; i < 16; i++) o[i] *= scale;
        __syncwarp();

        #pragma unroll 4
        for (int s = 0; s < 64; s++) {
            float p = Ss[qown * APAD + s];
            const float4* vr = (const float4*)(Vs + s * 64 + seg);
            float4 v0 = vr[0], v1 = vr[1], v2 = vr[2], v3 = vr[3];
            o[0]  += p * v0.x; o[1]  += p * v0.y; o[2]  += p * v0.z; o[3]  += p * v0.w;
            o[4]  += p * v1.x; o[5]  += p * v1.y; o[6]  += p * v1.z; o[7]  += p * v1.w;
            o[8]  += p * v2.x; o[9]  += p * v2.y; o[10] += p * v2.z; o[11] += p * v2.w;
            o[12] += p * v3.x; o[13] += p * v3.y; o[14] += p * v3.z; o[15] += p * v3.w;
        }
        __syncthreads();
    }

    float inv = maskq / l_run;
    #pragma unroll
    for (int j = 0; j < 16; j++)
        out[(size_t)(qb * 64 + qown) * DD + h * DHH + seg + j] = o[j] * inv;
}

// ---------------- host orchestration ----------------
extern "C" void kernel_launch(void* const* d_in, const int* in_sizes, int n_in,
                              void* d_out, int out_size) {
    (void)in_sizes; (void)n_in; (void)out_size;
    const int*   ids      = (const int*)  d_in[0];
    const float* mask     = (const float*)d_in[1];
    const int*   rand_attn= (const int*)  d_in[2];
    const float* emb_word = (const float*)d_in[3];
    const float* emb_pos  = (const float*)d_in[4];
    const float* eln_g    = (const float*)d_in[5];
    const float* eln_b    = (const float*)d_in[6];
    const float* Wq = (const float*)d_in[7];  const float* bq = (const float*)d_in[8];
    const float* Wk = (const float*)d_in[9];  const float* bk = (const float*)d_in[10];
    const float* Wv = (const float*)d_in[11]; const float* bv = (const float*)d_in[12];
    const float* Wo = (const float*)d_in[13]; const float* bo = (const float*)d_in[14];
    const float* ln1g = (const float*)d_in[15]; const float* ln1b = (const float*)d_in[16];
    const float* W1 = (const float*)d_in[17]; const float* b1 = (const float*)d_in[18];
    const float* W2 = (const float*)d_in[19]; const float* b2 = (const float*)d_in[20];
    const float* ln2g = (const float*)d_in[21]; const float* ln2b = (const float*)d_in[22];
    float* outp = (float*)d_out;

    float *px, *pt, *pq, *pk, *pv, *pa, *pf1;
    int *pkl, *pkc;
    __nv_bfloat16 *pwh, *pwl;
    cudaGetSymbolAddress((void**)&px,  g_x);
    cudaGetSymbolAddress((void**)&pt,  g_t);
    cudaGetSymbolAddress((void**)&pq,  g_q);
    cudaGetSymbolAddress((void**)&pk,  g_k);
    cudaGetSymbolAddress((void**)&pv,  g_v);
    cudaGetSymbolAddress((void**)&pa,  g_a);
    cudaGetSymbolAddress((void**)&pf1, g_f1);
    cudaGetSymbolAddress((void**)&pkl, g_klist);
    cudaGetSymbolAddress((void**)&pkc, g_kcount);
    cudaGetSymbolAddress((void**)&pwh, g_wTh);
    cudaGetSymbolAddress((void**)&pwl, g_wTl);

    cudaFuncSetAttribute(gemm_mma, cudaFuncAttributeMaxDynamicSharedMemorySize, GEMM_SMEM);
    const int ATTN_SMEM = (3 * 64 * APAD + 64 * 64 + 128 + 64) * 4;
    cudaFuncSetAttribute(attn_flash, cudaFuncAttributeMaxDynamicSharedMemorySize, ATTN_SMEM);

    const size_t OQ = 0, OK = 589824, OV = 1179648, OO = 1769472, O1 = 2359296, O2 = 4718592;

    for (int i = 0; i < LL; i++) {
        size_t lo = (size_t)i * WPL;
        wtrans<<<dim3(DD/32, DD/32), 256>>>(Wq + (size_t)i*DD*DD, pwh + lo + OQ, pwl + lo + OQ, DD, DD);
        wtrans<<<dim3(DD/32, DD/32), 256>>>(Wk + (size_t)i*DD*DD, pwh + lo + OK, pwl + lo + OK, DD, DD);
        wtrans<<<dim3(DD/32, DD/32), 256>>>(Wv + (size_t)i*DD*DD, pwh + lo + OV, pwl + lo + OV, DD, DD);
        wtrans<<<dim3(DD/32, DD/32), 256>>>(Wo + (size_t)i*DD*DD, pwh + lo + OO, pwl + lo + OO, DD, DD);
        wtrans<<<dim3(FFD/32, DD/32), 256>>>(W1 + (size_t)i*DD*FFD, pwh + lo + O1, pwl + lo + O1, DD, FFD);
        wtrans<<<dim3(DD/32, FFD/32), 256>>>(W2 + (size_t)i*FFD*DD, pwh + lo + O2, pwl + lo + O2, FFD, DD);
    }

    embed_kernel<<<NN, 256>>>(ids, emb_word, emb_pos, pt);
    ln_kernel<<<NN, 256>>>(pt, nullptr, eln_g, eln_b, px);
    build_klist<<<(HH * MM + 127) / 128, 128>>>(rand_attn, pkl, pkc);

    dim3 gProj(DD / 128, NN / 128);   // 6 x 32
    dim3 gF1(FFD / 128, NN / 128);    // 24 x 32
    dim3 gAttn(MM, HH);               // 64 x 12

    for (int i = 0; i < LL; i++) {
        size_t lo = (size_t)i * WPL;

        gemm_mma<<<gProj, 256, GEMM_SMEM>>>(px, pwh + lo + OQ, pwl + lo + OQ, bq + (size_t)i*DD, pq, DD, DD, 0);
        gemm_mma<<<gProj, 256, GEMM_SMEM>>>(px, pwh + lo + OK, pwl + lo + OK, bk + (size_t)i*DD, pk, DD, DD, 0);
        gemm_mma<<<gProj, 256, GEMM_SMEM>>>(px, pwh + lo + OV, pwl + lo + OV, bv + (size_t)i*DD, pv, DD, DD, 0);

        attn_flash<<<gAttn, 256, ATTN_SMEM>>>(pq, pk, pv, mask, pkl, pkc, pa);

        gemm_mma<<<gProj, 256, GEMM_SMEM>>>(pa, pwh + lo + OO, pwl + lo + OO, bo + (size_t)i*DD, pt, DD, DD, 0);
        ln_kernel<<<NN, 256>>>(px, pt, ln1g + (size_t)i*DD, ln1b + (size_t)i*DD, px);

        gemm_mma<<<gF1, 256, GEMM_SMEM>>>(px, pwh + lo + O1, pwl + lo + O1, b1 + (size_t)i*FFD, pf1, FFD, DD, 1);
        gemm_mma<<<gProj, 256, GEMM_SMEM>>>(pf1, pwh + lo + O2, pwl + lo + O2, b2 + (size_t)i*DD, pt, DD, FFD, 0);

        float* lnout = (i == LL - 1) ? outp : px;
        ln_kernel<<<NN, 256>>>(px, pt, ln2g + (size_t)i*DD, ln2b + (size_t)i*DD, lnout);
    }
}

// round 5
// speedup vs baseline: 8.2115x; 1.9853x over previous
#include <cuda_runtime.h>
#include <cuda_bf16.h>
#include <math.h>
#include <stdint.h>

// ---------------- problem constants ----------------
#define NN   4096
#define HH   12
#define DHH  64
#define DD   768
#define LL   4
#define FFD  3072
#define MM   64
#define RR   3
#define NEGV (-10000.0f)

// ---------------- device scratch ----------------
__device__ float g_x [NN * DD];          // fp32 residual stream
__device__ float g_t [NN * DD];          // fp32 temp (embed out / WO out / W2 out)
__device__ __nv_bfloat16 g_xh[NN * DD],  g_xl[NN * DD];
__device__ __nv_bfloat16 g_qh[NN * DD],  g_ql[NN * DD];
__device__ __nv_bfloat16 g_kh[NN * DD],  g_kl[NN * DD];
__device__ __nv_bfloat16 g_vh[NN * DD],  g_vl[NN * DD];
__device__ __nv_bfloat16 g_ah[NN * DD],  g_al[NN * DD];
__device__ __nv_bfloat16 g_fh[NN * FFD], g_fl[NN * FFD];
__device__ int   g_klist [HH * MM * 64];
__device__ int   g_kcount[HH * MM];
#define WPL 7077888ULL
__device__ __nv_bfloat16 g_wTh[LL * WPL];
__device__ __nv_bfloat16 g_wTl[LL * WPL];

// ---------------- asm helpers ----------------
__device__ __forceinline__ uint32_t smem_u32(const void* p) {
    uint32_t a;
    asm("{ .reg .u64 t; cvta.to.shared.u64 t, %1; cvt.u32.u64 %0, t; }" : "=r"(a) : "l"(p));
    return a;
}
__device__ __forceinline__ void cpa16(uint32_t dst, const void* src) {
    asm volatile("cp.async.cg.shared.global [%0], [%1], 16;" :: "r"(dst), "l"(src));
}
__device__ __forceinline__ void cpa_commit() { asm volatile("cp.async.commit_group;" ::: "memory"); }
__device__ __forceinline__ void cpa_wait0()  { asm volatile("cp.async.wait_group 0;" ::: "memory"); }
__device__ __forceinline__ void cpa_wait1()  { asm volatile("cp.async.wait_group 1;" ::: "memory"); }

__device__ __forceinline__ void mma_bf16(float* c, const uint32_t* a, const uint32_t* b) {
    asm volatile(
        "mma.sync.aligned.m16n8k16.row.col.f32.bf16.bf16.f32 "
        "{%0,%1,%2,%3}, {%4,%5,%6,%7}, {%8,%9}, {%0,%1,%2,%3};"
        : "+f"(c[0]), "+f"(c[1]), "+f"(c[2]), "+f"(c[3])
        : "r"(a[0]), "r"(a[1]), "r"(a[2]), "r"(a[3]), "r"(b[0]), "r"(b[1]));
}

__device__ __forceinline__ uint32_t pack_bf16h(float v0, float v1) {
    __nv_bfloat162 h = __floats2bfloat162_rn(v0, v1);
    return *(uint32_t*)&h;
}

// ---------------- misc kernels ----------------
__device__ __forceinline__ float block_reduce(float val, bool is_max, float* rbuf) {
    int lane = threadIdx.x & 31;
    int w    = threadIdx.x >> 5;
    #pragma unroll
    for (int o = 16; o; o >>= 1) {
        float other = __shfl_xor_sync(0xffffffffu, val, o);
        val = is_max ? fmaxf(val, other) : (val + other);
    }
    if (lane == 0) rbuf[w] = val;
    __syncthreads();
    if (threadIdx.x == 0) {
        int nw = (blockDim.x + 31) >> 5;
        float r = rbuf[0];
        for (int i = 1; i < nw; i++) r = is_max ? fmaxf(r, rbuf[i]) : (r + rbuf[i]);
        rbuf[0] = r;
    }
    __syncthreads();
    float res = rbuf[0];
    __syncthreads();
    return res;
}

__global__ void embed_kernel(const int* __restrict__ ids,
                             const float* __restrict__ ew,
                             const float* __restrict__ ep,
                             float* __restrict__ out) {
    int t = blockIdx.x;
    int id = ids[t];
    const float* wr = ew + (size_t)id * DD;
    const float* pr = ep + (size_t)t * DD;
    float* o = out + (size_t)t * DD;
    for (int d = threadIdx.x; d < DD; d += blockDim.x)
        o[d] = wr[d] + pr[d];
}

// layernorm: fp32 out (optional) + bf16 hi/lo out (optional)
__global__ void ln_kernel(const float* __restrict__ A,
                          const float* __restrict__ Bres,
                          const float* __restrict__ g,
                          const float* __restrict__ b,
                          float* __restrict__ outf,
                          __nv_bfloat16* __restrict__ outh,
                          __nv_bfloat16* __restrict__ outl) {
    __shared__ float s[DD];
    __shared__ float rbuf[8];
    int t = blockIdx.x;
    int tid = threadIdx.x;
    const float* ar = A + (size_t)t * DD;
    const float* br = Bres ? (Bres + (size_t)t * DD) : nullptr;
    float lsum = 0.f;
    for (int d = tid; d < DD; d += blockDim.x) {
        float v = ar[d];
        if (br) v += br[d];
        s[d] = v;
        lsum += v;
    }
    float mu = block_reduce(lsum, false, rbuf) * (1.0f / DD);
    float lvar = 0.f;
    for (int d = tid; d < DD; d += blockDim.x) {
        float dv = s[d] - mu;
        lvar += dv * dv;
    }
    float var = block_reduce(lvar, false, rbuf) * (1.0f / DD);
    float inv = rsqrtf(var + 1e-5f);
    for (int d = tid; d < DD; d += blockDim.x) {
        float val = (s[d] - mu) * inv * g[d] + b[d];
        if (outf) outf[(size_t)t * DD + d] = val;
        if (outh) {
            __nv_bfloat16 h = __float2bfloat16(val);
            outh[(size_t)t * DD + d] = h;
            outl[(size_t)t * DD + d] = __float2bfloat16(val - __bfloat162float(h));
        }
    }
}

// weight transpose + bf16 hi/lo split: W[K,N] fp32 -> [N,K] bf16 h/l
__global__ void wtrans(const float* __restrict__ W,
                       __nv_bfloat16* __restrict__ oh,
                       __nv_bfloat16* __restrict__ ol,
                       int K, int N) {
    __shared__ float sm[32][33];
    int n0 = blockIdx.x * 32, k0 = blockIdx.y * 32;
    int tx = threadIdx.x & 31, ty = threadIdx.x >> 5;
    #pragma unroll
    for (int j = 0; j < 4; j++) {
        int kk = ty + j * 8;
        sm[kk][tx] = W[(size_t)(k0 + kk) * N + n0 + tx];
    }
    __syncthreads();
    #pragma unroll
    for (int j = 0; j < 4; j++) {
        int nn = ty + j * 8;
        float v = sm[tx][nn];
        __nv_bfloat16 h = __float2bfloat16(v);
        float r = v - __bfloat162float(h);
        size_t o = (size_t)(n0 + nn) * K + k0 + tx;
        oh[o] = h;
        ol[o] = __float2bfloat16(r);
    }
}

// ---------------- HMMA GEMM ----------------
// A [M,K] bf16 h/l, B [N,K] bf16 h/l (pre-transposed). 128x128 tile, k-chunk 32,
// 3-split MMA, cp.async double-buffer. Output fp32 OR bf16 h/l (+gelu, +prescale).
#define RS      40
#define TILE_E  (128 * RS)
#define TILE_B  (TILE_E * 2)
#define STAGE_E (4 * TILE_E)
#define STAGE_B (STAGE_E * 2)
#define GEMM_SMEM (2 * STAGE_B)

__global__ __launch_bounds__(256)
void gemm_mma(const __nv_bfloat16* __restrict__ Agh, const __nv_bfloat16* __restrict__ Agl,
              const __nv_bfloat16* __restrict__ Bgh, const __nv_bfloat16* __restrict__ Bgl,
              const float* __restrict__ bias,
              float* __restrict__ Cf,
              __nv_bfloat16* __restrict__ Ch, __nv_bfloat16* __restrict__ Cl,
              int Nd, int K, int act, float prescale) {
    extern __shared__ __nv_bfloat16 smem[];
    uint32_t sb = smem_u32(smem);
    int tid = threadIdx.x;
    int m0 = blockIdx.y * 128, n0 = blockIdx.x * 128;
    int w = tid >> 5, lane = tid & 31;
    int wm = w & 1, wn = w >> 1;
    int gid = lane >> 2, tig = lane & 3;

    float acc[4][4][4];
    #pragma unroll
    for (int i = 0; i < 4; i++)
        #pragma unroll
        for (int j = 0; j < 4; j++)
            #pragma unroll
            for (int r = 0; r < 4; r++) acc[i][j][r] = 0.f;

    int nchunk = K >> 5;

    auto load_chunk = [&](int c, int s) {
        int k0 = c << 5;
        uint32_t stg = sb + s * STAGE_B;
        #pragma unroll
        for (int i = 0; i < 2; i++) {
            int linear = tid + i * 256;            // 512 chunks of 16B per tile
            int row = linear >> 2;
            int kc  = (linear & 3) << 3;
            uint32_t doff = (uint32_t)(row * RS + kc) * 2;
            size_t ga = (size_t)(m0 + row) * K + k0 + kc;
            cpa16(stg + doff,               Agh + ga);
            cpa16(stg + TILE_B + doff,      Agl + ga);
            size_t gb = (size_t)(n0 + row) * K + k0 + kc;
            cpa16(stg + 2 * TILE_B + doff,  Bgh + gb);
            cpa16(stg + 3 * TILE_B + doff,  Bgl + gb);
        }
    };

    load_chunk(0, 0);
    cpa_commit();

    for (int c = 0; c < nchunk; c++) {
        if (c + 1 < nchunk) {
            load_chunk(c + 1, (c + 1) & 1);
            cpa_commit();
            cpa_wait1();
        } else {
            cpa_wait0();
        }
        __syncthreads();

        const __nv_bfloat16* Ah = smem + (c & 1) * STAGE_E;
        const __nv_bfloat16* Al = Ah + TILE_E;
        const __nv_bfloat16* Bh = Ah + 2 * TILE_E;
        const __nv_bfloat16* Bl = Ah + 3 * TILE_E;

        #pragma unroll
        for (int ks = 0; ks < 32; ks += 16) {
            uint32_t a_h[4][4], a_l[4][4], b_h[4][2], b_l[4][2];
            int cb = ks + tig * 2;
            #pragma unroll
            for (int i = 0; i < 4; i++) {
                int r = wm * 64 + i * 16 + gid;
                a_h[i][0] = *(const uint32_t*)(Ah + r * RS + cb);
                a_h[i][1] = *(const uint32_t*)(Ah + (r + 8) * RS + cb);
                a_h[i][2] = *(const uint32_t*)(Ah + r * RS + cb + 8);
                a_h[i][3] = *(const uint32_t*)(Ah + (r + 8) * RS + cb + 8);
                a_l[i][0] = *(const uint32_t*)(Al + r * RS + cb);
                a_l[i][1] = *(const uint32_t*)(Al + (r + 8) * RS + cb);
                a_l[i][2] = *(const uint32_t*)(Al + r * RS + cb + 8);
                a_l[i][3] = *(const uint32_t*)(Al + (r + 8) * RS + cb + 8);
            }
            #pragma unroll
            for (int j = 0; j < 4; j++) {
                int nr = wn * 32 + j * 8 + gid;
                b_h[j][0] = *(const uint32_t*)(Bh + nr * RS + cb);
                b_h[j][1] = *(const uint32_t*)(Bh + nr * RS + cb + 8);
                b_l[j][0] = *(const uint32_t*)(Bl + nr * RS + cb);
                b_l[j][1] = *(const uint32_t*)(Bl + nr * RS + cb + 8);
            }
            #pragma unroll
            for (int i = 0; i < 4; i++)
                #pragma unroll
                for (int j = 0; j < 4; j++) {
                    mma_bf16(acc[i][j], a_h[i], b_h[j]);
                    mma_bf16(acc[i][j], a_h[i], b_l[j]);
                    mma_bf16(acc[i][j], a_l[i], b_h[j]);
                }
        }
        __syncthreads();
    }

    // epilogue
    #pragma unroll
    for (int i = 0; i < 4; i++) {
        int row = m0 + wm * 64 + i * 16 + gid;
        #pragma unroll
        for (int j = 0; j < 4; j++) {
            int col = n0 + wn * 32 + j * 8 + tig * 2;
            float b0 = bias[col], b1 = bias[col + 1];
            float v0 = (acc[i][j][0] + b0) * prescale;
            float v1 = (acc[i][j][1] + b1) * prescale;
            float v2 = (acc[i][j][2] + b0) * prescale;
            float v3 = (acc[i][j][3] + b1) * prescale;
            if (act) {
                v0 = 0.5f * v0 * (1.0f + erff(v0 * 0.70710678118654752f));
                v1 = 0.5f * v1 * (1.0f + erff(v1 * 0.70710678118654752f));
                v2 = 0.5f * v2 * (1.0f + erff(v2 * 0.70710678118654752f));
                v3 = 0.5f * v3 * (1.0f + erff(v3 * 0.70710678118654752f));
            }
            if (Cf) {
                *(float2*)(Cf + (size_t)row * Nd + col)       = make_float2(v0, v1);
                *(float2*)(Cf + (size_t)(row + 8) * Nd + col) = make_float2(v2, v3);
            } else {
                __nv_bfloat162 h01 = __floats2bfloat162_rn(v0, v1);
                __nv_bfloat162 h23 = __floats2bfloat162_rn(v2, v3);
                __nv_bfloat162 l01 = __floats2bfloat162_rn(v0 - __bfloat162float(h01.x),
                                                           v1 - __bfloat162float(h01.y));
                __nv_bfloat162 l23 = __floats2bfloat162_rn(v2 - __bfloat162float(h23.x),
                                                           v3 - __bfloat162float(h23.y));
                *(uint32_t*)(Ch + (size_t)row * Nd + col)       = *(uint32_t*)&h01;
                *(uint32_t*)(Cl + (size_t)row * Nd + col)       = *(uint32_t*)&l01;
                *(uint32_t*)(Ch + (size_t)(row + 8) * Nd + col) = *(uint32_t*)&h23;
                *(uint32_t*)(Cl + (size_t)(row + 8) * Nd + col) = *(uint32_t*)&l23;
            }
        }
    }
}

// ---------------- key-block list ----------------
__global__ void build_klist(const int* __restrict__ rand_attn,
                            int* __restrict__ klist,
                            int* __restrict__ kcount) {
    int idx = blockIdx.x * blockDim.x + threadIdx.x;
    if (idx >= HH * MM) return;
    int h  = idx / MM;
    int qb = idx % MM;
    int* lst = klist + idx * 64;
    int c = 0;
    if (qb == 0 || qb == MM - 1) {
        for (int j = 0; j < MM; j++) lst[c++] = j;
    } else if (qb == 1) {
        lst[c++] = 0; lst[c++] = 1; lst[c++] = 2; lst[c++] = MM - 1;
        const int* rr = rand_attn + ((size_t)h * (MM - 2) + 0) * RR;
        for (int r = 0; r < RR; r++) lst[c++] = rr[r] | 256;
    } else if (qb == MM - 2) {
        lst[c++] = 0; lst[c++] = MM - 3; lst[c++] = MM - 2; lst[c++] = MM - 1;
        const int* rr = rand_attn + ((size_t)h * (MM - 2) + (MM - 3)) * RR;
        for (int r = 0; r < RR; r++) lst[c++] = rr[r] | 256;
    } else {
        lst[c++] = 0;
        lst[c++] = (qb - 1) | 256;
        lst[c++] = qb | 256;
        lst[c++] = (qb + 1) | 256;
        const int* rr = rand_attn + ((size_t)h * (MM - 2) + (qb - 1)) * RR;
        for (int r = 0; r < RR; r++) lst[c++] = rr[r] | 256;
        lst[c++] = MM - 1;
    }
    kcount[idx] = c;
}

// ---------------- HMMA flash attention ----------------
// one CTA per (qblock, head), 256 threads, 8 warps in 2(M)x4(N).
// Q pre-scaled by 0.125 at projection. bf16 hi/lo 3-split for QK^T and PV.
#define ARS  72      // row stride (elems) for 64-col bf16 tiles
#define AVRS 66      // row stride for V^T tiles (64 s-cols)
#define AQH  0
#define AQL  9216
#define AKH  18432
#define AKL  27648
#define APH  36864
#define APL  46080
#define AVTH 55296
#define AVTL 63744
#define ASS  72192   // fp32 64x68
#define AMQ  89600
#define AMK  89856
#define ARSC 90112
#define ARL  90368
#define AENT 90624
#define ATTN_SMEM_B 90880

__global__ __launch_bounds__(256)
void attn_mma(const __nv_bfloat16* __restrict__ qh, const __nv_bfloat16* __restrict__ ql,
              const __nv_bfloat16* __restrict__ kh, const __nv_bfloat16* __restrict__ kl,
              const __nv_bfloat16* __restrict__ vh, const __nv_bfloat16* __restrict__ vl,
              const float* __restrict__ mask,
              const int* __restrict__ klist, const int* __restrict__ kcount,
              __nv_bfloat16* __restrict__ oh, __nv_bfloat16* __restrict__ ol) {
    extern __shared__ char sm[];
    uint32_t sb = smem_u32(sm);
    __nv_bfloat16* Qh  = (__nv_bfloat16*)(sm + AQH);
    __nv_bfloat16* Ql  = (__nv_bfloat16*)(sm + AQL);
    __nv_bfloat16* Kh  = (__nv_bfloat16*)(sm + AKH);
    __nv_bfloat16* Kl  = (__nv_bfloat16*)(sm + AKL);
    __nv_bfloat16* Ph  = (__nv_bfloat16*)(sm + APH);
    __nv_bfloat16* Pl  = (__nv_bfloat16*)(sm + APL);
    __nv_bfloat16* VTh = (__nv_bfloat16*)(sm + AVTH);
    __nv_bfloat16* VTl = (__nv_bfloat16*)(sm + AVTL);
    float* Ss  = (float*)(sm + ASS);
    float* mq  = (float*)(sm + AMQ);
    float* mk  = (float*)(sm + AMK);
    float* rsc = (float*)(sm + ARSC);
    float* rl  = (float*)(sm + ARL);
    int*   ents= (int*)(sm + AENT);

    int qb = blockIdx.x, h = blockIdx.y;
    int tid = threadIdx.x;
    int w = tid >> 5, lane = tid & 31;
    int wm = w & 1, wn = w >> 1;
    int gid = lane >> 2, tig = lane & 3;
    int srow = tid >> 2, sseg = (tid & 3) << 4;
    int lid = h * MM + qb;
    int cnt = kcount[lid];

    if (tid < 64) {
        ents[tid] = klist[lid * 64 + tid];
        mq[tid]   = mask[qb * 64 + tid];
    }
    // load Q (bf16 h/l) via cp.async
    #pragma unroll
    for (int i = 0; i < 2; i++) {
        int linear = tid + i * 256;
        int r = linear >> 3, c8 = (linear & 7) << 3;
        uint32_t doff = (uint32_t)(r * ARS + c8) * 2;
        size_t gofs = (size_t)(qb * 64 + r) * DD + h * DHH + c8;
        cpa16(sb + AQH + doff, qh + gofs);
        cpa16(sb + AQL + doff, ql + gofs);
    }
    cpa_commit();

    float m_run = -1e30f, l_run = 0.f;
    float o[2][2][4];
    #pragma unroll
    for (int i = 0; i < 2; i++)
        #pragma unroll
        for (int j = 0; j < 2; j++)
            #pragma unroll
            for (int r = 0; r < 4; r++) o[i][j][r] = 0.f;

    cpa_wait0();
    __syncthreads();

    for (int b = 0; b < cnt; b++) {
        int e = ents[b], kb = e & 0xff, fl = e >> 8;
        // K via cp.async
        #pragma unroll
        for (int i = 0; i < 2; i++) {
            int linear = tid + i * 256;
            int r = linear >> 3, c8 = (linear & 7) << 3;
            uint32_t doff = (uint32_t)(r * ARS + c8) * 2;
            size_t gofs = (size_t)(kb * 64 + r) * DD + h * DHH + c8;
            cpa16(sb + AKH + doff, kh + gofs);
            cpa16(sb + AKL + doff, kl + gofs);
        }
        cpa_commit();
        // V transposed: VT[d][s]
        #pragma unroll
        for (int i = 0; i < 8; i++) {
            int linear = tid + i * 256;
            int s = linear >> 5, d2 = linear & 31;
            size_t gofs = (size_t)(kb * 64 + s) * DD + h * DHH + d2 * 2;
            uint32_t pv = *(const uint32_t*)(vh + gofs);
            __nv_bfloat162 p2 = *(__nv_bfloat162*)&pv;
            VTh[(d2 * 2) * AVRS + s]     = p2.x;
            VTh[(d2 * 2 + 1) * AVRS + s] = p2.y;
            uint32_t pv2 = *(const uint32_t*)(vl + gofs);
            __nv_bfloat162 q2 = *(__nv_bfloat162*)&pv2;
            VTl[(d2 * 2) * AVRS + s]     = q2.x;
            VTl[(d2 * 2 + 1) * AVRS + s] = q2.y;
        }
        if (tid < 64) mk[tid] = mask[kb * 64 + tid];
        cpa_wait0();
        __syncthreads();

        // S = Q K^T  (3-split)
        float sa[2][2][4];
        #pragma unroll
        for (int i = 0; i < 2; i++)
            #pragma unroll
            for (int j = 0; j < 2; j++)
                #pragma unroll
                for (int r = 0; r < 4; r++) sa[i][j][r] = 0.f;
        #pragma unroll
        for (int ks = 0; ks < 64; ks += 16) {
            int cb = ks + tig * 2;
            uint32_t aH[2][4], aL[2][4], bH[2][2], bL[2][2];
            #pragma unroll
            for (int i = 0; i < 2; i++) {
                int r = wm * 32 + i * 16 + gid;
                aH[i][0] = *(const uint32_t*)(Qh + r * ARS + cb);
                aH[i][1] = *(const uint32_t*)(Qh + (r + 8) * ARS + cb);
                aH[i][2] = *(const uint32_t*)(Qh + r * ARS + cb + 8);
                aH[i][3] = *(const uint32_t*)(Qh + (r + 8) * ARS + cb + 8);
                aL[i][0] = *(const uint32_t*)(Ql + r * ARS + cb);
                aL[i][1] = *(const uint32_t*)(Ql + (r + 8) * ARS + cb);
                aL[i][2] = *(const uint32_t*)(Ql + r * ARS + cb + 8);
                aL[i][3] = *(const uint32_t*)(Ql + (r + 8) * ARS + cb + 8);
            }
            #pragma unroll
            for (int j = 0; j < 2; j++) {
                int nr = wn * 16 + j * 8 + gid;
                bH[j][0] = *(const uint32_t*)(Kh + nr * ARS + cb);
                bH[j][1] = *(const uint32_t*)(Kh + nr * ARS + cb + 8);
                bL[j][0] = *(const uint32_t*)(Kl + nr * ARS + cb);
                bL[j][1] = *(const uint32_t*)(Kl + nr * ARS + cb + 8);
            }
            #pragma unroll
            for (int i = 0; i < 2; i++)
                #pragma unroll
                for (int j = 0; j < 2; j++) {
                    mma_bf16(sa[i][j], aH[i], bH[j]);
                    mma_bf16(sa[i][j], aH[i], bL[j]);
                    mma_bf16(sa[i][j], aL[i], bH[j]);
                }
        }
        #pragma unroll
        for (int i = 0; i < 2; i++) {
            int r = wm * 32 + i * 16 + gid;
            #pragma unroll
            for (int j = 0; j < 2; j++) {
                int c = wn * 16 + j * 8 + tig * 2;
                Ss[r * 68 + c]           = sa[i][j][0];
                Ss[r * 68 + c + 1]       = sa[i][j][1];
                Ss[(r + 8) * 68 + c]     = sa[i][j][2];
                Ss[(r + 8) * 68 + c + 1] = sa[i][j][3];
            }
        }
        __syncthreads();

        // online softmax: 4 threads per row, 16 cols each
        float mqv = mq[srow];
        float sv[16];
        #pragma unroll
        for (int j = 0; j < 16; j += 4) {
            float4 f = *(float4*)(Ss + srow * 68 + sseg + j);
            sv[j] = f.x; sv[j+1] = f.y; sv[j+2] = f.z; sv[j+3] = f.w;
        }
        #pragma unroll
        for (int j = 0; j < 16; j++) {
            float mkv = mk[sseg + j];
            float eff = fl ? (mqv * mkv) : mkv;
            sv[j] += (1.0f - eff) * NEGV;
        }
        float lm = sv[0];
        #pragma unroll
        for (int j = 1; j < 16; j++) lm = fmaxf(lm, sv[j]);
        lm = fmaxf(lm, __shfl_xor_sync(0xffffffffu, lm, 1));
        lm = fmaxf(lm, __shfl_xor_sync(0xffffffffu, lm, 2));
        float m_new = fmaxf(m_run, lm);
        float sc = expf(m_run - m_new);
        float ls = 0.f;
        #pragma unroll
        for (int j = 0; j < 16; j += 2) {
            float p0 = expf(sv[j]     - m_new);
            float p1 = expf(sv[j + 1] - m_new);
            ls += p0 + p1;
            __nv_bfloat162 hh = __floats2bfloat162_rn(p0, p1);
            __nv_bfloat162 llv = __floats2bfloat162_rn(p0 - __bfloat162float(hh.x),
                                                       p1 - __bfloat162float(hh.y));
            *(uint32_t*)(Ph + srow * ARS + sseg + j) = *(uint32_t*)&hh;
            *(uint32_t*)(Pl + srow * ARS + sseg + j) = *(uint32_t*)&llv;
        }
        ls += __shfl_xor_sync(0xffffffffu, ls, 1);
        ls += __shfl_xor_sync(0xffffffffu, ls, 2);
        l_run = l_run * sc + ls;
        m_run = m_new;
        if ((tid & 3) == 0) rsc[srow] = sc;
        __syncthreads();

        // rescale O + PV (3-split)
        #pragma unroll
        for (int i = 0; i < 2; i++) {
            float s0 = rsc[wm * 32 + i * 16 + gid];
            float s1 = rsc[wm * 32 + i * 16 + gid + 8];
            #pragma unroll
            for (int j = 0; j < 2; j++) {
                o[i][j][0] *= s0; o[i][j][1] *= s0;
                o[i][j][2] *= s1; o[i][j][3] *= s1;
            }
        }
        #pragma unroll
        for (int ks = 0; ks < 64; ks += 16) {
            int cb = ks + tig * 2;
            uint32_t aH[2][4], aL[2][4], bH[2][2], bL[2][2];
            #pragma unroll
            for (int i = 0; i < 2; i++) {
                int r = wm * 32 + i * 16 + gid;
                aH[i][0] = *(const uint32_t*)(Ph + r * ARS + cb);
                aH[i][1] = *(const uint32_t*)(Ph + (r + 8) * ARS + cb);
                aH[i][2] = *(const uint32_t*)(Ph + r * ARS + cb + 8);
                aH[i][3] = *(const uint32_t*)(Ph + (r + 8) * ARS + cb + 8);
                aL[i][0] = *(const uint32_t*)(Pl + r * ARS + cb);
                aL[i][1] = *(const uint32_t*)(Pl + (r + 8) * ARS + cb);
                aL[i][2] = *(const uint32_t*)(Pl + r * ARS + cb + 8);
                aL[i][3] = *(const uint32_t*)(Pl + (r + 8) * ARS + cb + 8);
            }
            #pragma unroll
            for (int j = 0; j < 2; j++) {
                int dr = wn * 16 + j * 8 + gid;
                bH[j][0] = *(const uint32_t*)(VTh + dr * AVRS + cb);
                bH[j][1] = *(const uint32_t*)(VTh + dr * AVRS + cb + 8);
                bL[j][0] = *(const uint32_t*)(VTl + dr * AVRS + cb);
                bL[j][1] = *(const uint32_t*)(VTl + dr * AVRS + cb + 8);
            }
            #pragma unroll
            for (int i = 0; i < 2; i++)
                #pragma unroll
                for (int j = 0; j < 2; j++) {
                    mma_bf16(o[i][j], aH[i], bH[j]);
                    mma_bf16(o[i][j], aH[i], bL[j]);
                    mma_bf16(o[i][j], aL[i], bH[j]);
                }
        }
        __syncthreads();
    }

    if ((tid & 3) == 0) rl[srow] = l_run;
    __syncthreads();

    #pragma unroll
    for (int i = 0; i < 2; i++) {
        int r0 = wm * 32 + i * 16 + gid;
        int r1 = r0 + 8;
        float iv0 = mq[r0] / rl[r0];
        float iv1 = mq[r1] / rl[r1];
        #pragma unroll
        for (int j = 0; j < 2; j++) {
            int c = wn * 16 + j * 8 + tig * 2;
            float v0 = o[i][j][0] * iv0, v1 = o[i][j][1] * iv0;
            float v2 = o[i][j][2] * iv1, v3 = o[i][j][3] * iv1;
            __nv_bfloat162 h01 = __floats2bfloat162_rn(v0, v1);
            __nv_bfloat162 h23 = __floats2bfloat162_rn(v2, v3);
            __nv_bfloat162 l01 = __floats2bfloat162_rn(v0 - __bfloat162float(h01.x),
                                                       v1 - __bfloat162float(h01.y));
            __nv_bfloat162 l23 = __floats2bfloat162_rn(v2 - __bfloat162float(h23.x),
                                                       v3 - __bfloat162float(h23.y));
            size_t g0 = (size_t)(qb * 64 + r0) * DD + h * DHH + c;
            size_t g1 = (size_t)(qb * 64 + r1) * DD + h * DHH + c;
            *(uint32_t*)(oh + g0) = *(uint32_t*)&h01;
            *(uint32_t*)(ol + g0) = *(uint32_t*)&l01;
            *(uint32_t*)(oh + g1) = *(uint32_t*)&h23;
            *(uint32_t*)(ol + g1) = *(uint32_t*)&l23;
        }
    }
}

// ---------------- host orchestration ----------------
extern "C" void kernel_launch(void* const* d_in, const int* in_sizes, int n_in,
                              void* d_out, int out_size) {
    (void)in_sizes; (void)n_in; (void)out_size;
    const int*   ids      = (const int*)  d_in[0];
    const float* mask     = (const float*)d_in[1];
    const int*   rand_attn= (const int*)  d_in[2];
    const float* emb_word = (const float*)d_in[3];
    const float* emb_pos  = (const float*)d_in[4];
    const float* eln_g    = (const float*)d_in[5];
    const float* eln_b    = (const float*)d_in[6];
    const float* Wq = (const float*)d_in[7];  const float* bq = (const float*)d_in[8];
    const float* Wk = (const float*)d_in[9];  const float* bk = (const float*)d_in[10];
    const float* Wv = (const float*)d_in[11]; const float* bv = (const float*)d_in[12];
    const float* Wo = (const float*)d_in[13]; const float* bo = (const float*)d_in[14];
    const float* ln1g = (const float*)d_in[15]; const float* ln1b = (const float*)d_in[16];
    const float* W1 = (const float*)d_in[17]; const float* b1 = (const float*)d_in[18];
    const float* W2 = (const float*)d_in[19]; const float* b2 = (const float*)d_in[20];
    const float* ln2g = (const float*)d_in[21]; const float* ln2b = (const float*)d_in[22];
    float* outp = (float*)d_out;

    float *px, *pt;
    __nv_bfloat16 *xh, *xl, *pqh, *pql, *pkh, *pkl2, *pvh, *pvl, *pah, *pal, *pfh, *pfl, *pwh, *pwl;
    int *pklist, *pkc;
    cudaGetSymbolAddress((void**)&px,  g_x);
    cudaGetSymbolAddress((void**)&pt,  g_t);
    cudaGetSymbolAddress((void**)&xh,  g_xh);  cudaGetSymbolAddress((void**)&xl,  g_xl);
    cudaGetSymbolAddress((void**)&pqh, g_qh);  cudaGetSymbolAddress((void**)&pql, g_ql);
    cudaGetSymbolAddress((void**)&pkh, g_kh);  cudaGetSymbolAddress((void**)&pkl2,g_kl);
    cudaGetSymbolAddress((void**)&pvh, g_vh);  cudaGetSymbolAddress((void**)&pvl, g_vl);
    cudaGetSymbolAddress((void**)&pah, g_ah);  cudaGetSymbolAddress((void**)&pal, g_al);
    cudaGetSymbolAddress((void**)&pfh, g_fh);  cudaGetSymbolAddress((void**)&pfl, g_fl);
    cudaGetSymbolAddress((void**)&pwh, g_wTh); cudaGetSymbolAddress((void**)&pwl, g_wTl);
    cudaGetSymbolAddress((void**)&pklist, g_klist);
    cudaGetSymbolAddress((void**)&pkc,    g_kcount);

    cudaFuncSetAttribute(gemm_mma, cudaFuncAttributeMaxDynamicSharedMemorySize, GEMM_SMEM);
    cudaFuncSetAttribute(attn_mma, cudaFuncAttributeMaxDynamicSharedMemorySize, ATTN_SMEM_B);

    const size_t OQ = 0, OK = 589824, OV = 1179648, OO = 1769472, O1 = 2359296, O2 = 4718592;

    dim3 gProj(DD / 128, NN / 128);
    dim3 gF1(FFD / 128, NN / 128);
    dim3 gAttn(MM, HH);
    dim3 gT768(DD / 32, DD / 32);

    // ordering: launch #6 = gemm_mma (for ncu -s 5 -c 1)
    size_t l0 = 0;
    wtrans<<<gT768, 256>>>(Wq, pwh + OQ, pwl + OQ, DD, DD);                      // 1
    embed_kernel<<<NN, 256>>>(ids, emb_word, emb_pos, pt);                       // 2
    ln_kernel<<<NN, 256>>>(pt, nullptr, eln_g, eln_b, px, xh, xl);               // 3
    wtrans<<<gT768, 256>>>(Wk, pwh + OK, pwl + OK, DD, DD);                      // 4
    wtrans<<<gT768, 256>>>(Wv, pwh + OV, pwl + OV, DD, DD);                      // 5
    gemm_mma<<<gProj, 256, GEMM_SMEM>>>(xh, xl, pwh + OQ, pwl + OQ, bq, nullptr, pqh, pql, DD, DD, 0, 0.125f);  // 6
    gemm_mma<<<gProj, 256, GEMM_SMEM>>>(xh, xl, pwh + OK, pwl + OK, bk, nullptr, pkh, pkl2, DD, DD, 0, 1.0f);
    gemm_mma<<<gProj, 256, GEMM_SMEM>>>(xh, xl, pwh + OV, pwl + OV, bv, nullptr, pvh, pvl, DD, DD, 0, 1.0f);
    build_klist<<<(HH * MM + 127) / 128, 128>>>(rand_attn, pklist, pkc);
    wtrans<<<gT768, 256>>>(Wo, pwh + OO, pwl + OO, DD, DD);
    wtrans<<<dim3(FFD/32, DD/32), 256>>>(W1, pwh + O1, pwl + O1, DD, FFD);
    wtrans<<<dim3(DD/32, FFD/32), 256>>>(W2, pwh + O2, pwl + O2, FFD, DD);
    for (int i = 1; i < LL; i++) {
        size_t lo = (size_t)i * WPL;
        wtrans<<<gT768, 256>>>(Wq + (size_t)i*DD*DD, pwh + lo + OQ, pwl + lo + OQ, DD, DD);
        wtrans<<<gT768, 256>>>(Wk + (size_t)i*DD*DD, pwh + lo + OK, pwl + lo + OK, DD, DD);
        wtrans<<<gT768, 256>>>(Wv + (size_t)i*DD*DD, pwh + lo + OV, pwl + lo + OV, DD, DD);
        wtrans<<<gT768, 256>>>(Wo + (size_t)i*DD*DD, pwh + lo + OO, pwl + lo + OO, DD, DD);
        wtrans<<<dim3(FFD/32, DD/32), 256>>>(W1 + (size_t)i*DD*FFD, pwh + lo + O1, pwl + lo + O1, DD, FFD);
        wtrans<<<dim3(DD/32, FFD/32), 256>>>(W2 + (size_t)i*FFD*DD, pwh + lo + O2, pwl + lo + O2, FFD, DD);
    }

    for (int i = 0; i < LL; i++) {
        size_t lo = (size_t)i * WPL;
        if (i > 0) {
            gemm_mma<<<gProj, 256, GEMM_SMEM>>>(xh, xl, pwh + lo + OQ, pwl + lo + OQ, bq + (size_t)i*DD, nullptr, pqh, pql, DD, DD, 0, 0.125f);
            gemm_mma<<<gProj, 256, GEMM_SMEM>>>(xh, xl, pwh + lo + OK, pwl + lo + OK, bk + (size_t)i*DD, nullptr, pkh, pkl2, DD, DD, 0, 1.0f);
            gemm_mma<<<gProj, 256, GEMM_SMEM>>>(xh, xl, pwh + lo + OV, pwl + lo + OV, bv + (size_t)i*DD, nullptr, pvh, pvl, DD, DD, 0, 1.0f);
        }
        attn_mma<<<gAttn, 256, ATTN_SMEM_B>>>(pqh, pql, pkh, pkl2, pvh, pvl, mask, pklist, pkc, pah, pal);
        gemm_mma<<<gProj, 256, GEMM_SMEM>>>(pah, pal, pwh + lo + OO, pwl + lo + OO, bo + (size_t)i*DD, pt, nullptr, nullptr, DD, DD, 0, 1.0f);
        ln_kernel<<<NN, 256>>>(px, pt, ln1g + (size_t)i*DD, ln1b + (size_t)i*DD, px, xh, xl);
        gemm_mma<<<gF1, 256, GEMM_SMEM>>>(xh, xl, pwh + lo + O1, pwl + lo + O1, b1 + (size_t)i*FFD, nullptr, pfh, pfl, FFD, DD, 1, 1.0f);
        gemm_mma<<<gProj, 256, GEMM_SMEM>>>(pfh, pfl, pwh + lo + O2, pwl + lo + O2, b2 + (size_t)i*DD, pt, nullptr, nullptr, DD, FFD, 0, 1.0f);
        if (i == LL - 1)
            ln_kernel<<<NN, 256>>>(px, pt, ln2g + (size_t)i*DD, ln2b + (size_t)i*DD, outp, nullptr, nullptr);
        else
            ln_kernel<<<NN, 256>>>(px, pt, ln2g + (size_t)i*DD, ln2b + (size_t)i*DD, px, xh, xl);
    }
}

// round 6
// speedup vs baseline: 10.1335x; 1.2341x over previous
#include <cuda_runtime.h>
#include <cuda_bf16.h>
#include <math.h>
#include <stdint.h>

// ---------------- problem constants ----------------
#define NN   4096
#define HH   12
#define DHH  64
#define DD   768
#define LL   4
#define FFD  3072
#define MM   64
#define RR   3
#define NEGV (-10000.0f)
#define QKVS 2304

// ---------------- device scratch ----------------
__device__ float g_x [NN * DD];
__device__ float g_t [NN * DD];
__device__ __nv_bfloat16 g_xh[NN * DD],  g_xl[NN * DD];
__device__ __nv_bfloat16 g_qkvh[NN * QKVS], g_qkvl[NN * QKVS];
__device__ __nv_bfloat16 g_ah[NN * DD],  g_al[NN * DD];
__device__ __nv_bfloat16 g_fh[NN * FFD], g_fl[NN * FFD];
__device__ float g_bqkv[LL * QKVS];
__device__ int   g_klist [HH * MM * 64];
__device__ int   g_kcount[HH * MM];
#define WPL 7077888ULL
__device__ __nv_bfloat16 g_wTh[LL * WPL];
__device__ __nv_bfloat16 g_wTl[LL * WPL];

// ---------------- asm helpers ----------------
__device__ __forceinline__ uint32_t smem_u32(const void* p) {
    uint32_t a;
    asm("{ .reg .u64 t; cvta.to.shared.u64 t, %1; cvt.u32.u64 %0, t; }" : "=r"(a) : "l"(p));
    return a;
}
__device__ __forceinline__ void cpa16(uint32_t dst, const void* src) {
    asm volatile("cp.async.cg.shared.global [%0], [%1], 16;" :: "r"(dst), "l"(src));
}
__device__ __forceinline__ void cpa_commit() { asm volatile("cp.async.commit_group;" ::: "memory"); }
__device__ __forceinline__ void cpa_wait0()  { asm volatile("cp.async.wait_group 0;" ::: "memory"); }
__device__ __forceinline__ void cpa_wait1()  { asm volatile("cp.async.wait_group 1;" ::: "memory"); }

__device__ __forceinline__ void mma_bf16(float* c, const uint32_t* a, const uint32_t* b) {
    asm volatile(
        "mma.sync.aligned.m16n8k16.row.col.f32.bf16.bf16.f32 "
        "{%0,%1,%2,%3}, {%4,%5,%6,%7}, {%8,%9}, {%0,%1,%2,%3};"
        : "+f"(c[0]), "+f"(c[1]), "+f"(c[2]), "+f"(c[3])
        : "r"(a[0]), "r"(a[1]), "r"(a[2]), "r"(a[3]), "r"(b[0]), "r"(b[1]));
}
__device__ __forceinline__ void ldm_x4(uint32_t* r, uint32_t addr) {
    asm volatile("ldmatrix.sync.aligned.m8n8.x4.shared.b16 {%0,%1,%2,%3}, [%4];"
        : "=r"(r[0]), "=r"(r[1]), "=r"(r[2]), "=r"(r[3]) : "r"(addr));
}
__device__ __forceinline__ void ldm_x4_t(uint32_t* r, uint32_t addr) {
    asm volatile("ldmatrix.sync.aligned.m8n8.x4.trans.shared.b16 {%0,%1,%2,%3}, [%4];"
        : "=r"(r[0]), "=r"(r[1]), "=r"(r[2]), "=r"(r[3]) : "r"(addr));
}

// ---------------- misc kernels ----------------
__device__ __forceinline__ float block_reduce(float val, bool is_max, float* rbuf) {
    int lane = threadIdx.x & 31;
    int w    = threadIdx.x >> 5;
    #pragma unroll
    for (int o = 16; o; o >>= 1) {
        float other = __shfl_xor_sync(0xffffffffu, val, o);
        val = is_max ? fmaxf(val, other) : (val + other);
    }
    if (lane == 0) rbuf[w] = val;
    __syncthreads();
    if (threadIdx.x == 0) {
        int nw = (blockDim.x + 31) >> 5;
        float r = rbuf[0];
        for (int i = 1; i < nw; i++) r = is_max ? fmaxf(r, rbuf[i]) : (r + rbuf[i]);
        rbuf[0] = r;
    }
    __syncthreads();
    float res = rbuf[0];
    __syncthreads();
    return res;
}

__global__ void embed_kernel(const int* __restrict__ ids,
                             const float* __restrict__ ew,
                             const float* __restrict__ ep,
                             float* __restrict__ out) {
    int t = blockIdx.x;
    int id = ids[t];
    const float* wr = ew + (size_t)id * DD;
    const float* pr = ep + (size_t)t * DD;
    float* o = out + (size_t)t * DD;
    for (int d = threadIdx.x; d < DD; d += blockDim.x)
        o[d] = wr[d] + pr[d];
}

__global__ void ln_kernel(const float* __restrict__ A,
                          const float* __restrict__ Bres,
                          const float* __restrict__ g,
                          const float* __restrict__ b,
                          float* __restrict__ outf,
                          __nv_bfloat16* __restrict__ outh,
                          __nv_bfloat16* __restrict__ outl) {
    __shared__ float s[DD];
    __shared__ float rbuf[8];
    int t = blockIdx.x;
    int tid = threadIdx.x;
    const float* ar = A + (size_t)t * DD;
    const float* br = Bres ? (Bres + (size_t)t * DD) : nullptr;
    float lsum = 0.f;
    for (int d = tid; d < DD; d += blockDim.x) {
        float v = ar[d];
        if (br) v += br[d];
        s[d] = v;
        lsum += v;
    }
    float mu = block_reduce(lsum, false, rbuf) * (1.0f / DD);
    float lvar = 0.f;
    for (int d = tid; d < DD; d += blockDim.x) {
        float dv = s[d] - mu;
        lvar += dv * dv;
    }
    float var = block_reduce(lvar, false, rbuf) * (1.0f / DD);
    float inv = rsqrtf(var + 1e-5f);
    for (int d = tid; d < DD; d += blockDim.x) {
        float val = (s[d] - mu) * inv * g[d] + b[d];
        if (outf) outf[(size_t)t * DD + d] = val;
        if (outh) {
            __nv_bfloat16 h = __float2bfloat16(val);
            outh[(size_t)t * DD + d] = h;
            outl[(size_t)t * DD + d] = __float2bfloat16(val - __bfloat162float(h));
        }
    }
}

__global__ void wtrans(const float* __restrict__ W,
                       __nv_bfloat16* __restrict__ oh,
                       __nv_bfloat16* __restrict__ ol,
                       int K, int N) {
    __shared__ float sm[32][33];
    int n0 = blockIdx.x * 32, k0 = blockIdx.y * 32;
    int tx = threadIdx.x & 31, ty = threadIdx.x >> 5;
    #pragma unroll
    for (int j = 0; j < 4; j++) {
        int kk = ty + j * 8;
        sm[kk][tx] = W[(size_t)(k0 + kk) * N + n0 + tx];
    }
    __syncthreads();
    #pragma unroll
    for (int j = 0; j < 4; j++) {
        int nn = ty + j * 8;
        float v = sm[tx][nn];
        __nv_bfloat16 h = __float2bfloat16(v);
        float r = v - __bfloat162float(h);
        size_t o = (size_t)(n0 + nn) * K + k0 + tx;
        oh[o] = h;
        ol[o] = __float2bfloat16(r);
    }
}

__global__ void bias_cat(const float* __restrict__ bq, const float* __restrict__ bk,
                         const float* __restrict__ bv, float* __restrict__ out) {
    int i = blockIdx.x * blockDim.x + threadIdx.x;
    if (i >= LL * QKVS) return;
    int l = i / QKVS, c = i % QKVS;
    float v;
    if (c < 768)       v = bq[l * 768 + c];
    else if (c < 1536) v = bk[l * 768 + c - 768];
    else               v = bv[l * 768 + c - 1536];
    out[i] = v;
}

// ---------------- HMMA GEMM (ldmatrix + 3-stage cp.async) ----------------
#define RS      40
#define TILE_E  (128 * RS)
#define TILE_B  (TILE_E * 2)
#define STAGE_B (4 * TILE_B)
#define GEMM_SMEM (3 * STAGE_B)

__global__ __launch_bounds__(256)
void gemm_mma(const __nv_bfloat16* __restrict__ Agh, const __nv_bfloat16* __restrict__ Agl,
              const __nv_bfloat16* __restrict__ Bgh, const __nv_bfloat16* __restrict__ Bgl,
              const float* __restrict__ bias,
              float* __restrict__ Cf,
              __nv_bfloat16* __restrict__ Ch, __nv_bfloat16* __restrict__ Cl,
              int Nd, int K, int act, int qs_cols) {
    extern __shared__ __nv_bfloat16 smem[];
    uint32_t sb = smem_u32(smem);
    int tid = threadIdx.x;
    int m0 = blockIdx.y * 128, n0 = blockIdx.x * 128;
    int w = tid >> 5, l = tid & 31;
    int wm = w & 1, wn = w >> 1;
    int gid = l >> 2, tig = l & 3;

    uint32_t lane_a = (uint32_t)((wm * 64 + ((l >> 3) & 1) * 8 + (l & 7)) * RS + (l >> 4) * 8) * 2;
    uint32_t lane_b = (uint32_t)((wn * 32 + (l >> 4) * 8 + (l & 7)) * RS + ((l >> 3) & 1) * 8) * 2;

    float acc[4][4][4];
    #pragma unroll
    for (int i = 0; i < 4; i++)
        #pragma unroll
        for (int j = 0; j < 4; j++)
            #pragma unroll
            for (int r = 0; r < 4; r++) acc[i][j][r] = 0.f;

    int nchunk = K >> 5;

    auto load_chunk = [&](int c, int s) {
        int k0 = c << 5;
        uint32_t stg = sb + s * STAGE_B;
        #pragma unroll
        for (int i = 0; i < 2; i++) {
            int linear = tid + i * 256;
            int row = linear >> 2;
            int kc  = (linear & 3) << 3;
            uint32_t doff = (uint32_t)(row * RS + kc) * 2;
            size_t ga = (size_t)(m0 + row) * K + k0 + kc;
            cpa16(stg + doff,              Agh + ga);
            cpa16(stg + TILE_B + doff,     Agl + ga);
            size_t gb = (size_t)(n0 + row) * K + k0 + kc;
            cpa16(stg + 2 * TILE_B + doff, Bgh + gb);
            cpa16(stg + 3 * TILE_B + doff, Bgl + gb);
        }
    };

    load_chunk(0, 0); cpa_commit();
    if (nchunk > 1) { load_chunk(1, 1); cpa_commit(); }

    for (int c = 0; c < nchunk; c++) {
        if (c + 1 < nchunk) cpa_wait1(); else cpa_wait0();
        __syncthreads();
        uint32_t base = sb + (c % 3) * STAGE_B;

        #pragma unroll
        for (int ks = 0; ks < 32; ks += 16) {
            uint32_t a_h[4][4], a_l[4][4], b_h[4][2], b_l[4][2];
            #pragma unroll
            for (int i = 0; i < 4; i++) {
                ldm_x4(a_h[i], base + lane_a + (uint32_t)(i * 16 * RS + ks) * 2);
                ldm_x4(a_l[i], base + TILE_B + lane_a + (uint32_t)(i * 16 * RS + ks) * 2);
            }
            #pragma unroll
            for (int jj = 0; jj < 2; jj++) {
                uint32_t t[4];
                ldm_x4(t, base + 2 * TILE_B + lane_b + (uint32_t)(jj * 16 * RS + ks) * 2);
                b_h[2 * jj][0] = t[0]; b_h[2 * jj][1] = t[1];
                b_h[2 * jj + 1][0] = t[2]; b_h[2 * jj + 1][1] = t[3];
                ldm_x4(t, base + 3 * TILE_B + lane_b + (uint32_t)(jj * 16 * RS + ks) * 2);
                b_l[2 * jj][0] = t[0]; b_l[2 * jj][1] = t[1];
                b_l[2 * jj + 1][0] = t[2]; b_l[2 * jj + 1][1] = t[3];
            }
            #pragma unroll
            for (int i = 0; i < 4; i++)
                #pragma unroll
                for (int j = 0; j < 4; j++) {
                    mma_bf16(acc[i][j], a_h[i], b_h[j]);
                    mma_bf16(acc[i][j], a_h[i], b_l[j]);
                    mma_bf16(acc[i][j], a_l[i], b_h[j]);
                }
        }
        if (c + 2 < nchunk) { load_chunk(c + 2, (c + 2) % 3); cpa_commit(); }
    }

    #pragma unroll
    for (int i = 0; i < 4; i++) {
        int row = m0 + wm * 64 + i * 16 + gid;
        #pragma unroll
        for (int j = 0; j < 4; j++) {
            int col = n0 + wn * 32 + j * 8 + tig * 2;
            float b0 = bias[col], b1 = bias[col + 1];
            float v0 = acc[i][j][0] + b0;
            float v1 = acc[i][j][1] + b1;
            float v2 = acc[i][j][2] + b0;
            float v3 = acc[i][j][3] + b1;
            if (col < qs_cols) { v0 *= 0.125f; v1 *= 0.125f; v2 *= 0.125f; v3 *= 0.125f; }
            if (act) {
                v0 = 0.5f * v0 * (1.0f + erff(v0 * 0.70710678118654752f));
                v1 = 0.5f * v1 * (1.0f + erff(v1 * 0.70710678118654752f));
                v2 = 0.5f * v2 * (1.0f + erff(v2 * 0.70710678118654752f));
                v3 = 0.5f * v3 * (1.0f + erff(v3 * 0.70710678118654752f));
            }
            if (Cf) {
                *(float2*)(Cf + (size_t)row * Nd + col)       = make_float2(v0, v1);
                *(float2*)(Cf + (size_t)(row + 8) * Nd + col) = make_float2(v2, v3);
            } else {
                __nv_bfloat162 h01 = __floats2bfloat162_rn(v0, v1);
                __nv_bfloat162 h23 = __floats2bfloat162_rn(v2, v3);
                __nv_bfloat162 l01 = __floats2bfloat162_rn(v0 - __bfloat162float(h01.x),
                                                           v1 - __bfloat162float(h01.y));
                __nv_bfloat162 l23 = __floats2bfloat162_rn(v2 - __bfloat162float(h23.x),
                                                           v3 - __bfloat162float(h23.y));
                *(uint32_t*)(Ch + (size_t)row * Nd + col)       = *(uint32_t*)&h01;
                *(uint32_t*)(Cl + (size_t)row * Nd + col)       = *(uint32_t*)&l01;
                *(uint32_t*)(Ch + (size_t)(row + 8) * Nd + col) = *(uint32_t*)&h23;
                *(uint32_t*)(Cl + (size_t)(row + 8) * Nd + col) = *(uint32_t*)&l23;
            }
        }
    }
}

// ---------------- key-block list ----------------
__global__ void build_klist(const int* __restrict__ rand_attn,
                            int* __restrict__ klist,
                            int* __restrict__ kcount) {
    int idx = blockIdx.x * blockDim.x + threadIdx.x;
    if (idx >= HH * MM) return;
    int h  = idx / MM;
    int qb = idx % MM;
    int* lst = klist + idx * 64;
    int c = 0;
    if (qb == 0 || qb == MM - 1) {
        for (int j = 0; j < MM; j++) lst[c++] = j;
    } else if (qb == 1) {
        lst[c++] = 0; lst[c++] = 1; lst[c++] = 2; lst[c++] = MM - 1;
        const int* rr = rand_attn + ((size_t)h * (MM - 2) + 0) * RR;
        for (int r = 0; r < RR; r++) lst[c++] = rr[r] | 256;
    } else if (qb == MM - 2) {
        lst[c++] = 0; lst[c++] = MM - 3; lst[c++] = MM - 2; lst[c++] = MM - 1;
        const int* rr = rand_attn + ((size_t)h * (MM - 2) + (MM - 3)) * RR;
        for (int r = 0; r < RR; r++) lst[c++] = rr[r] | 256;
    } else {
        lst[c++] = 0;
        lst[c++] = (qb - 1) | 256;
        lst[c++] = qb | 256;
        lst[c++] = (qb + 1) | 256;
        const int* rr = rand_attn + ((size_t)h * (MM - 2) + (qb - 1)) * RR;
        for (int r = 0; r < RR; r++) lst[c++] = rr[r] | 256;
        lst[c++] = MM - 1;
    }
    kcount[idx] = c;
}

// ---------------- HMMA flash attention (ldmatrix + KV prefetch) ----------------
#define ARS  72
#define AQH  0
#define AQL  9216
#define AK0  18432
#define AV0  55296
#define APH  92160
#define APL  101376
#define ASS  110592
#define AMQ  128000
#define AMK  128256
#define ARSC 128512
#define ARL  128768
#define AENT 129024
#define ATTN_SMEM_B 129280

__global__ __launch_bounds__(256)
void attn_mma(const __nv_bfloat16* __restrict__ qkvh, const __nv_bfloat16* __restrict__ qkvl,
              const float* __restrict__ mask,
              const int* __restrict__ klist, const int* __restrict__ kcount,
              __nv_bfloat16* __restrict__ oh, __nv_bfloat16* __restrict__ ol) {
    extern __shared__ char sm[];
    uint32_t sb = smem_u32(sm);
    float* Ss  = (float*)(sm + ASS);
    float* mq  = (float*)(sm + AMQ);
    float* mk  = (float*)(sm + AMK);
    float* rsc = (float*)(sm + ARSC);
    float* rl  = (float*)(sm + ARL);
    int*   ents= (int*)(sm + AENT);
    __nv_bfloat16* Ph = (__nv_bfloat16*)(sm + APH);
    __nv_bfloat16* Pl = (__nv_bfloat16*)(sm + APL);

    const __nv_bfloat16* qh = qkvh;
    const __nv_bfloat16* ql = qkvl;
    const __nv_bfloat16* kh = qkvh + 768;
    const __nv_bfloat16* kl = qkvl + 768;
    const __nv_bfloat16* vh = qkvh + 1536;
    const __nv_bfloat16* vl = qkvl + 1536;

    int qb = blockIdx.x, h = blockIdx.y;
    int tid = threadIdx.x;
    int w = tid >> 5, l = tid & 31;
    int wm = w & 1, wn = w >> 1;
    int gid = l >> 2, tig = l & 3;
    int srow = tid >> 2, sseg = (tid & 3) << 4;
    int lid = h * MM + qb;
    int cnt = kcount[lid];

    uint32_t lane_qa = (uint32_t)((wm * 32 + ((l >> 3) & 1) * 8 + (l & 7)) * ARS + (l >> 4) * 8) * 2;
    uint32_t lane_kb = (uint32_t)((wn * 16 + (l >> 4) * 8 + (l & 7)) * ARS + ((l >> 3) & 1) * 8) * 2;
    uint32_t lane_vt = (uint32_t)((((l >> 3) & 1) * 8 + (l & 7)) * ARS + wn * 16 + (l >> 4) * 8) * 2;

    if (tid < 64) {
        ents[tid] = klist[lid * 64 + tid];
        mq[tid]   = mask[qb * 64 + tid];
    }

    auto load_kv = [&](int kb, int s) {
        uint32_t bk_ = sb + AK0 + s * 18432;
        uint32_t bv_ = sb + AV0 + s * 18432;
        #pragma unroll
        for (int i = 0; i < 2; i++) {
            int linear = tid + i * 256;
            int r = linear >> 3, c8 = (linear & 7) << 3;
            uint32_t doff = (uint32_t)(r * ARS + c8) * 2;
            size_t g = (size_t)(kb * 64 + r) * QKVS + h * DHH + c8;
            cpa16(bk_ + doff,        kh + g);
            cpa16(bk_ + 9216 + doff, kl + g);
            cpa16(bv_ + doff,        vh + g);
            cpa16(bv_ + 9216 + doff, vl + g);
        }
    };

    // Q + KV(block 0)
    #pragma unroll
    for (int i = 0; i < 2; i++) {
        int linear = tid + i * 256;
        int r = linear >> 3, c8 = (linear & 7) << 3;
        uint32_t doff = (uint32_t)(r * ARS + c8) * 2;
        size_t g = (size_t)(qb * 64 + r) * QKVS + h * DHH + c8;
        cpa16(sb + AQH + doff, qh + g);
        cpa16(sb + AQL + doff, ql + g);
    }
    __syncthreads();  // ents visible before loop
    {
        int kb0 = ents[0] & 0xff;
        load_kv(kb0, 0);
    }
    cpa_commit();
    cpa_wait0();
    __syncthreads();

    // hoist Q fragments
    uint32_t qfh[2][4][4], qfl[2][4][4];
    #pragma unroll
    for (int i = 0; i < 2; i++)
        #pragma unroll
        for (int ksi = 0; ksi < 4; ksi++) {
            ldm_x4(qfh[i][ksi], sb + AQH + lane_qa + (uint32_t)(i * 16 * ARS + ksi * 16) * 2);
            ldm_x4(qfl[i][ksi], sb + AQL + lane_qa + (uint32_t)(i * 16 * ARS + ksi * 16) * 2);
        }

    float m_run = -1e30f, l_run = 0.f;
    float o[2][2][4];
    #pragma unroll
    for (int i = 0; i < 2; i++)
        #pragma unroll
        for (int j = 0; j < 2; j++)
            #pragma unroll
            for (int r = 0; r < 4; r++) o[i][j][r] = 0.f;

    for (int b = 0; b < cnt; b++) {
        int e = ents[b], kb = e & 0xff, fl = e >> 8;
        if (b > 0) { cpa_wait0(); __syncthreads(); }
        if (b + 1 < cnt) { load_kv(ents[b + 1] & 0xff, (b + 1) & 1); cpa_commit(); }
        if (tid < 64) mk[tid] = mask[kb * 64 + tid];

        uint32_t baseKh = sb + AK0 + (b & 1) * 18432;
        uint32_t baseKl = baseKh + 9216;
        uint32_t baseVh = sb + AV0 + (b & 1) * 18432;
        uint32_t baseVl = baseVh + 9216;

        // S = Q K^T
        float sa[2][2][4];
        #pragma unroll
        for (int i = 0; i < 2; i++)
            #pragma unroll
            for (int j = 0; j < 2; j++)
                #pragma unroll
                for (int r = 0; r < 4; r++) sa[i][j][r] = 0.f;
        #pragma unroll
        for (int ksi = 0; ksi < 4; ksi++) {
            uint32_t bH[2][2], bL[2][2], t[4];
            ldm_x4(t, baseKh + lane_kb + (uint32_t)(ksi * 16) * 2);
            bH[0][0] = t[0]; bH[0][1] = t[1]; bH[1][0] = t[2]; bH[1][1] = t[3];
            ldm_x4(t, baseKl + lane_kb + (uint32_t)(ksi * 16) * 2);
            bL[0][0] = t[0]; bL[0][1] = t[1]; bL[1][0] = t[2]; bL[1][1] = t[3];
            #pragma unroll
            for (int i = 0; i < 2; i++)
                #pragma unroll
                for (int j = 0; j < 2; j++) {
                    mma_bf16(sa[i][j], qfh[i][ksi], bH[j]);
                    mma_bf16(sa[i][j], qfh[i][ksi], bL[j]);
                    mma_bf16(sa[i][j], qfl[i][ksi], bH[j]);
                }
        }
        #pragma unroll
        for (int i = 0; i < 2; i++) {
            int r = wm * 32 + i * 16 + gid;
            #pragma unroll
            for (int j = 0; j < 2; j++) {
                int c = wn * 16 + j * 8 + tig * 2;
                Ss[r * 68 + c]           = sa[i][j][0];
                Ss[r * 68 + c + 1]       = sa[i][j][1];
                Ss[(r + 8) * 68 + c]     = sa[i][j][2];
                Ss[(r + 8) * 68 + c + 1] = sa[i][j][3];
            }
        }
        __syncthreads();

        // online softmax
        float mqv = mq[srow];
        float sv[16];
        #pragma unroll
        for (int j = 0; j < 16; j += 4) {
            float4 f = *(float4*)(Ss + srow * 68 + sseg + j);
            sv[j] = f.x; sv[j+1] = f.y; sv[j+2] = f.z; sv[j+3] = f.w;
        }
        #pragma unroll
        for (int j = 0; j < 16; j++) {
            float mkv = mk[sseg + j];
            float eff = fl ? (mqv * mkv) : mkv;
            sv[j] += (1.0f - eff) * NEGV;
        }
        float lm = sv[0];
        #pragma unroll
        for (int j = 1; j < 16; j++) lm = fmaxf(lm, sv[j]);
        lm = fmaxf(lm, __shfl_xor_sync(0xffffffffu, lm, 1));
        lm = fmaxf(lm, __shfl_xor_sync(0xffffffffu, lm, 2));
        float m_new = fmaxf(m_run, lm);
        float sc = expf(m_run - m_new);
        float ls = 0.f;
        #pragma unroll
        for (int j = 0; j < 16; j += 2) {
            float p0 = expf(sv[j]     - m_new);
            float p1 = expf(sv[j + 1] - m_new);
            ls += p0 + p1;
            __nv_bfloat162 hh = __floats2bfloat162_rn(p0, p1);
            __nv_bfloat162 lv = __floats2bfloat162_rn(p0 - __bfloat162float(hh.x),
                                                      p1 - __bfloat162float(hh.y));
            *(uint32_t*)(Ph + srow * ARS + sseg + j) = *(uint32_t*)&hh;
            *(uint32_t*)(Pl + srow * ARS + sseg + j) = *(uint32_t*)&lv;
        }
        ls += __shfl_xor_sync(0xffffffffu, ls, 1);
        ls += __shfl_xor_sync(0xffffffffu, ls, 2);
        l_run = l_run * sc + ls;
        m_run = m_new;
        if ((tid & 3) == 0) rsc[srow] = sc;
        __syncthreads();

        // rescale O + PV
        #pragma unroll
        for (int i = 0; i < 2; i++) {
            float s0 = rsc[wm * 32 + i * 16 + gid];
            float s1 = rsc[wm * 32 + i * 16 + gid + 8];
            #pragma unroll
            for (int j = 0; j < 2; j++) {
                o[i][j][0] *= s0; o[i][j][1] *= s0;
                o[i][j][2] *= s1; o[i][j][3] *= s1;
            }
        }
        #pragma unroll
        for (int ksi = 0; ksi < 4; ksi++) {
            uint32_t aH[2][4], aL[2][4], bH[2][2], bL[2][2], t[4];
            #pragma unroll
            for (int i = 0; i < 2; i++) {
                ldm_x4(aH[i], sb + APH + lane_qa + (uint32_t)(i * 16 * ARS + ksi * 16) * 2);
                ldm_x4(aL[i], sb + APL + lane_qa + (uint32_t)(i * 16 * ARS + ksi * 16) * 2);
            }
            ldm_x4_t(t, baseVh + lane_vt + (uint32_t)(ksi * 16 * ARS) * 2);
            bH[0][0] = t[0]; bH[0][1] = t[1]; bH[1][0] = t[2]; bH[1][1] = t[3];
            ldm_x4_t(t, baseVl + lane_vt + (uint32_t)(ksi * 16 * ARS) * 2);
            bL[0][0] = t[0]; bL[0][1] = t[1]; bL[1][0] = t[2]; bL[1][1] = t[3];
            #pragma unroll
            for (int i = 0; i < 2; i++)
                #pragma unroll
                for (int j = 0; j < 2; j++) {
                    mma_bf16(o[i][j], aH[i], bH[j]);
                    mma_bf16(o[i][j], aH[i], bL[j]);
                    mma_bf16(o[i][j], aL[i], bH[j]);
                }
        }
    }

    if ((tid & 3) == 0) rl[srow] = l_run;
    __syncthreads();

    #pragma unroll
    for (int i = 0; i < 2; i++) {
        int r0 = wm * 32 + i * 16 + gid;
        int r1 = r0 + 8;
        float iv0 = mq[r0] / rl[r0];
        float iv1 = mq[r1] / rl[r1];
        #pragma unroll
        for (int j = 0; j < 2; j++) {
            int c = wn * 16 + j * 8 + tig * 2;
            float v0 = o[i][j][0] * iv0, v1 = o[i][j][1] * iv0;
            float v2 = o[i][j][2] * iv1, v3 = o[i][j][3] * iv1;
            __nv_bfloat162 h01 = __floats2bfloat162_rn(v0, v1);
            __nv_bfloat162 h23 = __floats2bfloat162_rn(v2, v3);
            __nv_bfloat162 l01 = __floats2bfloat162_rn(v0 - __bfloat162float(h01.x),
                                                       v1 - __bfloat162float(h01.y));
            __nv_bfloat162 l23 = __floats2bfloat162_rn(v2 - __bfloat162float(h23.x),
                                                       v3 - __bfloat162float(h23.y));
            size_t g0 = (size_t)(qb * 64 + r0) * DD + h * DHH + c;
            size_t g1 = (size_t)(qb * 64 + r1) * DD + h * DHH + c;
            *(uint32_t*)(oh + g0) = *(uint32_t*)&h01;
            *(uint32_t*)(ol + g0) = *(uint32_t*)&l01;
            *(uint32_t*)(oh + g1) = *(uint32_t*)&h23;
            *(uint32_t*)(ol + g1) = *(uint32_t*)&l23;
        }
    }
}

// ---------------- host orchestration ----------------
extern "C" void kernel_launch(void* const* d_in, const int* in_sizes, int n_in,
                              void* d_out, int out_size) {
    (void)in_sizes; (void)n_in; (void)out_size;
    const int*   ids      = (const int*)  d_in[0];
    const float* mask     = (const float*)d_in[1];
    const int*   rand_attn= (const int*)  d_in[2];
    const float* emb_word = (const float*)d_in[3];
    const float* emb_pos  = (const float*)d_in[4];
    const float* eln_g    = (const float*)d_in[5];
    const float* eln_b    = (const float*)d_in[6];
    const float* Wq = (const float*)d_in[7];  const float* bq = (const float*)d_in[8];
    const float* Wk = (const float*)d_in[9];  const float* bk = (const float*)d_in[10];
    const float* Wv = (const float*)d_in[11]; const float* bv = (const float*)d_in[12];
    const float* Wo = (const float*)d_in[13]; const float* bo = (const float*)d_in[14];
    const float* ln1g = (const float*)d_in[15]; const float* ln1b = (const float*)d_in[16];
    const float* W1 = (const float*)d_in[17]; const float* b1 = (const float*)d_in[18];
    const float* W2 = (const float*)d_in[19]; const float* b2 = (const float*)d_in[20];
    const float* ln2g = (const float*)d_in[21]; const float* ln2b = (const float*)d_in[22];
    float* outp = (float*)d_out;

    float *px, *pt, *pbqkv;
    __nv_bfloat16 *xh, *xl, *pqkvh, *pqkvl, *pah, *pal, *pfh, *pfl, *pwh, *pwl;
    int *pklist, *pkc;
    cudaGetSymbolAddress((void**)&px,  g_x);
    cudaGetSymbolAddress((void**)&pt,  g_t);
    cudaGetSymbolAddress((void**)&xh,  g_xh);   cudaGetSymbolAddress((void**)&xl,  g_xl);
    cudaGetSymbolAddress((void**)&pqkvh, g_qkvh); cudaGetSymbolAddress((void**)&pqkvl, g_qkvl);
    cudaGetSymbolAddress((void**)&pah, g_ah);   cudaGetSymbolAddress((void**)&pal, g_al);
    cudaGetSymbolAddress((void**)&pfh, g_fh);   cudaGetSymbolAddress((void**)&pfl, g_fl);
    cudaGetSymbolAddress((void**)&pwh, g_wTh);  cudaGetSymbolAddress((void**)&pwl, g_wTl);
    cudaGetSymbolAddress((void**)&pbqkv, g_bqkv);
    cudaGetSymbolAddress((void**)&pklist, g_klist);
    cudaGetSymbolAddress((void**)&pkc,    g_kcount);

    cudaFuncSetAttribute(gemm_mma, cudaFuncAttributeMaxDynamicSharedMemorySize, GEMM_SMEM);
    cudaFuncSetAttribute(attn_mma, cudaFuncAttributeMaxDynamicSharedMemorySize, ATTN_SMEM_B);

    const size_t OQ = 0, OK = 589824, OV = 1179648, OO = 1769472, O1 = 2359296, O2 = 4718592;

    dim3 gQKV(QKVS / 128, NN / 128);  // 18 x 32
    dim3 gProj(DD / 128, NN / 128);   // 6 x 32
    dim3 gF1(FFD / 128, NN / 128);    // 24 x 32
    dim3 gAttn(MM, HH);
    dim3 gT768(DD / 32, DD / 32);

    // launch #1: sacrificial duplicate QKV GEMM for ncu profiling (output
    // overwritten by the real QKV GEMM below before any consumer).
    gemm_mma<<<gQKV, 256, GEMM_SMEM>>>(xh, xl, pwh + OQ, pwl + OQ, pbqkv, nullptr, pqkvh, pqkvl, QKVS, DD, 0, 768);

    embed_kernel<<<NN, 256>>>(ids, emb_word, emb_pos, pt);
    ln_kernel<<<NN, 256>>>(pt, nullptr, eln_g, eln_b, px, xh, xl);
    bias_cat<<<(LL * QKVS + 255) / 256, 256>>>(bq, bk, bv, pbqkv);
    build_klist<<<(HH * MM + 127) / 128, 128>>>(rand_attn, pklist, pkc);
    for (int i = 0; i < LL; i++) {
        size_t lo = (size_t)i * WPL;
        wtrans<<<gT768, 256>>>(Wq + (size_t)i*DD*DD, pwh + lo + OQ, pwl + lo + OQ, DD, DD);
        wtrans<<<gT768, 256>>>(Wk + (size_t)i*DD*DD, pwh + lo + OK, pwl + lo + OK, DD, DD);
        wtrans<<<gT768, 256>>>(Wv + (size_t)i*DD*DD, pwh + lo + OV, pwl + lo + OV, DD, DD);
        wtrans<<<gT768, 256>>>(Wo + (size_t)i*DD*DD, pwh + lo + OO, pwl + lo + OO, DD, DD);
        wtrans<<<dim3(FFD/32, DD/32), 256>>>(W1 + (size_t)i*DD*FFD, pwh + lo + O1, pwl + lo + O1, DD, FFD);
        wtrans<<<dim3(DD/32, FFD/32), 256>>>(W2 + (size_t)i*FFD*DD, pwh + lo + O2, pwl + lo + O2, FFD, DD);
    }

    for (int i = 0; i < LL; i++) {
        size_t lo = (size_t)i * WPL;
        gemm_mma<<<gQKV, 256, GEMM_SMEM>>>(xh, xl, pwh + lo + OQ, pwl + lo + OQ,
                                           pbqkv + (size_t)i * QKVS, nullptr, pqkvh, pqkvl, QKVS, DD, 0, 768);
        attn_mma<<<gAttn, 256, ATTN_SMEM_B>>>(pqkvh, pqkvl, mask, pklist, pkc, pah, pal);
        gemm_mma<<<gProj, 256, GEMM_SMEM>>>(pah, pal, pwh + lo + OO, pwl + lo + OO,
                                            bo + (size_t)i*DD, pt, nullptr, nullptr, DD, DD, 0, 0);
        ln_kernel<<<NN, 256>>>(px, pt, ln1g + (size_t)i*DD, ln1b + (size_t)i*DD, px, xh, xl);
        gemm_mma<<<gF1, 256, GEMM_SMEM>>>(xh, xl, pwh + lo + O1, pwl + lo + O1,
                                          b1 + (size_t)i*FFD, nullptr, pfh, pfl, FFD, DD, 1, 0);
        gemm_mma<<<gProj, 256, GEMM_SMEM>>>(pfh, pfl, pwh + lo + O2, pwl + lo + O2,
                                            b2 + (size_t)i*DD, pt, nullptr, nullptr, DD, FFD, 0, 0);
        if (i == LL - 1)
            ln_kernel<<<NN, 256>>>(px, pt, ln2g + (size_t)i*DD, ln2b + (size_t)i*DD, outp, nullptr, nullptr);
        else
            ln_kernel<<<NN, 256>>>(px, pt, ln2g + (size_t)i*DD, ln2b + (size_t)i*DD, px, xh, xl);
    }
}

// round 7
// speedup vs baseline: 10.5627x; 1.0424x over previous
#include <cuda_runtime.h>
#include <cuda_bf16.h>
#include <math.h>
#include <stdint.h>

// ---------------- problem constants ----------------
#define NN   4096
#define HH   12
#define DHH  64
#define DD   768
#define LL   4
#define FFD  3072
#define MM   64
#define RR   3
#define NEGV (-10000.0f)
#define QKVS 2304

// ---------------- device scratch ----------------
__device__ float g_x [NN * DD];
__device__ float g_t [NN * DD];
__device__ __nv_bfloat16 g_xh[NN * DD],  g_xl[NN * DD];
__device__ __nv_bfloat16 g_qkvh[NN * QKVS], g_qkvl[NN * QKVS];
__device__ __nv_bfloat16 g_ah[NN * DD],  g_al[NN * DD];
__device__ __nv_bfloat16 g_fh[NN * FFD], g_fl[NN * FFD];
__device__ float g_bqkv[LL * QKVS];
__device__ int   g_klist [HH * MM * 64];
__device__ int   g_kcount[HH * MM];
#define WPL 7077888ULL
__device__ __nv_bfloat16 g_wTh[LL * WPL];
__device__ __nv_bfloat16 g_wTl[LL * WPL];

// ---------------- asm helpers ----------------
__device__ __forceinline__ uint32_t smem_u32(const void* p) {
    uint32_t a;
    asm("{ .reg .u64 t; cvta.to.shared.u64 t, %1; cvt.u32.u64 %0, t; }" : "=r"(a) : "l"(p));
    return a;
}
__device__ __forceinline__ void cpa16(uint32_t dst, const void* src) {
    asm volatile("cp.async.cg.shared.global [%0], [%1], 16;" :: "r"(dst), "l"(src));
}
__device__ __forceinline__ void cpa_commit() { asm volatile("cp.async.commit_group;" ::: "memory"); }
__device__ __forceinline__ void cpa_wait0()  { asm volatile("cp.async.wait_group 0;" ::: "memory"); }
__device__ __forceinline__ void cpa_wait2()  { asm volatile("cp.async.wait_group 2;" ::: "memory"); }

__device__ __forceinline__ void mma_bf16(float* c, const uint32_t* a, const uint32_t* b) {
    asm volatile(
        "mma.sync.aligned.m16n8k16.row.col.f32.bf16.bf16.f32 "
        "{%0,%1,%2,%3}, {%4,%5,%6,%7}, {%8,%9}, {%0,%1,%2,%3};"
        : "+f"(c[0]), "+f"(c[1]), "+f"(c[2]), "+f"(c[3])
        : "r"(a[0]), "r"(a[1]), "r"(a[2]), "r"(a[3]), "r"(b[0]), "r"(b[1]));
}
__device__ __forceinline__ void ldm_x4(uint32_t* r, uint32_t addr) {
    asm volatile("ldmatrix.sync.aligned.m8n8.x4.shared.b16 {%0,%1,%2,%3}, [%4];"
        : "=r"(r[0]), "=r"(r[1]), "=r"(r[2]), "=r"(r[3]) : "r"(addr));
}
__device__ __forceinline__ void ldm_x4_t(uint32_t* r, uint32_t addr) {
    asm volatile("ldmatrix.sync.aligned.m8n8.x4.trans.shared.b16 {%0,%1,%2,%3}, [%4];"
        : "=r"(r[0]), "=r"(r[1]), "=r"(r[2]), "=r"(r[3]) : "r"(addr));
}

// ---------------- misc kernels ----------------
__device__ __forceinline__ float block_reduce(float val, bool is_max, float* rbuf) {
    int lane = threadIdx.x & 31;
    int w    = threadIdx.x >> 5;
    #pragma unroll
    for (int o = 16; o; o >>= 1) {
        float other = __shfl_xor_sync(0xffffffffu, val, o);
        val = is_max ? fmaxf(val, other) : (val + other);
    }
    if (lane == 0) rbuf[w] = val;
    __syncthreads();
    if (threadIdx.x == 0) {
        int nw = (blockDim.x + 31) >> 5;
        float r = rbuf[0];
        for (int i = 1; i < nw; i++) r = is_max ? fmaxf(r, rbuf[i]) : (r + rbuf[i]);
        rbuf[0] = r;
    }
    __syncthreads();
    float res = rbuf[0];
    __syncthreads();
    return res;
}

// fused embedding + layernorm
__global__ void embed_ln(const int* __restrict__ ids,
                         const float* __restrict__ ew,
                         const float* __restrict__ ep,
                         const float* __restrict__ g,
                         const float* __restrict__ b,
                         float* __restrict__ outf,
                         __nv_bfloat16* __restrict__ outh,
                         __nv_bfloat16* __restrict__ outl) {
    __shared__ float s[DD];
    __shared__ float rbuf[8];
    int t = blockIdx.x;
    int tid = threadIdx.x;
    int id = ids[t];
    const float* wr = ew + (size_t)id * DD;
    const float* pr = ep + (size_t)t * DD;
    float lsum = 0.f;
    for (int d = tid; d < DD; d += blockDim.x) {
        float v = wr[d] + pr[d];
        s[d] = v;
        lsum += v;
    }
    float mu = block_reduce(lsum, false, rbuf) * (1.0f / DD);
    float lvar = 0.f;
    for (int d = tid; d < DD; d += blockDim.x) {
        float dv = s[d] - mu;
        lvar += dv * dv;
    }
    float var = block_reduce(lvar, false, rbuf) * (1.0f / DD);
    float inv = rsqrtf(var + 1e-5f);
    for (int d = tid; d < DD; d += blockDim.x) {
        float val = (s[d] - mu) * inv * g[d] + b[d];
        outf[(size_t)t * DD + d] = val;
        __nv_bfloat16 h = __float2bfloat16(val);
        outh[(size_t)t * DD + d] = h;
        outl[(size_t)t * DD + d] = __float2bfloat16(val - __bfloat162float(h));
    }
}

__global__ void ln_kernel(const float* __restrict__ A,
                          const float* __restrict__ Bres,
                          const float* __restrict__ g,
                          const float* __restrict__ b,
                          float* __restrict__ outf,
                          __nv_bfloat16* __restrict__ outh,
                          __nv_bfloat16* __restrict__ outl) {
    __shared__ float s[DD];
    __shared__ float rbuf[8];
    int t = blockIdx.x;
    int tid = threadIdx.x;
    const float* ar = A + (size_t)t * DD;
    const float* br = Bres ? (Bres + (size_t)t * DD) : nullptr;
    float lsum = 0.f;
    for (int d = tid; d < DD; d += blockDim.x) {
        float v = ar[d];
        if (br) v += br[d];
        s[d] = v;
        lsum += v;
    }
    float mu = block_reduce(lsum, false, rbuf) * (1.0f / DD);
    float lvar = 0.f;
    for (int d = tid; d < DD; d += blockDim.x) {
        float dv = s[d] - mu;
        lvar += dv * dv;
    }
    float var = block_reduce(lvar, false, rbuf) * (1.0f / DD);
    float inv = rsqrtf(var + 1e-5f);
    for (int d = tid; d < DD; d += blockDim.x) {
        float val = (s[d] - mu) * inv * g[d] + b[d];
        if (outf) outf[(size_t)t * DD + d] = val;
        if (outh) {
            __nv_bfloat16 h = __float2bfloat16(val);
            outh[(size_t)t * DD + d] = h;
            outl[(size_t)t * DD + d] = __float2bfloat16(val - __bfloat162float(h));
        }
    }
}

// generic weight transpose + bf16 hi/lo split: W[K,N] fp32 -> [N,K]
__global__ void wtrans(const float* __restrict__ W,
                       __nv_bfloat16* __restrict__ oh,
                       __nv_bfloat16* __restrict__ ol,
                       int K, int N) {
    __shared__ float sm[32][33];
    int n0 = blockIdx.x * 32, k0 = blockIdx.y * 32;
    int tx = threadIdx.x & 31, ty = threadIdx.x >> 5;
    #pragma unroll
    for (int j = 0; j < 4; j++) {
        int kk = ty + j * 8;
        sm[kk][tx] = W[(size_t)(k0 + kk) * N + n0 + tx];
    }
    __syncthreads();
    #pragma unroll
    for (int j = 0; j < 4; j++) {
        int nn = ty + j * 8;
        float v = sm[tx][nn];
        __nv_bfloat16 h = __float2bfloat16(v);
        float r = v - __bfloat162float(h);
        size_t o = (size_t)(n0 + nn) * K + k0 + tx;
        oh[o] = h;
        ol[o] = __float2bfloat16(r);
    }
}

// fused QKV weight transpose: Wq/Wk/Wv (768x768 each) -> combined [2304,768]
__global__ void wtrans_qkv(const float* __restrict__ Wq, const float* __restrict__ Wk,
                           const float* __restrict__ Wv,
                           __nv_bfloat16* __restrict__ oh, __nv_bfloat16* __restrict__ ol) {
    __shared__ float sm[32][33];
    int n0 = blockIdx.x * 32, k0 = blockIdx.y * 32;
    const float* W = (n0 < 768) ? Wq : (n0 < 1536) ? Wk : Wv;
    int nl0 = n0 % 768;
    int tx = threadIdx.x & 31, ty = threadIdx.x >> 5;
    #pragma unroll
    for (int j = 0; j < 4; j++) {
        int kk = ty + j * 8;
        sm[kk][tx] = W[(size_t)(k0 + kk) * 768 + nl0 + tx];
    }
    __syncthreads();
    #pragma unroll
    for (int j = 0; j < 4; j++) {
        int nn = ty + j * 8;
        float v = sm[tx][nn];
        __nv_bfloat16 h = __float2bfloat16(v);
        float r = v - __bfloat162float(h);
        size_t o = (size_t)(n0 + nn) * DD + k0 + tx;
        oh[o] = h;
        ol[o] = __float2bfloat16(r);
    }
}

__global__ void bias_cat(const float* __restrict__ bq, const float* __restrict__ bk,
                         const float* __restrict__ bv, float* __restrict__ out) {
    int i = blockIdx.x * blockDim.x + threadIdx.x;
    if (i >= LL * QKVS) return;
    int l = i / QKVS, c = i % QKVS;
    float v;
    if (c < 768)       v = bq[l * 768 + c];
    else if (c < 1536) v = bk[l * 768 + c - 768];
    else               v = bv[l * 768 + c - 1536];
    out[i] = v;
}

// ---------------- HMMA GEMM (ldmatrix + 4-stage cp.async) ----------------
#define RS      40
#define TILE_E  (128 * RS)
#define TILE_B  (TILE_E * 2)
#define STAGE_B (4 * TILE_B)
#define GEMM_SMEM (4 * STAGE_B)

__global__ __launch_bounds__(256)
void gemm_mma(const __nv_bfloat16* __restrict__ Agh, const __nv_bfloat16* __restrict__ Agl,
              const __nv_bfloat16* __restrict__ Bgh, const __nv_bfloat16* __restrict__ Bgl,
              const float* __restrict__ bias,
              float* __restrict__ Cf,
              __nv_bfloat16* __restrict__ Ch, __nv_bfloat16* __restrict__ Cl,
              int Nd, int K, int act, int qs_cols) {
    extern __shared__ __nv_bfloat16 smem[];
    uint32_t sb = smem_u32(smem);
    int tid = threadIdx.x;
    int m0 = blockIdx.y * 128, n0 = blockIdx.x * 128;
    int w = tid >> 5, l = tid & 31;
    int wm = w & 1, wn = w >> 1;
    int gid = l >> 2, tig = l & 3;

    uint32_t lane_a = (uint32_t)((wm * 64 + ((l >> 3) & 1) * 8 + (l & 7)) * RS + (l >> 4) * 8) * 2;
    uint32_t lane_b = (uint32_t)((wn * 32 + (l >> 4) * 8 + (l & 7)) * RS + ((l >> 3) & 1) * 8) * 2;

    float acc[4][4][4];
    #pragma unroll
    for (int i = 0; i < 4; i++)
        #pragma unroll
        for (int j = 0; j < 4; j++)
            #pragma unroll
            for (int r = 0; r < 4; r++) acc[i][j][r] = 0.f;

    int nchunk = K >> 5;

    auto load_chunk = [&](int c, int s) {
        int k0 = c << 5;
        uint32_t stg = sb + s * STAGE_B;
        #pragma unroll
        for (int i = 0; i < 2; i++) {
            int linear = tid + i * 256;
            int row = linear >> 2;
            int kc  = (linear & 3) << 3;
            uint32_t doff = (uint32_t)(row * RS + kc) * 2;
            size_t ga = (size_t)(m0 + row) * K + k0 + kc;
            cpa16(stg + doff,              Agh + ga);
            cpa16(stg + TILE_B + doff,     Agl + ga);
            size_t gb = (size_t)(n0 + row) * K + k0 + kc;
            cpa16(stg + 2 * TILE_B + doff, Bgh + gb);
            cpa16(stg + 3 * TILE_B + doff, Bgl + gb);
        }
    };

    // preload 3 chunks (or fewer; empty commits keep group-count invariant)
    #pragma unroll
    for (int p = 0; p < 3; p++) {
        if (p < nchunk) load_chunk(p, p);
        cpa_commit();
    }

    for (int c = 0; c < nchunk; c++) {
        cpa_wait2();          // retires group for chunk c (3 groups always in flight)
        __syncthreads();
        uint32_t base = sb + (c & 3) * STAGE_B;

        #pragma unroll
        for (int ks = 0; ks < 32; ks += 16) {
            uint32_t a_h[4][4], a_l[4][4], b_h[4][2], b_l[4][2];
            #pragma unroll
            for (int i = 0; i < 4; i++) {
                ldm_x4(a_h[i], base + lane_a + (uint32_t)(i * 16 * RS + ks) * 2);
                ldm_x4(a_l[i], base + TILE_B + lane_a + (uint32_t)(i * 16 * RS + ks) * 2);
            }
            #pragma unroll
            for (int jj = 0; jj < 2; jj++) {
                uint32_t t[4];
                ldm_x4(t, base + 2 * TILE_B + lane_b + (uint32_t)(jj * 16 * RS + ks) * 2);
                b_h[2 * jj][0] = t[0]; b_h[2 * jj][1] = t[1];
                b_h[2 * jj + 1][0] = t[2]; b_h[2 * jj + 1][1] = t[3];
                ldm_x4(t, base + 3 * TILE_B + lane_b + (uint32_t)(jj * 16 * RS + ks) * 2);
                b_l[2 * jj][0] = t[0]; b_l[2 * jj][1] = t[1];
                b_l[2 * jj + 1][0] = t[2]; b_l[2 * jj + 1][1] = t[3];
            }
            #pragma unroll
            for (int i = 0; i < 4; i++)
                #pragma unroll
                for (int j = 0; j < 4; j++) {
                    mma_bf16(acc[i][j], a_h[i], b_h[j]);
                    mma_bf16(acc[i][j], a_h[i], b_l[j]);
                    mma_bf16(acc[i][j], a_l[i], b_h[j]);
                }
        }
        if (c + 3 < nchunk) load_chunk(c + 3, (c + 3) & 3);
        cpa_commit();
    }

    #pragma unroll
    for (int i = 0; i < 4; i++) {
        int row = m0 + wm * 64 + i * 16 + gid;
        #pragma unroll
        for (int j = 0; j < 4; j++) {
            int col = n0 + wn * 32 + j * 8 + tig * 2;
            float b0 = bias[col], b1 = bias[col + 1];
            float v0 = acc[i][j][0] + b0;
            float v1 = acc[i][j][1] + b1;
            float v2 = acc[i][j][2] + b0;
            float v3 = acc[i][j][3] + b1;
            if (col < qs_cols) { v0 *= 0.125f; v1 *= 0.125f; v2 *= 0.125f; v3 *= 0.125f; }
            if (act) {
                v0 = 0.5f * v0 * (1.0f + erff(v0 * 0.70710678118654752f));
                v1 = 0.5f * v1 * (1.0f + erff(v1 * 0.70710678118654752f));
                v2 = 0.5f * v2 * (1.0f + erff(v2 * 0.70710678118654752f));
                v3 = 0.5f * v3 * (1.0f + erff(v3 * 0.70710678118654752f));
            }
            if (Cf) {
                *(float2*)(Cf + (size_t)row * Nd + col)       = make_float2(v0, v1);
                *(float2*)(Cf + (size_t)(row + 8) * Nd + col) = make_float2(v2, v3);
            } else {
                __nv_bfloat162 h01 = __floats2bfloat162_rn(v0, v1);
                __nv_bfloat162 h23 = __floats2bfloat162_rn(v2, v3);
                __nv_bfloat162 l01 = __floats2bfloat162_rn(v0 - __bfloat162float(h01.x),
                                                           v1 - __bfloat162float(h01.y));
                __nv_bfloat162 l23 = __floats2bfloat162_rn(v2 - __bfloat162float(h23.x),
                                                           v3 - __bfloat162float(h23.y));
                *(uint32_t*)(Ch + (size_t)row * Nd + col)       = *(uint32_t*)&h01;
                *(uint32_t*)(Cl + (size_t)row * Nd + col)       = *(uint32_t*)&l01;
                *(uint32_t*)(Ch + (size_t)(row + 8) * Nd + col) = *(uint32_t*)&h23;
                *(uint32_t*)(Cl + (size_t)(row + 8) * Nd + col) = *(uint32_t*)&l23;
            }
        }
    }
}

// ---------------- key-block list ----------------
__global__ void build_klist(const int* __restrict__ rand_attn,
                            int* __restrict__ klist,
                            int* __restrict__ kcount) {
    int idx = blockIdx.x * blockDim.x + threadIdx.x;
    if (idx >= HH * MM) return;
    int h  = idx / MM;
    int qb = idx % MM;
    int* lst = klist + idx * 64;
    int c = 0;
    if (qb == 0 || qb == MM - 1) {
        for (int j = 0; j < MM; j++) lst[c++] = j;
    } else if (qb == 1) {
        lst[c++] = 0; lst[c++] = 1; lst[c++] = 2; lst[c++] = MM - 1;
        const int* rr = rand_attn + ((size_t)h * (MM - 2) + 0) * RR;
        for (int r = 0; r < RR; r++) lst[c++] = rr[r] | 256;
    } else if (qb == MM - 2) {
        lst[c++] = 0; lst[c++] = MM - 3; lst[c++] = MM - 2; lst[c++] = MM - 1;
        const int* rr = rand_attn + ((size_t)h * (MM - 2) + (MM - 3)) * RR;
        for (int r = 0; r < RR; r++) lst[c++] = rr[r] | 256;
    } else {
        lst[c++] = 0;
        lst[c++] = (qb - 1) | 256;
        lst[c++] = qb | 256;
        lst[c++] = (qb + 1) | 256;
        const int* rr = rand_attn + ((size_t)h * (MM - 2) + (qb - 1)) * RR;
        for (int r = 0; r < RR; r++) lst[c++] = rr[r] | 256;
        lst[c++] = MM - 1;
    }
    kcount[idx] = c;
}

// ---------------- HMMA flash attention ----------------
#define ARS  72
#define AQH  0
#define AQL  9216
#define AK0  18432
#define AV0  55296
#define APH  92160
#define APL  101376
#define ASS  110592
#define AMQ  128000
#define AMK  128256
#define ARSC 128512
#define ARL  128768
#define AENT 129024
#define ATTN_SMEM_B 129280

__global__ __launch_bounds__(256)
void attn_mma(const __nv_bfloat16* __restrict__ qkvh, const __nv_bfloat16* __restrict__ qkvl,
              const float* __restrict__ mask,
              const int* __restrict__ klist, const int* __restrict__ kcount,
              __nv_bfloat16* __restrict__ oh, __nv_bfloat16* __restrict__ ol) {
    extern __shared__ char sm[];
    uint32_t sb = smem_u32(sm);
    float* Ss  = (float*)(sm + ASS);
    float* mq  = (float*)(sm + AMQ);
    float* mk  = (float*)(sm + AMK);
    float* rsc = (float*)(sm + ARSC);
    float* rl  = (float*)(sm + ARL);
    int*   ents= (int*)(sm + AENT);
    __nv_bfloat16* Ph = (__nv_bfloat16*)(sm + APH);
    __nv_bfloat16* Pl = (__nv_bfloat16*)(sm + APL);

    const __nv_bfloat16* qh = qkvh;
    const __nv_bfloat16* ql = qkvl;
    const __nv_bfloat16* kh = qkvh + 768;
    const __nv_bfloat16* kl = qkvl + 768;
    const __nv_bfloat16* vh = qkvh + 1536;
    const __nv_bfloat16* vl = qkvl + 1536;

    int qb = blockIdx.x, h = blockIdx.y;
    int tid = threadIdx.x;
    int w = tid >> 5, l = tid & 31;
    int wm = w & 1, wn = w >> 1;
    int gid = l >> 2, tig = l & 3;
    int srow = tid >> 2, sseg = (tid & 3) << 4;
    int lid = h * MM + qb;
    int cnt = kcount[lid];

    uint32_t lane_qa = (uint32_t)((wm * 32 + ((l >> 3) & 1) * 8 + (l & 7)) * ARS + (l >> 4) * 8) * 2;
    uint32_t lane_kb = (uint32_t)((wn * 16 + (l >> 4) * 8 + (l & 7)) * ARS + ((l >> 3) & 1) * 8) * 2;
    uint32_t lane_vt = (uint32_t)((((l >> 3) & 1) * 8 + (l & 7)) * ARS + wn * 16 + (l >> 4) * 8) * 2;

    if (tid < 64) {
        ents[tid] = klist[lid * 64 + tid];
        mq[tid]   = mask[qb * 64 + tid];
    }

    auto load_kv = [&](int kb, int s) {
        uint32_t bk_ = sb + AK0 + s * 18432;
        uint32_t bv_ = sb + AV0 + s * 18432;
        #pragma unroll
        for (int i = 0; i < 2; i++) {
            int linear = tid + i * 256;
            int r = linear >> 3, c8 = (linear & 7) << 3;
            uint32_t doff = (uint32_t)(r * ARS + c8) * 2;
            size_t g = (size_t)(kb * 64 + r) * QKVS + h * DHH + c8;
            cpa16(bk_ + doff,        kh + g);
            cpa16(bk_ + 9216 + doff, kl + g);
            cpa16(bv_ + doff,        vh + g);
            cpa16(bv_ + 9216 + doff, vl + g);
        }
    };

    #pragma unroll
    for (int i = 0; i < 2; i++) {
        int linear = tid + i * 256;
        int r = linear >> 3, c8 = (linear & 7) << 3;
        uint32_t doff = (uint32_t)(r * ARS + c8) * 2;
        size_t g = (size_t)(qb * 64 + r) * QKVS + h * DHH + c8;
        cpa16(sb + AQH + doff, qh + g);
        cpa16(sb + AQL + doff, ql + g);
    }
    __syncthreads();
    load_kv(ents[0] & 0xff, 0);
    cpa_commit();
    cpa_wait0();
    __syncthreads();

    uint32_t qfh[2][4][4], qfl[2][4][4];
    #pragma unroll
    for (int i = 0; i < 2; i++)
        #pragma unroll
        for (int ksi = 0; ksi < 4; ksi++) {
            ldm_x4(qfh[i][ksi], sb + AQH + lane_qa + (uint32_t)(i * 16 * ARS + ksi * 16) * 2);
            ldm_x4(qfl[i][ksi], sb + AQL + lane_qa + (uint32_t)(i * 16 * ARS + ksi * 16) * 2);
        }

    float m_run = -1e30f, l_run = 0.f;
    float o[2][2][4];
    #pragma unroll
    for (int i = 0; i < 2; i++)
        #pragma unroll
        for (int j = 0; j < 2; j++)
            #pragma unroll
            for (int r = 0; r < 4; r++) o[i][j][r] = 0.f;

    for (int b = 0; b < cnt; b++) {
        int e = ents[b], kb = e & 0xff, fl = e >> 8;
        if (b > 0) { cpa_wait0(); __syncthreads(); }
        if (b + 1 < cnt) { load_kv(ents[b + 1] & 0xff, (b + 1) & 1); cpa_commit(); }
        if (tid < 64) mk[tid] = mask[kb * 64 + tid];

        uint32_t baseKh = sb + AK0 + (b & 1) * 18432;
        uint32_t baseKl = baseKh + 9216;
        uint32_t baseVh = sb + AV0 + (b & 1) * 18432;
        uint32_t baseVl = baseVh + 9216;

        float sa[2][2][4];
        #pragma unroll
        for (int i = 0; i < 2; i++)
            #pragma unroll
            for (int j = 0; j < 2; j++)
                #pragma unroll
                for (int r = 0; r < 4; r++) sa[i][j][r] = 0.f;
        #pragma unroll
        for (int ksi = 0; ksi < 4; ksi++) {
            uint32_t bH[2][2], bL[2][2], t[4];
            ldm_x4(t, baseKh + lane_kb + (uint32_t)(ksi * 16) * 2);
            bH[0][0] = t[0]; bH[0][1] = t[1]; bH[1][0] = t[2]; bH[1][1] = t[3];
            ldm_x4(t, baseKl + lane_kb + (uint32_t)(ksi * 16) * 2);
            bL[0][0] = t[0]; bL[0][1] = t[1]; bL[1][0] = t[2]; bL[1][1] = t[3];
            #pragma unroll
            for (int i = 0; i < 2; i++)
                #pragma unroll
                for (int j = 0; j < 2; j++) {
                    mma_bf16(sa[i][j], qfh[i][ksi], bH[j]);
                    mma_bf16(sa[i][j], qfh[i][ksi], bL[j]);
                    mma_bf16(sa[i][j], qfl[i][ksi], bH[j]);
                }
        }
        #pragma unroll
        for (int i = 0; i < 2; i++) {
            int r = wm * 32 + i * 16 + gid;
            #pragma unroll
            for (int j = 0; j < 2; j++) {
                int c = wn * 16 + j * 8 + tig * 2;
                Ss[r * 68 + c]           = sa[i][j][0];
                Ss[r * 68 + c + 1]       = sa[i][j][1];
                Ss[(r + 8) * 68 + c]     = sa[i][j][2];
                Ss[(r + 8) * 68 + c + 1] = sa[i][j][3];
            }
        }
        __syncthreads();

        float mqv = mq[srow];
        float sv[16];
        #pragma unroll
        for (int j = 0; j < 16; j += 4) {
            float4 f = *(float4*)(Ss + srow * 68 + sseg + j);
            sv[j] = f.x; sv[j+1] = f.y; sv[j+2] = f.z; sv[j+3] = f.w;
        }
        #pragma unroll
        for (int j = 0; j < 16; j++) {
            float mkv = mk[sseg + j];
            float eff = fl ? (mqv * mkv) : mkv;
            sv[j] += (1.0f - eff) * NEGV;
        }
        float lm = sv[0];
        #pragma unroll
        for (int j = 1; j < 16; j++) lm = fmaxf(lm, sv[j]);
        lm = fmaxf(lm, __shfl_xor_sync(0xffffffffu, lm, 1));
        lm = fmaxf(lm, __shfl_xor_sync(0xffffffffu, lm, 2));
        float m_new = fmaxf(m_run, lm);
        float sc = expf(m_run - m_new);
        float ls = 0.f;
        #pragma unroll
        for (int j = 0; j < 16; j += 2) {
            float p0 = expf(sv[j]     - m_new);
            float p1 = expf(sv[j + 1] - m_new);
            ls += p0 + p1;
            __nv_bfloat162 hh = __floats2bfloat162_rn(p0, p1);
            __nv_bfloat162 lv = __floats2bfloat162_rn(p0 - __bfloat162float(hh.x),
                                                      p1 - __bfloat162float(hh.y));
            *(uint32_t*)(Ph + srow * ARS + sseg + j) = *(uint32_t*)&hh;
            *(uint32_t*)(Pl + srow * ARS + sseg + j) = *(uint32_t*)&lv;
        }
        ls += __shfl_xor_sync(0xffffffffu, ls, 1);
        ls += __shfl_xor_sync(0xffffffffu, ls, 2);
        l_run = l_run * sc + ls;
        m_run = m_new;
        if ((tid & 3) == 0) rsc[srow] = sc;
        __syncthreads();

        #pragma unroll
        for (int i = 0; i < 2; i++) {
            float s0 = rsc[wm * 32 + i * 16 + gid];
            float s1 = rsc[wm * 32 + i * 16 + gid + 8];
            #pragma unroll
            for (int j = 0; j < 2; j++) {
                o[i][j][0] *= s0; o[i][j][1] *= s0;
                o[i][j][2] *= s1; o[i][j][3] *= s1;
            }
        }
        #pragma unroll
        for (int ksi = 0; ksi < 4; ksi++) {
            uint32_t aH[2][4], aL[2][4], bH[2][2], bL[2][2], t[4];
            #pragma unroll
            for (int i = 0; i < 2; i++) {
                ldm_x4(aH[i], sb + APH + lane_qa + (uint32_t)(i * 16 * ARS + ksi * 16) * 2);
                ldm_x4(aL[i], sb + APL + lane_qa + (uint32_t)(i * 16 * ARS + ksi * 16) * 2);
            }
            ldm_x4_t(t, baseVh + lane_vt + (uint32_t)(ksi * 16 * ARS) * 2);
            bH[0][0] = t[0]; bH[0][1] = t[1]; bH[1][0] = t[2]; bH[1][1] = t[3];
            ldm_x4_t(t, baseVl + lane_vt + (uint32_t)(ksi * 16 * ARS) * 2);
            bL[0][0] = t[0]; bL[0][1] = t[1]; bL[1][0] = t[2]; bL[1][1] = t[3];
            #pragma unroll
            for (int i = 0; i < 2; i++)
                #pragma unroll
                for (int j = 0; j < 2; j++) {
                    mma_bf16(o[i][j], aH[i], bH[j]);
                    mma_bf16(o[i][j], aH[i], bL[j]);
                    mma_bf16(o[i][j], aL[i], bH[j]);
                }
        }
    }

    if ((tid & 3) == 0) rl[srow] = l_run;
    __syncthreads();

    #pragma unroll
    for (int i = 0; i < 2; i++) {
        int r0 = wm * 32 + i * 16 + gid;
        int r1 = r0 + 8;
        float iv0 = mq[r0] / rl[r0];
        float iv1 = mq[r1] / rl[r1];
        #pragma unroll
        for (int j = 0; j < 2; j++) {
            int c = wn * 16 + j * 8 + tig * 2;
            float v0 = o[i][j][0] * iv0, v1 = o[i][j][1] * iv0;
            float v2 = o[i][j][2] * iv1, v3 = o[i][j][3] * iv1;
            __nv_bfloat162 h01 = __floats2bfloat162_rn(v0, v1);
            __nv_bfloat162 h23 = __floats2bfloat162_rn(v2, v3);
            __nv_bfloat162 l01 = __floats2bfloat162_rn(v0 - __bfloat162float(h01.x),
                                                       v1 - __bfloat162float(h01.y));
            __nv_bfloat162 l23 = __floats2bfloat162_rn(v2 - __bfloat162float(h23.x),
                                                       v3 - __bfloat162float(h23.y));
            size_t g0 = (size_t)(qb * 64 + r0) * DD + h * DHH + c;
            size_t g1 = (size_t)(qb * 64 + r1) * DD + h * DHH + c;
            *(uint32_t*)(oh + g0) = *(uint32_t*)&h01;
            *(uint32_t*)(ol + g0) = *(uint32_t*)&l01;
            *(uint32_t*)(oh + g1) = *(uint32_t*)&h23;
            *(uint32_t*)(ol + g1) = *(uint32_t*)&l23;
        }
    }
}

// ---------------- host orchestration ----------------
extern "C" void kernel_launch(void* const* d_in, const int* in_sizes, int n_in,
                              void* d_out, int out_size) {
    (void)in_sizes; (void)n_in; (void)out_size;
    const int*   ids      = (const int*)  d_in[0];
    const float* mask     = (const float*)d_in[1];
    const int*   rand_attn= (const int*)  d_in[2];
    const float* emb_word = (const float*)d_in[3];
    const float* emb_pos  = (const float*)d_in[4];
    const float* eln_g    = (const float*)d_in[5];
    const float* eln_b    = (const float*)d_in[6];
    const float* Wq = (const float*)d_in[7];  const float* bq = (const float*)d_in[8];
    const float* Wk = (const float*)d_in[9];  const float* bk = (const float*)d_in[10];
    const float* Wv = (const float*)d_in[11]; const float* bv = (const float*)d_in[12];
    const float* Wo = (const float*)d_in[13]; const float* bo = (const float*)d_in[14];
    const float* ln1g = (const float*)d_in[15]; const float* ln1b = (const float*)d_in[16];
    const float* W1 = (const float*)d_in[17]; const float* b1 = (const float*)d_in[18];
    const float* W2 = (const float*)d_in[19]; const float* b2 = (const float*)d_in[20];
    const float* ln2g = (const float*)d_in[21]; const float* ln2b = (const float*)d_in[22];
    float* outp = (float*)d_out;

    float *px, *pt, *pbqkv;
    __nv_bfloat16 *xh, *xl, *pqkvh, *pqkvl, *pah, *pal, *pfh, *pfl, *pwh, *pwl;
    int *pklist, *pkc;
    cudaGetSymbolAddress((void**)&px,  g_x);
    cudaGetSymbolAddress((void**)&pt,  g_t);
    cudaGetSymbolAddress((void**)&xh,  g_xh);   cudaGetSymbolAddress((void**)&xl,  g_xl);
    cudaGetSymbolAddress((void**)&pqkvh, g_qkvh); cudaGetSymbolAddress((void**)&pqkvl, g_qkvl);
    cudaGetSymbolAddress((void**)&pah, g_ah);   cudaGetSymbolAddress((void**)&pal, g_al);
    cudaGetSymbolAddress((void**)&pfh, g_fh);   cudaGetSymbolAddress((void**)&pfl, g_fl);
    cudaGetSymbolAddress((void**)&pwh, g_wTh);  cudaGetSymbolAddress((void**)&pwl, g_wTl);
    cudaGetSymbolAddress((void**)&pbqkv, g_bqkv);
    cudaGetSymbolAddress((void**)&pklist, g_klist);
    cudaGetSymbolAddress((void**)&pkc,    g_kcount);

    cudaFuncSetAttribute(gemm_mma, cudaFuncAttributeMaxDynamicSharedMemorySize, GEMM_SMEM);
    cudaFuncSetAttribute(attn_mma, cudaFuncAttributeMaxDynamicSharedMemorySize, ATTN_SMEM_B);

    const size_t OQ = 0, OO = 1769472, O1 = 2359296, O2 = 4718592;

    dim3 gQKV(QKVS / 128, NN / 128);  // 18 x 32
    dim3 gProj(DD / 128, NN / 128);   // 6 x 32
    dim3 gF1(FFD / 128, NN / 128);    // 24 x 32
    dim3 gAttn(MM, HH);
    dim3 gT768(DD / 32, DD / 32);
    dim3 gTQKV(QKVS / 32, DD / 32);   // 72 x 24

    // launch order: #4 (ncu capture position) = layer-0 QKV gemm_mma
    embed_ln<<<NN, 256>>>(ids, emb_word, emb_pos, eln_g, eln_b, px, xh, xl);          // 1
    bias_cat<<<(LL * QKVS + 255) / 256, 256>>>(bq, bk, bv, pbqkv);                    // 2
    wtrans_qkv<<<gTQKV, 256>>>(Wq, Wk, Wv, pwh + OQ, pwl + OQ);                       // 3
    gemm_mma<<<gQKV, 256, GEMM_SMEM>>>(xh, xl, pwh + OQ, pwl + OQ,
                                       pbqkv, nullptr, pqkvh, pqkvl, QKVS, DD, 0, 768); // 4 <- profiled
    build_klist<<<(HH * MM + 127) / 128, 128>>>(rand_attn, pklist, pkc);

    // remaining weight preprocessing
    wtrans<<<gT768, 256>>>(Wo, pwh + OO, pwl + OO, DD, DD);
    wtrans<<<dim3(FFD/32, DD/32), 256>>>(W1, pwh + O1, pwl + O1, DD, FFD);
    wtrans<<<dim3(DD/32, FFD/32), 256>>>(W2, pwh + O2, pwl + O2, FFD, DD);
    for (int i = 1; i < LL; i++) {
        size_t lo = (size_t)i * WPL;
        wtrans_qkv<<<gTQKV, 256>>>(Wq + (size_t)i*DD*DD, Wk + (size_t)i*DD*DD, Wv + (size_t)i*DD*DD,
                                   pwh + lo + OQ, pwl + lo + OQ);
        wtrans<<<gT768, 256>>>(Wo + (size_t)i*DD*DD, pwh + lo + OO, pwl + lo + OO, DD, DD);
        wtrans<<<dim3(FFD/32, DD/32), 256>>>(W1 + (size_t)i*DD*FFD, pwh + lo + O1, pwl + lo + O1, DD, FFD);
        wtrans<<<dim3(DD/32, FFD/32), 256>>>(W2 + (size_t)i*FFD*DD, pwh + lo + O2, pwl + lo + O2, FFD, DD);
    }

    for (int i = 0; i < LL; i++) {
        size_t lo = (size_t)i * WPL;
        if (i > 0)
            gemm_mma<<<gQKV, 256, GEMM_SMEM>>>(xh, xl, pwh + lo + OQ, pwl + lo + OQ,
                                               pbqkv + (size_t)i * QKVS, nullptr, pqkvh, pqkvl, QKVS, DD, 0, 768);
        attn_mma<<<gAttn, 256, ATTN_SMEM_B>>>(pqkvh, pqkvl, mask, pklist, pkc, pah, pal);
        gemm_mma<<<gProj, 256, GEMM_SMEM>>>(pah, pal, pwh + lo + OO, pwl + lo + OO,
                                            bo + (size_t)i*DD, pt, nullptr, nullptr, DD, DD, 0, 0);
        ln_kernel<<<NN, 256>>>(px, pt, ln1g + (size_t)i*DD, ln1b + (size_t)i*DD, px, xh, xl);
        gemm_mma<<<gF1, 256, GEMM_SMEM>>>(xh, xl, pwh + lo + O1, pwl + lo + O1,
                                          b1 + (size_t)i*FFD, nullptr, pfh, pfl, FFD, DD, 1, 0);
        gemm_mma<<<gProj, 256, GEMM_SMEM>>>(pfh, pfl, pwh + lo + O2, pwl + lo + O2,
                                            b2 + (size_t)i*DD, pt, nullptr, nullptr, DD, FFD, 0, 0);
        if (i == LL - 1)
            ln_kernel<<<NN, 256>>>(px, pt, ln2g + (size_t)i*DD, ln2b + (size_t)i*DD, outp, nullptr, nullptr);
        else
            ln_kernel<<<NN, 256>>>(px, pt, ln2g + (size_t)i*DD, ln2b + (size_t)i*DD, px, xh, xl);
    }
}

// round 8
// speedup vs baseline: 11.3477x; 1.0743x over previous
#include <cuda_runtime.h>
#include <cuda_bf16.h>
#include <math.h>
#include <stdint.h>

// ---------------- problem constants ----------------
#define NN   4096
#define HH   12
#define DHH  64
#define DD   768
#define LL   4
#define FFD  3072
#define MM   64
#define RR   3
#define NEGV (-10000.0f)
#define QKVS 2304

// ---------------- device scratch ----------------
__device__ float g_x [NN * DD];
__device__ float g_t [NN * DD];
__device__ __nv_bfloat16 g_xh[NN * DD],  g_xl[NN * DD];
__device__ __nv_bfloat16 g_qkvh[NN * QKVS], g_qkvl[NN * QKVS];
__device__ __nv_bfloat16 g_ah[NN * DD],  g_al[NN * DD];
__device__ __nv_bfloat16 g_fh[NN * FFD], g_fl[NN * FFD];
__device__ float g_bqkv[LL * QKVS];
__device__ int   g_klist [HH * MM * 64];
__device__ int   g_kcount[HH * MM];
#define WPL 7077888ULL
__device__ __nv_bfloat16 g_wTh[LL * WPL];
__device__ __nv_bfloat16 g_wTl[LL * WPL];

// ---------------- asm helpers ----------------
__device__ __forceinline__ uint32_t smem_u32(const void* p) {
    uint32_t a;
    asm("{ .reg .u64 t; cvta.to.shared.u64 t, %1; cvt.u32.u64 %0, t; }" : "=r"(a) : "l"(p));
    return a;
}
__device__ __forceinline__ void cpa16(uint32_t dst, const void* src) {
    asm volatile("cp.async.cg.shared.global [%0], [%1], 16;" :: "r"(dst), "l"(src));
}
__device__ __forceinline__ void cpa_commit() { asm volatile("cp.async.commit_group;" ::: "memory"); }
__device__ __forceinline__ void cpa_wait0()  { asm volatile("cp.async.wait_group 0;" ::: "memory"); }
__device__ __forceinline__ void cpa_wait1()  { asm volatile("cp.async.wait_group 1;" ::: "memory"); }

__device__ __forceinline__ void mma_bf16(float* c, const uint32_t* a, const uint32_t* b) {
    asm volatile(
        "mma.sync.aligned.m16n8k16.row.col.f32.bf16.bf16.f32 "
        "{%0,%1,%2,%3}, {%4,%5,%6,%7}, {%8,%9}, {%0,%1,%2,%3};"
        : "+f"(c[0]), "+f"(c[1]), "+f"(c[2]), "+f"(c[3])
        : "r"(a[0]), "r"(a[1]), "r"(a[2]), "r"(a[3]), "r"(b[0]), "r"(b[1]));
}
__device__ __forceinline__ void ldm_x4(uint32_t* r, uint32_t addr) {
    asm volatile("ldmatrix.sync.aligned.m8n8.x4.shared.b16 {%0,%1,%2,%3}, [%4];"
        : "=r"(r[0]), "=r"(r[1]), "=r"(r[2]), "=r"(r[3]) : "r"(addr));
}
__device__ __forceinline__ void ldm_x4_t(uint32_t* r, uint32_t addr) {
    asm volatile("ldmatrix.sync.aligned.m8n8.x4.trans.shared.b16 {%0,%1,%2,%3}, [%4];"
        : "=r"(r[0]), "=r"(r[1]), "=r"(r[2]), "=r"(r[3]) : "r"(addr));
}

// ---------------- misc kernels ----------------
__device__ __forceinline__ float block_reduce(float val, bool is_max, float* rbuf) {
    int lane = threadIdx.x & 31;
    int w    = threadIdx.x >> 5;
    #pragma unroll
    for (int o = 16; o; o >>= 1) {
        float other = __shfl_xor_sync(0xffffffffu, val, o);
        val = is_max ? fmaxf(val, other) : (val + other);
    }
    if (lane == 0) rbuf[w] = val;
    __syncthreads();
    if (threadIdx.x == 0) {
        int nw = (blockDim.x + 31) >> 5;
        float r = rbuf[0];
        for (int i = 1; i < nw; i++) r = is_max ? fmaxf(r, rbuf[i]) : (r + rbuf[i]);
        rbuf[0] = r;
    }
    __syncthreads();
    float res = rbuf[0];
    __syncthreads();
    return res;
}

__global__ void embed_ln(const int* __restrict__ ids,
                         const float* __restrict__ ew,
                         const float* __restrict__ ep,
                         const float* __restrict__ g,
                         const float* __restrict__ b,
                         float* __restrict__ outf,
                         __nv_bfloat16* __restrict__ outh,
                         __nv_bfloat16* __restrict__ outl) {
    __shared__ float s[DD];
    __shared__ float rbuf[8];
    int t = blockIdx.x;
    int tid = threadIdx.x;
    int id = ids[t];
    const float* wr = ew + (size_t)id * DD;
    const float* pr = ep + (size_t)t * DD;
    float lsum = 0.f;
    for (int d = tid; d < DD; d += blockDim.x) {
        float v = wr[d] + pr[d];
        s[d] = v;
        lsum += v;
    }
    float mu = block_reduce(lsum, false, rbuf) * (1.0f / DD);
    float lvar = 0.f;
    for (int d = tid; d < DD; d += blockDim.x) {
        float dv = s[d] - mu;
        lvar += dv * dv;
    }
    float var = block_reduce(lvar, false, rbuf) * (1.0f / DD);
    float inv = rsqrtf(var + 1e-5f);
    for (int d = tid; d < DD; d += blockDim.x) {
        float val = (s[d] - mu) * inv * g[d] + b[d];
        outf[(size_t)t * DD + d] = val;
        __nv_bfloat16 h = __float2bfloat16(val);
        outh[(size_t)t * DD + d] = h;
        outl[(size_t)t * DD + d] = __float2bfloat16(val - __bfloat162float(h));
    }
}

__global__ void ln_kernel(const float* __restrict__ A,
                          const float* __restrict__ Bres,
                          const float* __restrict__ g,
                          const float* __restrict__ b,
                          float* __restrict__ outf,
                          __nv_bfloat16* __restrict__ outh,
                          __nv_bfloat16* __restrict__ outl) {
    __shared__ float s[DD];
    __shared__ float rbuf[8];
    int t = blockIdx.x;
    int tid = threadIdx.x;
    const float* ar = A + (size_t)t * DD;
    const float* br = Bres ? (Bres + (size_t)t * DD) : nullptr;
    float lsum = 0.f;
    for (int d = tid; d < DD; d += blockDim.x) {
        float v = ar[d];
        if (br) v += br[d];
        s[d] = v;
        lsum += v;
    }
    float mu = block_reduce(lsum, false, rbuf) * (1.0f / DD);
    float lvar = 0.f;
    for (int d = tid; d < DD; d += blockDim.x) {
        float dv = s[d] - mu;
        lvar += dv * dv;
    }
    float var = block_reduce(lvar, false, rbuf) * (1.0f / DD);
    float inv = rsqrtf(var + 1e-5f);
    for (int d = tid; d < DD; d += blockDim.x) {
        float val = (s[d] - mu) * inv * g[d] + b[d];
        if (outf) outf[(size_t)t * DD + d] = val;
        if (outh) {
            __nv_bfloat16 h = __float2bfloat16(val);
            outh[(size_t)t * DD + d] = h;
            outl[(size_t)t * DD + d] = __float2bfloat16(val - __bfloat162float(h));
        }
    }
}

__global__ void wtrans(const float* __restrict__ W,
                       __nv_bfloat16* __restrict__ oh,
                       __nv_bfloat16* __restrict__ ol,
                       int K, int N) {
    __shared__ float sm[32][33];
    int n0 = blockIdx.x * 32, k0 = blockIdx.y * 32;
    int tx = threadIdx.x & 31, ty = threadIdx.x >> 5;
    #pragma unroll
    for (int j = 0; j < 4; j++) {
        int kk = ty + j * 8;
        sm[kk][tx] = W[(size_t)(k0 + kk) * N + n0 + tx];
    }
    __syncthreads();
    #pragma unroll
    for (int j = 0; j < 4; j++) {
        int nn = ty + j * 8;
        float v = sm[tx][nn];
        __nv_bfloat16 h = __float2bfloat16(v);
        float r = v - __bfloat162float(h);
        size_t o = (size_t)(n0 + nn) * K + k0 + tx;
        oh[o] = h;
        ol[o] = __float2bfloat16(r);
    }
}

__global__ void wtrans_qkv(const float* __restrict__ Wq, const float* __restrict__ Wk,
                           const float* __restrict__ Wv,
                           __nv_bfloat16* __restrict__ oh, __nv_bfloat16* __restrict__ ol) {
    __shared__ float sm[32][33];
    int n0 = blockIdx.x * 32, k0 = blockIdx.y * 32;
    const float* W = (n0 < 768) ? Wq : (n0 < 1536) ? Wk : Wv;
    int nl0 = n0 % 768;
    int tx = threadIdx.x & 31, ty = threadIdx.x >> 5;
    #pragma unroll
    for (int j = 0; j < 4; j++) {
        int kk = ty + j * 8;
        sm[kk][tx] = W[(size_t)(k0 + kk) * 768 + nl0 + tx];
    }
    __syncthreads();
    #pragma unroll
    for (int j = 0; j < 4; j++) {
        int nn = ty + j * 8;
        float v = sm[tx][nn];
        __nv_bfloat16 h = __float2bfloat16(v);
        float r = v - __bfloat162float(h);
        size_t o = (size_t)(n0 + nn) * DD + k0 + tx;
        oh[o] = h;
        ol[o] = __float2bfloat16(r);
    }
}

__global__ void bias_cat(const float* __restrict__ bq, const float* __restrict__ bk,
                         const float* __restrict__ bv, float* __restrict__ out) {
    int i = blockIdx.x * blockDim.x + threadIdx.x;
    if (i >= LL * QKVS) return;
    int l = i / QKVS, c = i % QKVS;
    float v;
    if (c < 768)       v = bq[l * 768 + c];
    else if (c < 1536) v = bk[l * 768 + c - 768];
    else               v = bv[l * 768 + c - 1536];
    out[i] = v;
}

// ---------------- HMMA GEMM: k-chunk 64, 3 stages, reg-double-buffered frags ----
#define RS      72                  // 64 + 8 pad (bf16 elems)
#define TILE_E  (128 * RS)
#define TILE_B  (TILE_E * 2)        // 18432 B
#define STAGE_B (4 * TILE_B)        // 73728 B
#define GEMM_SMEM (3 * STAGE_B)     // 221184 B

__global__ __launch_bounds__(256)
void gemm_mma(const __nv_bfloat16* __restrict__ Agh, const __nv_bfloat16* __restrict__ Agl,
              const __nv_bfloat16* __restrict__ Bgh, const __nv_bfloat16* __restrict__ Bgl,
              const float* __restrict__ bias,
              float* __restrict__ Cf,
              __nv_bfloat16* __restrict__ Ch, __nv_bfloat16* __restrict__ Cl,
              int Nd, int K, int act, int qs_cols) {
    extern __shared__ __nv_bfloat16 smem[];
    uint32_t sb = smem_u32(smem);
    int tid = threadIdx.x;
    int m0 = blockIdx.y * 128, n0 = blockIdx.x * 128;
    int w = tid >> 5, l = tid & 31;
    int wm = w & 1, wn = w >> 1;
    int gid = l >> 2, tig = l & 3;

    uint32_t lane_a = (uint32_t)((wm * 64 + ((l >> 3) & 1) * 8 + (l & 7)) * RS + (l >> 4) * 8) * 2;
    uint32_t lane_b = (uint32_t)((wn * 32 + (l >> 4) * 8 + (l & 7)) * RS + ((l >> 3) & 1) * 8) * 2;

    float acc[4][4][4];
    #pragma unroll
    for (int i = 0; i < 4; i++)
        #pragma unroll
        for (int j = 0; j < 4; j++)
            #pragma unroll
            for (int r = 0; r < 4; r++) acc[i][j][r] = 0.f;

    int nchunk = K >> 6;

    auto load_chunk = [&](int c, int s) {
        int k0 = c << 6;
        uint32_t stg = sb + s * STAGE_B;
        #pragma unroll
        for (int i = 0; i < 4; i++) {
            int linear = tid + i * 256;          // 1024 x 16B chunks per tile
            int row = linear >> 3;
            int kc  = (linear & 7) << 3;
            uint32_t doff = (uint32_t)(row * RS + kc) * 2;
            size_t ga = (size_t)(m0 + row) * K + k0 + kc;
            cpa16(stg + doff,              Agh + ga);
            cpa16(stg + TILE_B + doff,     Agl + ga);
            size_t gb = (size_t)(n0 + row) * K + k0 + kc;
            cpa16(stg + 2 * TILE_B + doff, Bgh + gb);
            cpa16(stg + 3 * TILE_B + doff, Bgl + gb);
        }
    };

    load_chunk(0, 0); cpa_commit();
    load_chunk(1, 1); cpa_commit();

    uint32_t aH[2][4][4], aL[2][4][4], bH[2][4][2], bL[2][4][2];

    auto ldfr = [&](uint32_t base, int ks, int pb) {
        #pragma unroll
        for (int i = 0; i < 4; i++) {
            ldm_x4(aH[pb][i], base + lane_a + (uint32_t)(i * 16 * RS + ks * 16) * 2);
            ldm_x4(aL[pb][i], base + TILE_B + lane_a + (uint32_t)(i * 16 * RS + ks * 16) * 2);
        }
        #pragma unroll
        for (int jj = 0; jj < 2; jj++) {
            uint32_t t[4];
            ldm_x4(t, base + 2 * TILE_B + lane_b + (uint32_t)(jj * 16 * RS + ks * 16) * 2);
            bH[pb][2 * jj][0] = t[0]; bH[pb][2 * jj][1] = t[1];
            bH[pb][2 * jj + 1][0] = t[2]; bH[pb][2 * jj + 1][1] = t[3];
            ldm_x4(t, base + 3 * TILE_B + lane_b + (uint32_t)(jj * 16 * RS + ks * 16) * 2);
            bL[pb][2 * jj][0] = t[0]; bL[pb][2 * jj][1] = t[1];
            bL[pb][2 * jj + 1][0] = t[2]; bL[pb][2 * jj + 1][1] = t[3];
        }
    };

    for (int c = 0; c < nchunk; c++) {
        if (c + 1 < nchunk) cpa_wait1(); else cpa_wait0();
        __syncthreads();
        uint32_t base = sb + (c % 3) * STAGE_B;

        ldfr(base, 0, 0);
        #pragma unroll
        for (int ks = 0; ks < 4; ks++) {
            int cur = ks & 1;
            if (ks < 3) ldfr(base, ks + 1, cur ^ 1);
            #pragma unroll
            for (int i = 0; i < 4; i++)
                #pragma unroll
                for (int j = 0; j < 4; j++) {
                    mma_bf16(acc[i][j], aH[cur][i], bH[cur][j]);
                    mma_bf16(acc[i][j], aH[cur][i], bL[cur][j]);
                    mma_bf16(acc[i][j], aL[cur][i], bH[cur][j]);
                }
        }
        if (c + 2 < nchunk) load_chunk(c + 2, (c + 2) % 3);
        cpa_commit();
    }

    #pragma unroll
    for (int i = 0; i < 4; i++) {
        int row = m0 + wm * 64 + i * 16 + gid;
        #pragma unroll
        for (int j = 0; j < 4; j++) {
            int col = n0 + wn * 32 + j * 8 + tig * 2;
            float b0 = bias[col], b1 = bias[col + 1];
            float v0 = acc[i][j][0] + b0;
            float v1 = acc[i][j][1] + b1;
            float v2 = acc[i][j][2] + b0;
            float v3 = acc[i][j][3] + b1;
            if (col < qs_cols) { v0 *= 0.125f; v1 *= 0.125f; v2 *= 0.125f; v3 *= 0.125f; }
            if (act) {
                v0 = 0.5f * v0 * (1.0f + erff(v0 * 0.70710678118654752f));
                v1 = 0.5f * v1 * (1.0f + erff(v1 * 0.70710678118654752f));
                v2 = 0.5f * v2 * (1.0f + erff(v2 * 0.70710678118654752f));
                v3 = 0.5f * v3 * (1.0f + erff(v3 * 0.70710678118654752f));
            }
            if (Cf) {
                *(float2*)(Cf + (size_t)row * Nd + col)       = make_float2(v0, v1);
                *(float2*)(Cf + (size_t)(row + 8) * Nd + col) = make_float2(v2, v3);
            } else {
                __nv_bfloat162 h01 = __floats2bfloat162_rn(v0, v1);
                __nv_bfloat162 h23 = __floats2bfloat162_rn(v2, v3);
                __nv_bfloat162 l01 = __floats2bfloat162_rn(v0 - __bfloat162float(h01.x),
                                                           v1 - __bfloat162float(h01.y));
                __nv_bfloat162 l23 = __floats2bfloat162_rn(v2 - __bfloat162float(h23.x),
                                                           v3 - __bfloat162float(h23.y));
                *(uint32_t*)(Ch + (size_t)row * Nd + col)       = *(uint32_t*)&h01;
                *(uint32_t*)(Cl + (size_t)row * Nd + col)       = *(uint32_t*)&l01;
                *(uint32_t*)(Ch + (size_t)(row + 8) * Nd + col) = *(uint32_t*)&h23;
                *(uint32_t*)(Cl + (size_t)(row + 8) * Nd + col) = *(uint32_t*)&l23;
            }
        }
    }
}

// ---------------- key-block list ----------------
__global__ void build_klist(const int* __restrict__ rand_attn,
                            int* __restrict__ klist,
                            int* __restrict__ kcount) {
    int idx = blockIdx.x * blockDim.x + threadIdx.x;
    if (idx >= HH * MM) return;
    int h  = idx / MM;
    int qb = idx % MM;
    int* lst = klist + idx * 64;
    int c = 0;
    if (qb == 0 || qb == MM - 1) {
        for (int j = 0; j < MM; j++) lst[c++] = j;
    } else if (qb == 1) {
        lst[c++] = 0; lst[c++] = 1; lst[c++] = 2; lst[c++] = MM - 1;
        const int* rr = rand_attn + ((size_t)h * (MM - 2) + 0) * RR;
        for (int r = 0; r < RR; r++) lst[c++] = rr[r] | 256;
    } else if (qb == MM - 2) {
        lst[c++] = 0; lst[c++] = MM - 3; lst[c++] = MM - 2; lst[c++] = MM - 1;
        const int* rr = rand_attn + ((size_t)h * (MM - 2) + (MM - 3)) * RR;
        for (int r = 0; r < RR; r++) lst[c++] = rr[r] | 256;
    } else {
        lst[c++] = 0;
        lst[c++] = (qb - 1) | 256;
        lst[c++] = qb | 256;
        lst[c++] = (qb + 1) | 256;
        const int* rr = rand_attn + ((size_t)h * (MM - 2) + (qb - 1)) * RR;
        for (int r = 0; r < RR; r++) lst[c++] = rr[r] | 256;
        lst[c++] = MM - 1;
    }
    kcount[idx] = c;
}

// ---------------- HMMA flash attention (P aliases Q smem; 2 CTAs/SM) ---------
#define ARS  72
#define AQH  0            // Q hi (reused by P hi after Q frags hoisted)
#define AQL  9216         // Q lo (reused by P lo)
#define AK0  18432        // K, 2 stages x 18432
#define AV0  55296        // V, 2 stages x 18432
#define ASS  92160        // fp32 64x68 scores
#define AMQ  109568
#define AMK  109824
#define ARSC 110080
#define ARL  110336
#define AENT 110592
#define ATTN_SMEM_B 110848

__global__ __launch_bounds__(256, 2)
void attn_mma(const __nv_bfloat16* __restrict__ qkvh, const __nv_bfloat16* __restrict__ qkvl,
              const float* __restrict__ mask,
              const int* __restrict__ klist, const int* __restrict__ kcount,
              __nv_bfloat16* __restrict__ oh, __nv_bfloat16* __restrict__ ol) {
    extern __shared__ char sm[];
    uint32_t sb = smem_u32(sm);
    float* Ss  = (float*)(sm + ASS);
    float* mq  = (float*)(sm + AMQ);
    float* mk  = (float*)(sm + AMK);
    float* rsc = (float*)(sm + ARSC);
    float* rl  = (float*)(sm + ARL);
    int*   ents= (int*)(sm + AENT);
    __nv_bfloat16* Ph = (__nv_bfloat16*)(sm + AQH);   // aliases Q hi
    __nv_bfloat16* Pl = (__nv_bfloat16*)(sm + AQL);   // aliases Q lo

    const __nv_bfloat16* qh = qkvh;
    const __nv_bfloat16* ql = qkvl;
    const __nv_bfloat16* kh = qkvh + 768;
    const __nv_bfloat16* kl = qkvl + 768;
    const __nv_bfloat16* vh = qkvh + 1536;
    const __nv_bfloat16* vl = qkvl + 1536;

    int qb = blockIdx.x, h = blockIdx.y;
    int tid = threadIdx.x;
    int w = tid >> 5, l = tid & 31;
    int wm = w & 1, wn = w >> 1;
    int gid = l >> 2, tig = l & 3;
    int srow = tid >> 2, sseg = (tid & 3) << 4;
    int lid = h * MM + qb;
    int cnt = kcount[lid];

    uint32_t lane_qa = (uint32_t)((wm * 32 + ((l >> 3) & 1) * 8 + (l & 7)) * ARS + (l >> 4) * 8) * 2;
    uint32_t lane_kb = (uint32_t)((wn * 16 + (l >> 4) * 8 + (l & 7)) * ARS + ((l >> 3) & 1) * 8) * 2;
    uint32_t lane_vt = (uint32_t)((((l >> 3) & 1) * 8 + (l & 7)) * ARS + wn * 16 + (l >> 4) * 8) * 2;

    if (tid < 64) {
        ents[tid] = klist[lid * 64 + tid];
        mq[tid]   = mask[qb * 64 + tid];
    }

    auto load_kv = [&](int kb, int s) {
        uint32_t bk_ = sb + AK0 + s * 18432;
        uint32_t bv_ = sb + AV0 + s * 18432;
        #pragma unroll
        for (int i = 0; i < 2; i++) {
            int linear = tid + i * 256;
            int r = linear >> 3, c8 = (linear & 7) << 3;
            uint32_t doff = (uint32_t)(r * ARS + c8) * 2;
            size_t g = (size_t)(kb * 64 + r) * QKVS + h * DHH + c8;
            cpa16(bk_ + doff,        kh + g);
            cpa16(bk_ + 9216 + doff, kl + g);
            cpa16(bv_ + doff,        vh + g);
            cpa16(bv_ + 9216 + doff, vl + g);
        }
    };

    #pragma unroll
    for (int i = 0; i < 2; i++) {
        int linear = tid + i * 256;
        int r = linear >> 3, c8 = (linear & 7) << 3;
        uint32_t doff = (uint32_t)(r * ARS + c8) * 2;
        size_t g = (size_t)(qb * 64 + r) * QKVS + h * DHH + c8;
        cpa16(sb + AQH + doff, qh + g);
        cpa16(sb + AQL + doff, ql + g);
    }
    __syncthreads();
    load_kv(ents[0] & 0xff, 0);
    cpa_commit();
    cpa_wait0();
    __syncthreads();

    // hoist Q fragments; Q smem region is then free for P
    uint32_t qfh[2][4][4], qfl[2][4][4];
    #pragma unroll
    for (int i = 0; i < 2; i++)
        #pragma unroll
        for (int ksi = 0; ksi < 4; ksi++) {
            ldm_x4(qfh[i][ksi], sb + AQH + lane_qa + (uint32_t)(i * 16 * ARS + ksi * 16) * 2);
            ldm_x4(qfl[i][ksi], sb + AQL + lane_qa + (uint32_t)(i * 16 * ARS + ksi * 16) * 2);
        }

    float m_run = -1e30f, l_run = 0.f;
    float o[2][2][4];
    #pragma unroll
    for (int i = 0; i < 2; i++)
        #pragma unroll
        for (int j = 0; j < 2; j++)
            #pragma unroll
            for (int r = 0; r < 4; r++) o[i][j][r] = 0.f;

    for (int b = 0; b < cnt; b++) {
        int e = ents[b], kb = e & 0xff, fl = e >> 8;
        if (b > 0) { cpa_wait0(); __syncthreads(); }
        if (b + 1 < cnt) { load_kv(ents[b + 1] & 0xff, (b + 1) & 1); cpa_commit(); }
        if (tid < 64) mk[tid] = mask[kb * 64 + tid];

        uint32_t baseKh = sb + AK0 + (b & 1) * 18432;
        uint32_t baseKl = baseKh + 9216;
        uint32_t baseVh = sb + AV0 + (b & 1) * 18432;
        uint32_t baseVl = baseVh + 9216;

        float sa[2][2][4];
        #pragma unroll
        for (int i = 0; i < 2; i++)
            #pragma unroll
            for (int j = 0; j < 2; j++)
                #pragma unroll
                for (int r = 0; r < 4; r++) sa[i][j][r] = 0.f;
        #pragma unroll
        for (int ksi = 0; ksi < 4; ksi++) {
            uint32_t bH[2][2], bL[2][2], t[4];
            ldm_x4(t, baseKh + lane_kb + (uint32_t)(ksi * 16) * 2);
            bH[0][0] = t[0]; bH[0][1] = t[1]; bH[1][0] = t[2]; bH[1][1] = t[3];
            ldm_x4(t, baseKl + lane_kb + (uint32_t)(ksi * 16) * 2);
            bL[0][0] = t[0]; bL[0][1] = t[1]; bL[1][0] = t[2]; bL[1][1] = t[3];
            #pragma unroll
            for (int i = 0; i < 2; i++)
                #pragma unroll
                for (int j = 0; j < 2; j++) {
                    mma_bf16(sa[i][j], qfh[i][ksi], bH[j]);
                    mma_bf16(sa[i][j], qfh[i][ksi], bL[j]);
                    mma_bf16(sa[i][j], qfl[i][ksi], bH[j]);
                }
        }
        #pragma unroll
        for (int i = 0; i < 2; i++) {
            int r = wm * 32 + i * 16 + gid;
            #pragma unroll
            for (int j = 0; j < 2; j++) {
                int c = wn * 16 + j * 8 + tig * 2;
                Ss[r * 68 + c]           = sa[i][j][0];
                Ss[r * 68 + c + 1]       = sa[i][j][1];
                Ss[(r + 8) * 68 + c]     = sa[i][j][2];
                Ss[(r + 8) * 68 + c + 1] = sa[i][j][3];
            }
        }
        __syncthreads();

        float mqv = mq[srow];
        float sv[16];
        #pragma unroll
        for (int j = 0; j < 16; j += 4) {
            float4 f = *(float4*)(Ss + srow * 68 + sseg + j);
            sv[j] = f.x; sv[j+1] = f.y; sv[j+2] = f.z; sv[j+3] = f.w;
        }
        #pragma unroll
        for (int j = 0; j < 16; j++) {
            float mkv = mk[sseg + j];
            float eff = fl ? (mqv * mkv) : mkv;
            sv[j] += (1.0f - eff) * NEGV;
        }
        float lm = sv[0];
        #pragma unroll
        for (int j = 1; j < 16; j++) lm = fmaxf(lm, sv[j]);
        lm = fmaxf(lm, __shfl_xor_sync(0xffffffffu, lm, 1));
        lm = fmaxf(lm, __shfl_xor_sync(0xffffffffu, lm, 2));
        float m_new = fmaxf(m_run, lm);
        float sc = expf(m_run - m_new);
        float ls = 0.f;
        #pragma unroll
        for (int j = 0; j < 16; j += 2) {
            float p0 = expf(sv[j]     - m_new);
            float p1 = expf(sv[j + 1] - m_new);
            ls += p0 + p1;
            __nv_bfloat162 hh = __floats2bfloat162_rn(p0, p1);
            __nv_bfloat162 lv = __floats2bfloat162_rn(p0 - __bfloat162float(hh.x),
                                                      p1 - __bfloat162float(hh.y));
            *(uint32_t*)(Ph + srow * ARS + sseg + j) = *(uint32_t*)&hh;
            *(uint32_t*)(Pl + srow * ARS + sseg + j) = *(uint32_t*)&lv;
        }
        ls += __shfl_xor_sync(0xffffffffu, ls, 1);
        ls += __shfl_xor_sync(0xffffffffu, ls, 2);
        l_run = l_run * sc + ls;
        m_run = m_new;
        if ((tid & 3) == 0) rsc[srow] = sc;
        __syncthreads();

        #pragma unroll
        for (int i = 0; i < 2; i++) {
            float s0 = rsc[wm * 32 + i * 16 + gid];
            float s1 = rsc[wm * 32 + i * 16 + gid + 8];
            #pragma unroll
            for (int j = 0; j < 2; j++) {
                o[i][j][0] *= s0; o[i][j][1] *= s0;
                o[i][j][2] *= s1; o[i][j][3] *= s1;
            }
        }
        #pragma unroll
        for (int ksi = 0; ksi < 4; ksi++) {
            uint32_t aH[2][4], aL[2][4], bH[2][2], bL[2][2], t[4];
            #pragma unroll
            for (int i = 0; i < 2; i++) {
                ldm_x4(aH[i], sb + AQH + lane_qa + (uint32_t)(i * 16 * ARS + ksi * 16) * 2);
                ldm_x4(aL[i], sb + AQL + lane_qa + (uint32_t)(i * 16 * ARS + ksi * 16) * 2);
            }
            ldm_x4_t(t, baseVh + lane_vt + (uint32_t)(ksi * 16 * ARS) * 2);
            bH[0][0] = t[0]; bH[0][1] = t[1]; bH[1][0] = t[2]; bH[1][1] = t[3];
            ldm_x4_t(t, baseVl + lane_vt + (uint32_t)(ksi * 16 * ARS) * 2);
            bL[0][0] = t[0]; bL[0][1] = t[1]; bL[1][0] = t[2]; bL[1][1] = t[3];
            #pragma unroll
            for (int i = 0; i < 2; i++)
                #pragma unroll
                for (int j = 0; j < 2; j++) {
                    mma_bf16(o[i][j], aH[i], bH[j]);
                    mma_bf16(o[i][j], aH[i], bL[j]);
                    mma_bf16(o[i][j], aL[i], bH[j]);
                }
        }
        __syncthreads();   // P buffer reused next iter; all readers done
    }

    if ((tid & 3) == 0) rl[srow] = l_run;
    __syncthreads();

    #pragma unroll
    for (int i = 0; i < 2; i++) {
        int r0 = wm * 32 + i * 16 + gid;
        int r1 = r0 + 8;
        float iv0 = mq[r0] / rl[r0];
        float iv1 = mq[r1] / rl[r1];
        #pragma unroll
        for (int j = 0; j < 2; j++) {
            int c = wn * 16 + j * 8 + tig * 2;
            float v0 = o[i][j][0] * iv0, v1 = o[i][j][1] * iv0;
            float v2 = o[i][j][2] * iv1, v3 = o[i][j][3] * iv1;
            __nv_bfloat162 h01 = __floats2bfloat162_rn(v0, v1);
            __nv_bfloat162 h23 = __floats2bfloat162_rn(v2, v3);
            __nv_bfloat162 l01 = __floats2bfloat162_rn(v0 - __bfloat162float(h01.x),
                                                       v1 - __bfloat162float(h01.y));
            __nv_bfloat162 l23 = __floats2bfloat162_rn(v2 - __bfloat162float(h23.x),
                                                       v3 - __bfloat162float(h23.y));
            size_t g0 = (size_t)(qb * 64 + r0) * DD + h * DHH + c;
            size_t g1 = (size_t)(qb * 64 + r1) * DD + h * DHH + c;
            *(uint32_t*)(oh + g0) = *(uint32_t*)&h01;
            *(uint32_t*)(ol + g0) = *(uint32_t*)&l01;
            *(uint32_t*)(oh + g1) = *(uint32_t*)&h23;
            *(uint32_t*)(ol + g1) = *(uint32_t*)&l23;
        }
    }
}

// ---------------- host orchestration ----------------
extern "C" void kernel_launch(void* const* d_in, const int* in_sizes, int n_in,
                              void* d_out, int out_size) {
    (void)in_sizes; (void)n_in; (void)out_size;
    const int*   ids      = (const int*)  d_in[0];
    const float* mask     = (const float*)d_in[1];
    const int*   rand_attn= (const int*)  d_in[2];
    const float* emb_word = (const float*)d_in[3];
    const float* emb_pos  = (const float*)d_in[4];
    const float* eln_g    = (const float*)d_in[5];
    const float* eln_b    = (const float*)d_in[6];
    const float* Wq = (const float*)d_in[7];  const float* bq = (const float*)d_in[8];
    const float* Wk = (const float*)d_in[9];  const float* bk = (const float*)d_in[10];
    const float* Wv = (const float*)d_in[11]; const float* bv = (const float*)d_in[12];
    const float* Wo = (const float*)d_in[13]; const float* bo = (const float*)d_in[14];
    const float* ln1g = (const float*)d_in[15]; const float* ln1b = (const float*)d_in[16];
    const float* W1 = (const float*)d_in[17]; const float* b1 = (const float*)d_in[18];
    const float* W2 = (const float*)d_in[19]; const float* b2 = (const float*)d_in[20];
    const float* ln2g = (const float*)d_in[21]; const float* ln2b = (const float*)d_in[22];
    float* outp = (float*)d_out;

    float *px, *pt, *pbqkv;
    __nv_bfloat16 *xh, *xl, *pqkvh, *pqkvl, *pah, *pal, *pfh, *pfl, *pwh, *pwl;
    int *pklist, *pkc;
    cudaGetSymbolAddress((void**)&px,  g_x);
    cudaGetSymbolAddress((void**)&pt,  g_t);
    cudaGetSymbolAddress((void**)&xh,  g_xh);   cudaGetSymbolAddress((void**)&xl,  g_xl);
    cudaGetSymbolAddress((void**)&pqkvh, g_qkvh); cudaGetSymbolAddress((void**)&pqkvl, g_qkvl);
    cudaGetSymbolAddress((void**)&pah, g_ah);   cudaGetSymbolAddress((void**)&pal, g_al);
    cudaGetSymbolAddress((void**)&pfh, g_fh);   cudaGetSymbolAddress((void**)&pfl, g_fl);
    cudaGetSymbolAddress((void**)&pwh, g_wTh);  cudaGetSymbolAddress((void**)&pwl, g_wTl);
    cudaGetSymbolAddress((void**)&pbqkv, g_bqkv);
    cudaGetSymbolAddress((void**)&pklist, g_klist);
    cudaGetSymbolAddress((void**)&pkc,    g_kcount);

    cudaFuncSetAttribute(gemm_mma, cudaFuncAttributeMaxDynamicSharedMemorySize, GEMM_SMEM);
    cudaFuncSetAttribute(attn_mma, cudaFuncAttributeMaxDynamicSharedMemorySize, ATTN_SMEM_B);

    const size_t OQ = 0, OO = 1769472, O1 = 2359296, O2 = 4718592;

    dim3 gQKV(QKVS / 128, NN / 128);  // 18 x 32
    dim3 gProj(DD / 128, NN / 128);   // 6 x 32
    dim3 gF1(FFD / 128, NN / 128);    // 24 x 32
    dim3 gAttn(MM, HH);
    dim3 gT768(DD / 32, DD / 32);
    dim3 gTQKV(QKVS / 32, DD / 32);

    // launch order: #4 (ncu capture position) = layer-0 QKV gemm_mma
    embed_ln<<<NN, 256>>>(ids, emb_word, emb_pos, eln_g, eln_b, px, xh, xl);          // 1
    bias_cat<<<(LL * QKVS + 255) / 256, 256>>>(bq, bk, bv, pbqkv);                    // 2
    wtrans_qkv<<<gTQKV, 256>>>(Wq, Wk, Wv, pwh + OQ, pwl + OQ);                       // 3
    gemm_mma<<<gQKV, 256, GEMM_SMEM>>>(xh, xl, pwh + OQ, pwl + OQ,
                                       pbqkv, nullptr, pqkvh, pqkvl, QKVS, DD, 0, 768); // 4 <- profiled
    build_klist<<<(HH * MM + 127) / 128, 128>>>(rand_attn, pklist, pkc);

    wtrans<<<gT768, 256>>>(Wo, pwh + OO, pwl + OO, DD, DD);
    wtrans<<<dim3(FFD/32, DD/32), 256>>>(W1, pwh + O1, pwl + O1, DD, FFD);
    wtrans<<<dim3(DD/32, FFD/32), 256>>>(W2, pwh + O2, pwl + O2, FFD, DD);
    for (int i = 1; i < LL; i++) {
        size_t lo = (size_t)i * WPL;
        wtrans_qkv<<<gTQKV, 256>>>(Wq + (size_t)i*DD*DD, Wk + (size_t)i*DD*DD, Wv + (size_t)i*DD*DD,
                                   pwh + lo + OQ, pwl + lo + OQ);
        wtrans<<<gT768, 256>>>(Wo + (size_t)i*DD*DD, pwh + lo + OO, pwl + lo + OO, DD, DD);
        wtrans<<<dim3(FFD/32, DD/32), 256>>>(W1 + (size_t)i*DD*FFD, pwh + lo + O1, pwl + lo + O1, DD, FFD);
        wtrans<<<dim3(DD/32, FFD/32), 256>>>(W2 + (size_t)i*FFD*DD, pwh + lo + O2, pwl + lo + O2, FFD, DD);
    }

    for (int i = 0; i < LL; i++) {
        size_t lo = (size_t)i * WPL;
        if (i > 0)
            gemm_mma<<<gQKV, 256, GEMM_SMEM>>>(xh, xl, pwh + lo + OQ, pwl + lo + OQ,
                                               pbqkv + (size_t)i * QKVS, nullptr, pqkvh, pqkvl, QKVS, DD, 0, 768);
        attn_mma<<<gAttn, 256, ATTN_SMEM_B>>>(pqkvh, pqkvl, mask, pklist, pkc, pah, pal);
        gemm_mma<<<gProj, 256, GEMM_SMEM>>>(pah, pal, pwh + lo + OO, pwl + lo + OO,
                                            bo + (size_t)i*DD, pt, nullptr, nullptr, DD, DD, 0, 0);
        ln_kernel<<<NN, 256>>>(px, pt, ln1g + (size_t)i*DD, ln1b + (size_t)i*DD, px, xh, xl);
        gemm_mma<<<gF1, 256, GEMM_SMEM>>>(xh, xl, pwh + lo + O1, pwl + lo + O1,
                                          b1 + (size_t)i*FFD, nullptr, pfh, pfl, FFD, DD, 1, 0);
        gemm_mma<<<gProj, 256, GEMM_SMEM>>>(pfh, pfl, pwh + lo + O2, pwl + lo + O2,
                                            b2 + (size_t)i*DD, pt, nullptr, nullptr, DD, FFD, 0, 0);
        if (i == LL - 1)
            ln_kernel<<<NN, 256>>>(px, pt, ln2g + (size_t)i*DD, ln2b + (size_t)i*DD, outp, nullptr, nullptr);
        else
            ln_kernel<<<NN, 256>>>(px, pt, ln2g + (size_t)i*DD, ln2b + (size_t)i*DD, px, xh, xl);
    }
}

// round 9
// speedup vs baseline: 11.9699x; 1.0548x over previous
#include <cuda_runtime.h>
#include <cuda_bf16.h>
#include <math.h>
#include <stdint.h>

// ---------------- problem constants ----------------
#define NN   4096
#define HH   12
#define DHH  64
#define DD   768
#define LL   4
#define FFD  3072
#define MM   64
#define RR   3
#define NEGV (-10000.0f)
#define QKVS 2304

// ---------------- device scratch ----------------
__device__ float g_x [NN * DD];
__device__ float g_t [NN * DD];
__device__ __nv_bfloat16 g_xh[NN * DD],  g_xl[NN * DD];
__device__ __nv_bfloat16 g_qkvh[NN * QKVS], g_qkvl[NN * QKVS];
__device__ __nv_bfloat16 g_ah[NN * DD],  g_al[NN * DD];
__device__ __nv_bfloat16 g_fh[NN * FFD], g_fl[NN * FFD];
__device__ float g_bqkv[LL * QKVS];
__device__ int   g_klist [HH * MM * 64];
__device__ int   g_kcount[HH * MM];
#define WPL 7077888ULL
__device__ __nv_bfloat16 g_wTh[LL * WPL];
__device__ __nv_bfloat16 g_wTl[LL * WPL];

// ---------------- asm helpers ----------------
__device__ __forceinline__ uint32_t smem_u32(const void* p) {
    uint32_t a;
    asm("{ .reg .u64 t; cvta.to.shared.u64 t, %1; cvt.u32.u64 %0, t; }" : "=r"(a) : "l"(p));
    return a;
}
__device__ __forceinline__ void cpa16(uint32_t dst, const void* src) {
    asm volatile("cp.async.cg.shared.global [%0], [%1], 16;" :: "r"(dst), "l"(src));
}
__device__ __forceinline__ void cpa_commit() { asm volatile("cp.async.commit_group;" ::: "memory"); }
__device__ __forceinline__ void cpa_wait0()  { asm volatile("cp.async.wait_group 0;" ::: "memory"); }
__device__ __forceinline__ void cpa_wait1()  { asm volatile("cp.async.wait_group 1;" ::: "memory"); }

__device__ __forceinline__ void mma_bf16(float* c, const uint32_t* a, const uint32_t* b) {
    asm volatile(
        "mma.sync.aligned.m16n8k16.row.col.f32.bf16.bf16.f32 "
        "{%0,%1,%2,%3}, {%4,%5,%6,%7}, {%8,%9}, {%0,%1,%2,%3};"
        : "+f"(c[0]), "+f"(c[1]), "+f"(c[2]), "+f"(c[3])
        : "r"(a[0]), "r"(a[1]), "r"(a[2]), "r"(a[3]), "r"(b[0]), "r"(b[1]));
}
__device__ __forceinline__ void ldm_x4(uint32_t* r, uint32_t addr) {
    asm volatile("ldmatrix.sync.aligned.m8n8.x4.shared.b16 {%0,%1,%2,%3}, [%4];"
        : "=r"(r[0]), "=r"(r[1]), "=r"(r[2]), "=r"(r[3]) : "r"(addr));
}
__device__ __forceinline__ void ldm_x4_t(uint32_t* r, uint32_t addr) {
    asm volatile("ldmatrix.sync.aligned.m8n8.x4.trans.shared.b16 {%0,%1,%2,%3}, [%4];"
        : "=r"(r[0]), "=r"(r[1]), "=r"(r[2]), "=r"(r[3]) : "r"(addr));
}

// ---------------- misc kernels ----------------
__device__ __forceinline__ float block_reduce(float val, bool is_max, float* rbuf) {
    int lane = threadIdx.x & 31;
    int w    = threadIdx.x >> 5;
    #pragma unroll
    for (int o = 16; o; o >>= 1) {
        float other = __shfl_xor_sync(0xffffffffu, val, o);
        val = is_max ? fmaxf(val, other) : (val + other);
    }
    if (lane == 0) rbuf[w] = val;
    __syncthreads();
    if (threadIdx.x == 0) {
        int nw = (blockDim.x + 31) >> 5;
        float r = rbuf[0];
        for (int i = 1; i < nw; i++) r = is_max ? fmaxf(r, rbuf[i]) : (r + rbuf[i]);
        rbuf[0] = r;
    }
    __syncthreads();
    float res = rbuf[0];
    __syncthreads();
    return res;
}

__global__ void embed_ln(const int* __restrict__ ids,
                         const float* __restrict__ ew,
                         const float* __restrict__ ep,
                         const float* __restrict__ g,
                         const float* __restrict__ b,
                         float* __restrict__ outf,
                         __nv_bfloat16* __restrict__ outh,
                         __nv_bfloat16* __restrict__ outl) {
    __shared__ float s[DD];
    __shared__ float rbuf[8];
    int t = blockIdx.x;
    int tid = threadIdx.x;
    int id = ids[t];
    const float* wr = ew + (size_t)id * DD;
    const float* pr = ep + (size_t)t * DD;
    float lsum = 0.f;
    for (int d = tid; d < DD; d += blockDim.x) {
        float v = wr[d] + pr[d];
        s[d] = v;
        lsum += v;
    }
    float mu = block_reduce(lsum, false, rbuf) * (1.0f / DD);
    float lvar = 0.f;
    for (int d = tid; d < DD; d += blockDim.x) {
        float dv = s[d] - mu;
        lvar += dv * dv;
    }
    float var = block_reduce(lvar, false, rbuf) * (1.0f / DD);
    float inv = rsqrtf(var + 1e-5f);
    for (int d = tid; d < DD; d += blockDim.x) {
        float val = (s[d] - mu) * inv * g[d] + b[d];
        outf[(size_t)t * DD + d] = val;
        __nv_bfloat16 h = __float2bfloat16(val);
        outh[(size_t)t * DD + d] = h;
        outl[(size_t)t * DD + d] = __float2bfloat16(val - __bfloat162float(h));
    }
}

__global__ void ln_kernel(const float* __restrict__ A,
                          const float* __restrict__ Bres,
                          const float* __restrict__ g,
                          const float* __restrict__ b,
                          float* __restrict__ outf,
                          __nv_bfloat16* __restrict__ outh,
                          __nv_bfloat16* __restrict__ outl) {
    __shared__ float s[DD];
    __shared__ float rbuf[8];
    int t = blockIdx.x;
    int tid = threadIdx.x;
    const float* ar = A + (size_t)t * DD;
    const float* br = Bres ? (Bres + (size_t)t * DD) : nullptr;
    float lsum = 0.f;
    for (int d = tid; d < DD; d += blockDim.x) {
        float v = ar[d];
        if (br) v += br[d];
        s[d] = v;
        lsum += v;
    }
    float mu = block_reduce(lsum, false, rbuf) * (1.0f / DD);
    float lvar = 0.f;
    for (int d = tid; d < DD; d += blockDim.x) {
        float dv = s[d] - mu;
        lvar += dv * dv;
    }
    float var = block_reduce(lvar, false, rbuf) * (1.0f / DD);
    float inv = rsqrtf(var + 1e-5f);
    for (int d = tid; d < DD; d += blockDim.x) {
        float val = (s[d] - mu) * inv * g[d] + b[d];
        if (outf) outf[(size_t)t * DD + d] = val;
        if (outh) {
            __nv_bfloat16 h = __float2bfloat16(val);
            outh[(size_t)t * DD + d] = h;
            outl[(size_t)t * DD + d] = __float2bfloat16(val - __bfloat162float(h));
        }
    }
}

__global__ void wtrans(const float* __restrict__ W,
                       __nv_bfloat16* __restrict__ oh,
                       __nv_bfloat16* __restrict__ ol,
                       int K, int N) {
    __shared__ float sm[32][33];
    int n0 = blockIdx.x * 32, k0 = blockIdx.y * 32;
    int tx = threadIdx.x & 31, ty = threadIdx.x >> 5;
    #pragma unroll
    for (int j = 0; j < 4; j++) {
        int kk = ty + j * 8;
        sm[kk][tx] = W[(size_t)(k0 + kk) * N + n0 + tx];
    }
    __syncthreads();
    #pragma unroll
    for (int j = 0; j < 4; j++) {
        int nn = ty + j * 8;
        float v = sm[tx][nn];
        __nv_bfloat16 h = __float2bfloat16(v);
        float r = v - __bfloat162float(h);
        size_t o = (size_t)(n0 + nn) * K + k0 + tx;
        oh[o] = h;
        ol[o] = __float2bfloat16(r);
    }
}

__global__ void wtrans_qkv(const float* __restrict__ Wq, const float* __restrict__ Wk,
                           const float* __restrict__ Wv,
                           __nv_bfloat16* __restrict__ oh, __nv_bfloat16* __restrict__ ol) {
    __shared__ float sm[32][33];
    int n0 = blockIdx.x * 32, k0 = blockIdx.y * 32;
    const float* W = (n0 < 768) ? Wq : (n0 < 1536) ? Wk : Wv;
    int nl0 = n0 % 768;
    int tx = threadIdx.x & 31, ty = threadIdx.x >> 5;
    #pragma unroll
    for (int j = 0; j < 4; j++) {
        int kk = ty + j * 8;
        sm[kk][tx] = W[(size_t)(k0 + kk) * 768 + nl0 + tx];
    }
    __syncthreads();
    #pragma unroll
    for (int j = 0; j < 4; j++) {
        int nn = ty + j * 8;
        float v = sm[tx][nn];
        __nv_bfloat16 h = __float2bfloat16(v);
        float r = v - __bfloat162float(h);
        size_t o = (size_t)(n0 + nn) * DD + k0 + tx;
        oh[o] = h;
        ol[o] = __float2bfloat16(r);
    }
}

__global__ void bias_cat(const float* __restrict__ bq, const float* __restrict__ bk,
                         const float* __restrict__ bv, float* __restrict__ out) {
    int i = blockIdx.x * blockDim.x + threadIdx.x;
    if (i >= LL * QKVS) return;
    int l = i / QKVS, c = i % QKVS;
    float v;
    if (c < 768)       v = bq[l * 768 + c];
    else if (c < 1536) v = bk[l * 768 + c - 768];
    else               v = bv[l * 768 + c - 1536];
    out[i] = v;
}

// ---------------- HMMA GEMM: k-chunk 32, hi|lo packed tiles, 3 stages, 2 CTA/SM --
// Tile layout (per stage): A[128][72] bf16 (hi cols 0-31, lo cols 32-63, pad 64-71)
//                          B[128][72] same. Stage = 36864 B. 3 stages = 110592 B.
#define RS      72
#define TILE_B  (128 * RS * 2)      // 18432
#define STAGE_B (2 * TILE_B)        // 36864
#define GEMM_SMEM (3 * STAGE_B)     // 110592

__global__ __launch_bounds__(256, 2)
void gemm_mma(const __nv_bfloat16* __restrict__ Agh, const __nv_bfloat16* __restrict__ Agl,
              const __nv_bfloat16* __restrict__ Bgh, const __nv_bfloat16* __restrict__ Bgl,
              const float* __restrict__ bias,
              float* __restrict__ Cf,
              __nv_bfloat16* __restrict__ Ch, __nv_bfloat16* __restrict__ Cl,
              int Nd, int K, int act, int qs_cols) {
    extern __shared__ __nv_bfloat16 smem[];
    uint32_t sb = smem_u32(smem);
    int tid = threadIdx.x;
    int m0 = blockIdx.y * 128, n0 = blockIdx.x * 128;
    int w = tid >> 5, l = tid & 31;
    int wm = w & 1, wn = w >> 1;
    int gid = l >> 2, tig = l & 3;

    uint32_t lane_a = (uint32_t)((wm * 64 + ((l >> 3) & 1) * 8 + (l & 7)) * RS + (l >> 4) * 8) * 2;
    uint32_t lane_b = (uint32_t)((wn * 32 + (l >> 4) * 8 + (l & 7)) * RS + ((l >> 3) & 1) * 8) * 2;

    float acc[4][4][4];
    #pragma unroll
    for (int i = 0; i < 4; i++)
        #pragma unroll
        for (int j = 0; j < 4; j++)
            #pragma unroll
            for (int r = 0; r < 4; r++) acc[i][j][r] = 0.f;

    int nchunk = K >> 5;

    auto load_chunk = [&](int c, int s) {
        int k0 = c << 5;
        uint32_t stg = sb + s * STAGE_B;
        #pragma unroll
        for (int i = 0; i < 2; i++) {
            int linear = tid + i * 256;          // 512 x 16B per (tile,half)
            int row = linear >> 2;
            int kc  = (linear & 3) << 3;
            uint32_t dhi = (uint32_t)(row * RS + kc) * 2;
            uint32_t dlo = (uint32_t)(row * RS + 32 + kc) * 2;
            size_t ga = (size_t)(m0 + row) * K + k0 + kc;
            cpa16(stg + dhi,          Agh + ga);
            cpa16(stg + dlo,          Agl + ga);
            size_t gb = (size_t)(n0 + row) * K + k0 + kc;
            cpa16(stg + TILE_B + dhi, Bgh + gb);
            cpa16(stg + TILE_B + dlo, Bgl + gb);
        }
    };

    load_chunk(0, 0); cpa_commit();
    load_chunk(1, 1); cpa_commit();

    for (int c = 0; c < nchunk; c++) {
        if (c + 1 < nchunk) cpa_wait1(); else cpa_wait0();
        __syncthreads();
        uint32_t base = sb + (c % 3) * STAGE_B;

        #pragma unroll
        for (int ks = 0; ks < 2; ks++) {
            uint32_t khi = (uint32_t)(ks * 16) * 2;
            uint32_t klo = (uint32_t)(32 + ks * 16) * 2;

            uint32_t aH[4][4], bH[4][2];
            #pragma unroll
            for (int i = 0; i < 4; i++)
                ldm_x4(aH[i], base + lane_a + (uint32_t)(i * 16 * RS) * 2 + khi);
            #pragma unroll
            for (int jj = 0; jj < 2; jj++) {
                uint32_t t[4];
                ldm_x4(t, base + TILE_B + lane_b + (uint32_t)(jj * 16 * RS) * 2 + khi);
                bH[2 * jj][0] = t[0]; bH[2 * jj][1] = t[1];
                bH[2 * jj + 1][0] = t[2]; bH[2 * jj + 1][1] = t[3];
            }
            #pragma unroll
            for (int i = 0; i < 4; i++)
                #pragma unroll
                for (int j = 0; j < 4; j++)
                    mma_bf16(acc[i][j], aH[i], bH[j]);

            uint32_t bL[4][2];
            #pragma unroll
            for (int jj = 0; jj < 2; jj++) {
                uint32_t t[4];
                ldm_x4(t, base + TILE_B + lane_b + (uint32_t)(jj * 16 * RS) * 2 + klo);
                bL[2 * jj][0] = t[0]; bL[2 * jj][1] = t[1];
                bL[2 * jj + 1][0] = t[2]; bL[2 * jj + 1][1] = t[3];
            }
            #pragma unroll
            for (int i = 0; i < 4; i++)
                #pragma unroll
                for (int j = 0; j < 4; j++)
                    mma_bf16(acc[i][j], aH[i], bL[j]);

            uint32_t aL[4][4];
            #pragma unroll
            for (int i = 0; i < 4; i++)
                ldm_x4(aL[i], base + lane_a + (uint32_t)(i * 16 * RS) * 2 + klo);
            #pragma unroll
            for (int i = 0; i < 4; i++)
                #pragma unroll
                for (int j = 0; j < 4; j++)
                    mma_bf16(acc[i][j], aL[i], bH[j]);
        }
        if (c + 2 < nchunk) load_chunk(c + 2, (c + 2) % 3);
        cpa_commit();
    }

    #pragma unroll
    for (int i = 0; i < 4; i++) {
        int row = m0 + wm * 64 + i * 16 + gid;
        #pragma unroll
        for (int j = 0; j < 4; j++) {
            int col = n0 + wn * 32 + j * 8 + tig * 2;
            float b0 = bias[col], b1 = bias[col + 1];
            float v0 = acc[i][j][0] + b0;
            float v1 = acc[i][j][1] + b1;
            float v2 = acc[i][j][2] + b0;
            float v3 = acc[i][j][3] + b1;
            if (col < qs_cols) { v0 *= 0.125f; v1 *= 0.125f; v2 *= 0.125f; v3 *= 0.125f; }
            if (act) {
                v0 = 0.5f * v0 * (1.0f + erff(v0 * 0.70710678118654752f));
                v1 = 0.5f * v1 * (1.0f + erff(v1 * 0.70710678118654752f));
                v2 = 0.5f * v2 * (1.0f + erff(v2 * 0.70710678118654752f));
                v3 = 0.5f * v3 * (1.0f + erff(v3 * 0.70710678118654752f));
            }
            if (Cf) {
                *(float2*)(Cf + (size_t)row * Nd + col)       = make_float2(v0, v1);
                *(float2*)(Cf + (size_t)(row + 8) * Nd + col) = make_float2(v2, v3);
            } else {
                __nv_bfloat162 h01 = __floats2bfloat162_rn(v0, v1);
                __nv_bfloat162 h23 = __floats2bfloat162_rn(v2, v3);
                __nv_bfloat162 l01 = __floats2bfloat162_rn(v0 - __bfloat162float(h01.x),
                                                           v1 - __bfloat162float(h01.y));
                __nv_bfloat162 l23 = __floats2bfloat162_rn(v2 - __bfloat162float(h23.x),
                                                           v3 - __bfloat162float(h23.y));
                *(uint32_t*)(Ch + (size_t)row * Nd + col)       = *(uint32_t*)&h01;
                *(uint32_t*)(Cl + (size_t)row * Nd + col)       = *(uint32_t*)&l01;
                *(uint32_t*)(Ch + (size_t)(row + 8) * Nd + col) = *(uint32_t*)&h23;
                *(uint32_t*)(Cl + (size_t)(row + 8) * Nd + col) = *(uint32_t*)&l23;
            }
        }
    }
}

// ---------------- key-block list ----------------
__global__ void build_klist(const int* __restrict__ rand_attn,
                            int* __restrict__ klist,
                            int* __restrict__ kcount) {
    int idx = blockIdx.x * blockDim.x + threadIdx.x;
    if (idx >= HH * MM) return;
    int h  = idx / MM;
    int qb = idx % MM;
    int* lst = klist + idx * 64;
    int c = 0;
    if (qb == 0 || qb == MM - 1) {
        for (int j = 0; j < MM; j++) lst[c++] = j;
    } else if (qb == 1) {
        lst[c++] = 0; lst[c++] = 1; lst[c++] = 2; lst[c++] = MM - 1;
        const int* rr = rand_attn + ((size_t)h * (MM - 2) + 0) * RR;
        for (int r = 0; r < RR; r++) lst[c++] = rr[r] | 256;
    } else if (qb == MM - 2) {
        lst[c++] = 0; lst[c++] = MM - 3; lst[c++] = MM - 2; lst[c++] = MM - 1;
        const int* rr = rand_attn + ((size_t)h * (MM - 2) + (MM - 3)) * RR;
        for (int r = 0; r < RR; r++) lst[c++] = rr[r] | 256;
    } else {
        lst[c++] = 0;
        lst[c++] = (qb - 1) | 256;
        lst[c++] = qb | 256;
        lst[c++] = (qb + 1) | 256;
        const int* rr = rand_attn + ((size_t)h * (MM - 2) + (qb - 1)) * RR;
        for (int r = 0; r < RR; r++) lst[c++] = rr[r] | 256;
        lst[c++] = MM - 1;
    }
    kcount[idx] = c;
}

// ---------------- HMMA flash attention (P aliases Q smem; 2 CTAs/SM) ---------
#define ARS  72
#define AQH  0
#define AQL  9216
#define AK0  18432
#define AV0  55296
#define ASS  92160
#define AMQ  109568
#define AMK  109824
#define ARSC 110080
#define ARL  110336
#define AENT 110592
#define ATTN_SMEM_B 110848

__global__ __launch_bounds__(256, 2)
void attn_mma(const __nv_bfloat16* __restrict__ qkvh, const __nv_bfloat16* __restrict__ qkvl,
              const float* __restrict__ mask,
              const int* __restrict__ klist, const int* __restrict__ kcount,
              __nv_bfloat16* __restrict__ oh, __nv_bfloat16* __restrict__ ol) {
    extern __shared__ char sm[];
    uint32_t sb = smem_u32(sm);
    float* Ss  = (float*)(sm + ASS);
    float* mq  = (float*)(sm + AMQ);
    float* mk  = (float*)(sm + AMK);
    float* rsc = (float*)(sm + ARSC);
    float* rl  = (float*)(sm + ARL);
    int*   ents= (int*)(sm + AENT);
    __nv_bfloat16* Ph = (__nv_bfloat16*)(sm + AQH);
    __nv_bfloat16* Pl = (__nv_bfloat16*)(sm + AQL);

    const __nv_bfloat16* qh = qkvh;
    const __nv_bfloat16* ql = qkvl;
    const __nv_bfloat16* kh = qkvh + 768;
    const __nv_bfloat16* kl = qkvl + 768;
    const __nv_bfloat16* vh = qkvh + 1536;
    const __nv_bfloat16* vl = qkvl + 1536;

    int qb = blockIdx.x, h = blockIdx.y;
    int tid = threadIdx.x;
    int w = tid >> 5, l = tid & 31;
    int wm = w & 1, wn = w >> 1;
    int gid = l >> 2, tig = l & 3;
    int srow = tid >> 2, sseg = (tid & 3) << 4;
    int lid = h * MM + qb;
    int cnt = kcount[lid];

    uint32_t lane_qa = (uint32_t)((wm * 32 + ((l >> 3) & 1) * 8 + (l & 7)) * ARS + (l >> 4) * 8) * 2;
    uint32_t lane_kb = (uint32_t)((wn * 16 + (l >> 4) * 8 + (l & 7)) * ARS + ((l >> 3) & 1) * 8) * 2;
    uint32_t lane_vt = (uint32_t)((((l >> 3) & 1) * 8 + (l & 7)) * ARS + wn * 16 + (l >> 4) * 8) * 2;

    if (tid < 64) {
        ents[tid] = klist[lid * 64 + tid];
        mq[tid]   = mask[qb * 64 + tid];
    }

    auto load_kv = [&](int kb, int s) {
        uint32_t bk_ = sb + AK0 + s * 18432;
        uint32_t bv_ = sb + AV0 + s * 18432;
        #pragma unroll
        for (int i = 0; i < 2; i++) {
            int linear = tid + i * 256;
            int r = linear >> 3, c8 = (linear & 7) << 3;
            uint32_t doff = (uint32_t)(r * ARS + c8) * 2;
            size_t g = (size_t)(kb * 64 + r) * QKVS + h * DHH + c8;
            cpa16(bk_ + doff,        kh + g);
            cpa16(bk_ + 9216 + doff, kl + g);
            cpa16(bv_ + doff,        vh + g);
            cpa16(bv_ + 9216 + doff, vl + g);
        }
    };

    #pragma unroll
    for (int i = 0; i < 2; i++) {
        int linear = tid + i * 256;
        int r = linear >> 3, c8 = (linear & 7) << 3;
        uint32_t doff = (uint32_t)(r * ARS + c8) * 2;
        size_t g = (size_t)(qb * 64 + r) * QKVS + h * DHH + c8;
        cpa16(sb + AQH + doff, qh + g);
        cpa16(sb + AQL + doff, ql + g);
    }
    __syncthreads();
    load_kv(ents[0] & 0xff, 0);
    cpa_commit();
    cpa_wait0();
    __syncthreads();

    uint32_t qfh[2][4][4], qfl[2][4][4];
    #pragma unroll
    for (int i = 0; i < 2; i++)
        #pragma unroll
        for (int ksi = 0; ksi < 4; ksi++) {
            ldm_x4(qfh[i][ksi], sb + AQH + lane_qa + (uint32_t)(i * 16 * ARS + ksi * 16) * 2);
            ldm_x4(qfl[i][ksi], sb + AQL + lane_qa + (uint32_t)(i * 16 * ARS + ksi * 16) * 2);
        }

    float m_run = -1e30f, l_run = 0.f;
    float o[2][2][4];
    #pragma unroll
    for (int i = 0; i < 2; i++)
        #pragma unroll
        for (int j = 0; j < 2; j++)
            #pragma unroll
            for (int r = 0; r < 4; r++) o[i][j][r] = 0.f;

    for (int b = 0; b < cnt; b++) {
        int e = ents[b], kb = e & 0xff, fl = e >> 8;
        if (b > 0) { cpa_wait0(); __syncthreads(); }
        if (b + 1 < cnt) { load_kv(ents[b + 1] & 0xff, (b + 1) & 1); cpa_commit(); }
        if (tid < 64) mk[tid] = mask[kb * 64 + tid];

        uint32_t baseKh = sb + AK0 + (b & 1) * 18432;
        uint32_t baseKl = baseKh + 9216;
        uint32_t baseVh = sb + AV0 + (b & 1) * 18432;
        uint32_t baseVl = baseVh + 9216;

        float sa[2][2][4];
        #pragma unroll
        for (int i = 0; i < 2; i++)
            #pragma unroll
            for (int j = 0; j < 2; j++)
                #pragma unroll
                for (int r = 0; r < 4; r++) sa[i][j][r] = 0.f;
        #pragma unroll
        for (int ksi = 0; ksi < 4; ksi++) {
            uint32_t bH[2][2], bL[2][2], t[4];
            ldm_x4(t, baseKh + lane_kb + (uint32_t)(ksi * 16) * 2);
            bH[0][0] = t[0]; bH[0][1] = t[1]; bH[1][0] = t[2]; bH[1][1] = t[3];
            ldm_x4(t, baseKl + lane_kb + (uint32_t)(ksi * 16) * 2);
            bL[0][0] = t[0]; bL[0][1] = t[1]; bL[1][0] = t[2]; bL[1][1] = t[3];
            #pragma unroll
            for (int i = 0; i < 2; i++)
                #pragma unroll
                for (int j = 0; j < 2; j++) {
                    mma_bf16(sa[i][j], qfh[i][ksi], bH[j]);
                    mma_bf16(sa[i][j], qfh[i][ksi], bL[j]);
                    mma_bf16(sa[i][j], qfl[i][ksi], bH[j]);
                }
        }
        #pragma unroll
        for (int i = 0; i < 2; i++) {
            int r = wm * 32 + i * 16 + gid;
            #pragma unroll
            for (int j = 0; j < 2; j++) {
                int c = wn * 16 + j * 8 + tig * 2;
                Ss[r * 68 + c]           = sa[i][j][0];
                Ss[r * 68 + c + 1]       = sa[i][j][1];
                Ss[(r + 8) * 68 + c]     = sa[i][j][2];
                Ss[(r + 8) * 68 + c + 1] = sa[i][j][3];
            }
        }
        __syncthreads();

        float mqv = mq[srow];
        float sv[16];
        #pragma unroll
        for (int j = 0; j < 16; j += 4) {
            float4 f = *(float4*)(Ss + srow * 68 + sseg + j);
            sv[j] = f.x; sv[j+1] = f.y; sv[j+2] = f.z; sv[j+3] = f.w;
        }
        #pragma unroll
        for (int j = 0; j < 16; j++) {
            float mkv = mk[sseg + j];
            float eff = fl ? (mqv * mkv) : mkv;
            sv[j] += (1.0f - eff) * NEGV;
        }
        float lm = sv[0];
        #pragma unroll
        for (int j = 1; j < 16; j++) lm = fmaxf(lm, sv[j]);
        lm = fmaxf(lm, __shfl_xor_sync(0xffffffffu, lm, 1));
        lm = fmaxf(lm, __shfl_xor_sync(0xffffffffu, lm, 2));
        float m_new = fmaxf(m_run, lm);
        float sc = expf(m_run - m_new);
        float ls = 0.f;
        #pragma unroll
        for (int j = 0; j < 16; j += 2) {
            float p0 = expf(sv[j]     - m_new);
            float p1 = expf(sv[j + 1] - m_new);
            ls += p0 + p1;
            __nv_bfloat162 hh = __floats2bfloat162_rn(p0, p1);
            __nv_bfloat162 lv = __floats2bfloat162_rn(p0 - __bfloat162float(hh.x),
                                                      p1 - __bfloat162float(hh.y));
            *(uint32_t*)(Ph + srow * ARS + sseg + j) = *(uint32_t*)&hh;
            *(uint32_t*)(Pl + srow * ARS + sseg + j) = *(uint32_t*)&lv;
        }
        ls += __shfl_xor_sync(0xffffffffu, ls, 1);
        ls += __shfl_xor_sync(0xffffffffu, ls, 2);
        l_run = l_run * sc + ls;
        m_run = m_new;
        if ((tid & 3) == 0) rsc[srow] = sc;
        __syncthreads();

        #pragma unroll
        for (int i = 0; i < 2; i++) {
            float s0 = rsc[wm * 32 + i * 16 + gid];
            float s1 = rsc[wm * 32 + i * 16 + gid + 8];
            #pragma unroll
            for (int j = 0; j < 2; j++) {
                o[i][j][0] *= s0; o[i][j][1] *= s0;
                o[i][j][2] *= s1; o[i][j][3] *= s1;
            }
        }
        #pragma unroll
        for (int ksi = 0; ksi < 4; ksi++) {
            uint32_t aH[2][4], aL[2][4], bH[2][2], bL[2][2], t[4];
            #pragma unroll
            for (int i = 0; i < 2; i++) {
                ldm_x4(aH[i], sb + AQH + lane_qa + (uint32_t)(i * 16 * ARS + ksi * 16) * 2);
                ldm_x4(aL[i], sb + AQL + lane_qa + (uint32_t)(i * 16 * ARS + ksi * 16) * 2);
            }
            ldm_x4_t(t, baseVh + lane_vt + (uint32_t)(ksi * 16 * ARS) * 2);
            bH[0][0] = t[0]; bH[0][1] = t[1]; bH[1][0] = t[2]; bH[1][1] = t[3];
            ldm_x4_t(t, baseVl + lane_vt + (uint32_t)(ksi * 16 * ARS) * 2);
            bL[0][0] = t[0]; bL[0][1] = t[1]; bL[1][0] = t[2]; bL[1][1] = t[3];
            #pragma unroll
            for (int i = 0; i < 2; i++)
                #pragma unroll
                for (int j = 0; j < 2; j++) {
                    mma_bf16(o[i][j], aH[i], bH[j]);
                    mma_bf16(o[i][j], aH[i], bL[j]);
                    mma_bf16(o[i][j], aL[i], bH[j]);
                }
        }
        __syncthreads();
    }

    if ((tid & 3) == 0) rl[srow] = l_run;
    __syncthreads();

    #pragma unroll
    for (int i = 0; i < 2; i++) {
        int r0 = wm * 32 + i * 16 + gid;
        int r1 = r0 + 8;
        float iv0 = mq[r0] / rl[r0];
        float iv1 = mq[r1] / rl[r1];
        #pragma unroll
        for (int j = 0; j < 2; j++) {
            int c = wn * 16 + j * 8 + tig * 2;
            float v0 = o[i][j][0] * iv0, v1 = o[i][j][1] * iv0;
            float v2 = o[i][j][2] * iv1, v3 = o[i][j][3] * iv1;
            __nv_bfloat162 h01 = __floats2bfloat162_rn(v0, v1);
            __nv_bfloat162 h23 = __floats2bfloat162_rn(v2, v3);
            __nv_bfloat162 l01 = __floats2bfloat162_rn(v0 - __bfloat162float(h01.x),
                                                       v1 - __bfloat162float(h01.y));
            __nv_bfloat162 l23 = __floats2bfloat162_rn(v2 - __bfloat162float(h23.x),
                                                       v3 - __bfloat162float(h23.y));
            size_t g0 = (size_t)(qb * 64 + r0) * DD + h * DHH + c;
            size_t g1 = (size_t)(qb * 64 + r1) * DD + h * DHH + c;
            *(uint32_t*)(oh + g0) = *(uint32_t*)&h01;
            *(uint32_t*)(ol + g0) = *(uint32_t*)&l01;
            *(uint32_t*)(oh + g1) = *(uint32_t*)&h23;
            *(uint32_t*)(ol + g1) = *(uint32_t*)&l23;
        }
    }
}

// ---------------- host orchestration ----------------
extern "C" void kernel_launch(void* const* d_in, const int* in_sizes, int n_in,
                              void* d_out, int out_size) {
    (void)in_sizes; (void)n_in; (void)out_size;
    const int*   ids      = (const int*)  d_in[0];
    const float* mask     = (const float*)d_in[1];
    const int*   rand_attn= (const int*)  d_in[2];
    const float* emb_word = (const float*)d_in[3];
    const float* emb_pos  = (const float*)d_in[4];
    const float* eln_g    = (const float*)d_in[5];
    const float* eln_b    = (const float*)d_in[6];
    const float* Wq = (const float*)d_in[7];  const float* bq = (const float*)d_in[8];
    const float* Wk = (const float*)d_in[9];  const float* bk = (const float*)d_in[10];
    const float* Wv = (const float*)d_in[11]; const float* bv = (const float*)d_in[12];
    const float* Wo = (const float*)d_in[13]; const float* bo = (const float*)d_in[14];
    const float* ln1g = (const float*)d_in[15]; const float* ln1b = (const float*)d_in[16];
    const float* W1 = (const float*)d_in[17]; const float* b1 = (const float*)d_in[18];
    const float* W2 = (const float*)d_in[19]; const float* b2 = (const float*)d_in[20];
    const float* ln2g = (const float*)d_in[21]; const float* ln2b = (const float*)d_in[22];
    float* outp = (float*)d_out;

    float *px, *pt, *pbqkv;
    __nv_bfloat16 *xh, *xl, *pqkvh, *pqkvl, *pah, *pal, *pfh, *pfl, *pwh, *pwl;
    int *pklist, *pkc;
    cudaGetSymbolAddress((void**)&px,  g_x);
    cudaGetSymbolAddress((void**)&pt,  g_t);
    cudaGetSymbolAddress((void**)&xh,  g_xh);   cudaGetSymbolAddress((void**)&xl,  g_xl);
    cudaGetSymbolAddress((void**)&pqkvh, g_qkvh); cudaGetSymbolAddress((void**)&pqkvl, g_qkvl);
    cudaGetSymbolAddress((void**)&pah, g_ah);   cudaGetSymbolAddress((void**)&pal, g_al);
    cudaGetSymbolAddress((void**)&pfh, g_fh);   cudaGetSymbolAddress((void**)&pfl, g_fl);
    cudaGetSymbolAddress((void**)&pwh, g_wTh);  cudaGetSymbolAddress((void**)&pwl, g_wTl);
    cudaGetSymbolAddress((void**)&pbqkv, g_bqkv);
    cudaGetSymbolAddress((void**)&pklist, g_klist);
    cudaGetSymbolAddress((void**)&pkc,    g_kcount);

    cudaFuncSetAttribute(gemm_mma, cudaFuncAttributeMaxDynamicSharedMemorySize, GEMM_SMEM);
    cudaFuncSetAttribute(attn_mma, cudaFuncAttributeMaxDynamicSharedMemorySize, ATTN_SMEM_B);

    const size_t OQ = 0, OO = 1769472, O1 = 2359296, O2 = 4718592;

    dim3 gQKV(QKVS / 128, NN / 128);
    dim3 gProj(DD / 128, NN / 128);
    dim3 gF1(FFD / 128, NN / 128);
    dim3 gAttn(MM, HH);
    dim3 gT768(DD / 32, DD / 32);
    dim3 gTQKV(QKVS / 32, DD / 32);

    // launch order: #4 (ncu capture position) = layer-0 QKV gemm_mma
    embed_ln<<<NN, 256>>>(ids, emb_word, emb_pos, eln_g, eln_b, px, xh, xl);          // 1
    bias_cat<<<(LL * QKVS + 255) / 256, 256>>>(bq, bk, bv, pbqkv);                    // 2
    wtrans_qkv<<<gTQKV, 256>>>(Wq, Wk, Wv, pwh + OQ, pwl + OQ);                       // 3
    gemm_mma<<<gQKV, 256, GEMM_SMEM>>>(xh, xl, pwh + OQ, pwl + OQ,
                                       pbqkv, nullptr, pqkvh, pqkvl, QKVS, DD, 0, 768); // 4 <- profiled
    build_klist<<<(HH * MM + 127) / 128, 128>>>(rand_attn, pklist, pkc);

    wtrans<<<gT768, 256>>>(Wo, pwh + OO, pwl + OO, DD, DD);
    wtrans<<<dim3(FFD/32, DD/32), 256>>>(W1, pwh + O1, pwl + O1, DD, FFD);
    wtrans<<<dim3(DD/32, FFD/32), 256>>>(W2, pwh + O2, pwl + O2, FFD, DD);
    for (int i = 1; i < LL; i++) {
        size_t lo = (size_t)i * WPL;
        wtrans_qkv<<<gTQKV, 256>>>(Wq + (size_t)i*DD*DD, Wk + (size_t)i*DD*DD, Wv + (size_t)i*DD*DD,
                                   pwh + lo + OQ, pwl + lo + OQ);
        wtrans<<<gT768, 256>>>(Wo + (size_t)i*DD*DD, pwh + lo + OO, pwl + lo + OO, DD, DD);
        wtrans<<<dim3(FFD/32, DD/32), 256>>>(W1 + (size_t)i*DD*FFD, pwh + lo + O1, pwl + lo + O1, DD, FFD);
        wtrans<<<dim3(DD/32, FFD/32), 256>>>(W2 + (size_t)i*FFD*DD, pwh + lo + O2, pwl + lo + O2, FFD, DD);
    }

    for (int i = 0; i < LL; i++) {
        size_t lo = (size_t)i * WPL;
        if (i > 0)
            gemm_mma<<<gQKV, 256, GEMM_SMEM>>>(xh, xl, pwh + lo + OQ, pwl + lo + OQ,
                                               pbqkv + (size_t)i * QKVS, nullptr, pqkvh, pqkvl, QKVS, DD, 0, 768);
        attn_mma<<<gAttn, 256, ATTN_SMEM_B>>>(pqkvh, pqkvl, mask, pklist, pkc, pah, pal);
        gemm_mma<<<gProj, 256, GEMM_SMEM>>>(pah, pal, pwh + lo + OO, pwl + lo + OO,
                                            bo + (size_t)i*DD, pt, nullptr, nullptr, DD, DD, 0, 0);
        ln_kernel<<<NN, 256>>>(px, pt, ln1g + (size_t)i*DD, ln1b + (size_t)i*DD, px, xh, xl);
        gemm_mma<<<gF1, 256, GEMM_SMEM>>>(xh, xl, pwh + lo + O1, pwl + lo + O1,
                                          b1 + (size_t)i*FFD, nullptr, pfh, pfl, FFD, DD, 1, 0);
        gemm_mma<<<gProj, 256, GEMM_SMEM>>>(pfh, pfl, pwh + lo + O2, pwl + lo + O2,
                                            b2 + (size_t)i*DD, pt, nullptr, nullptr, DD, FFD, 0, 0);
        if (i == LL - 1)
            ln_kernel<<<NN, 256>>>(px, pt, ln2g + (size_t)i*DD, ln2b + (size_t)i*DD, outp, nullptr, nullptr);
        else
            ln_kernel<<<NN, 256>>>(px, pt, ln2g + (size_t)i*DD, ln2b + (size_t)i*DD, px, xh, xl);
    }
}

// round 10
// speedup vs baseline: 13.6675x; 1.1418x over previous
#include <cuda_runtime.h>
#include <cuda_bf16.h>
#include <math.h>
#include <stdint.h>

// ---------------- problem constants ----------------
#define NN   4096
#define HH   12
#define DHH  64
#define DD   768
#define LL   4
#define FFD  3072
#define MM   64
#define RR   3
#define NEGV (-10000.0f)
#define QKVS 2304
#define ATTN_GRID 936     // 744 middle-row items + 192 full-row split items
#define NSLOT 192

// ---------------- device scratch ----------------
__device__ float g_x [NN * DD];
__device__ float g_t [NN * DD];
__device__ __nv_bfloat16 g_xh[NN * DD],  g_xl[NN * DD];
__device__ __nv_bfloat16 g_qkvh[NN * QKVS], g_qkvl[NN * QKVS];
__device__ __nv_bfloat16 g_ah[NN * DD],  g_al[NN * DD];
__device__ __nv_bfloat16 g_fh[NN * FFD], g_fl[NN * FFD];
__device__ float g_bqkv[LL * QKVS];
__device__ int   g_klist [HH * MM * 64];
__device__ int   g_kcount[HH * MM];
__device__ float g_po[NSLOT * 64 * 64];
__device__ float g_pm[NSLOT * 64];
__device__ float g_pl[NSLOT * 64];
#define WPL 7077888ULL
__device__ __nv_bfloat16 g_wTh[LL * WPL];
__device__ __nv_bfloat16 g_wTl[LL * WPL];

// ---------------- asm helpers ----------------
__device__ __forceinline__ uint32_t smem_u32(const void* p) {
    uint32_t a;
    asm("{ .reg .u64 t; cvta.to.shared.u64 t, %1; cvt.u32.u64 %0, t; }" : "=r"(a) : "l"(p));
    return a;
}
__device__ __forceinline__ void cpa16(uint32_t dst, const void* src) {
    asm volatile("cp.async.cg.shared.global [%0], [%1], 16;" :: "r"(dst), "l"(src));
}
__device__ __forceinline__ void cpa_commit() { asm volatile("cp.async.commit_group;" ::: "memory"); }
__device__ __forceinline__ void cpa_wait0()  { asm volatile("cp.async.wait_group 0;" ::: "memory"); }
__device__ __forceinline__ void cpa_wait1()  { asm volatile("cp.async.wait_group 1;" ::: "memory"); }

__device__ __forceinline__ void mma_bf16(float* c, const uint32_t* a, const uint32_t* b) {
    asm volatile(
        "mma.sync.aligned.m16n8k16.row.col.f32.bf16.bf16.f32 "
        "{%0,%1,%2,%3}, {%4,%5,%6,%7}, {%8,%9}, {%0,%1,%2,%3};"
        : "+f"(c[0]), "+f"(c[1]), "+f"(c[2]), "+f"(c[3])
        : "r"(a[0]), "r"(a[1]), "r"(a[2]), "r"(a[3]), "r"(b[0]), "r"(b[1]));
}
__device__ __forceinline__ void ldm_x4(uint32_t* r, uint32_t addr) {
    asm volatile("ldmatrix.sync.aligned.m8n8.x4.shared.b16 {%0,%1,%2,%3}, [%4];"
        : "=r"(r[0]), "=r"(r[1]), "=r"(r[2]), "=r"(r[3]) : "r"(addr));
}
__device__ __forceinline__ void ldm_x4_t(uint32_t* r, uint32_t addr) {
    asm volatile("ldmatrix.sync.aligned.m8n8.x4.trans.shared.b16 {%0,%1,%2,%3}, [%4];"
        : "=r"(r[0]), "=r"(r[1]), "=r"(r[2]), "=r"(r[3]) : "r"(addr));
}

// ---------------- misc kernels ----------------
__device__ __forceinline__ float block_reduce(float val, bool is_max, float* rbuf) {
    int lane = threadIdx.x & 31;
    int w    = threadIdx.x >> 5;
    #pragma unroll
    for (int o = 16; o; o >>= 1) {
        float other = __shfl_xor_sync(0xffffffffu, val, o);
        val = is_max ? fmaxf(val, other) : (val + other);
    }
    if (lane == 0) rbuf[w] = val;
    __syncthreads();
    if (threadIdx.x == 0) {
        int nw = (blockDim.x + 31) >> 5;
        float r = rbuf[0];
        for (int i = 1; i < nw; i++) r = is_max ? fmaxf(r, rbuf[i]) : (r + rbuf[i]);
        rbuf[0] = r;
    }
    __syncthreads();
    float res = rbuf[0];
    __syncthreads();
    return res;
}

__global__ void embed_ln(const int* __restrict__ ids,
                         const float* __restrict__ ew,
                         const float* __restrict__ ep,
                         const float* __restrict__ g,
                         const float* __restrict__ b,
                         float* __restrict__ outf,
                         __nv_bfloat16* __restrict__ outh,
                         __nv_bfloat16* __restrict__ outl) {
    __shared__ float s[DD];
    __shared__ float rbuf[8];
    int t = blockIdx.x;
    int tid = threadIdx.x;
    int id = ids[t];
    const float* wr = ew + (size_t)id * DD;
    const float* pr = ep + (size_t)t * DD;
    float lsum = 0.f;
    for (int d = tid; d < DD; d += blockDim.x) {
        float v = wr[d] + pr[d];
        s[d] = v;
        lsum += v;
    }
    float mu = block_reduce(lsum, false, rbuf) * (1.0f / DD);
    float lvar = 0.f;
    for (int d = tid; d < DD; d += blockDim.x) {
        float dv = s[d] - mu;
        lvar += dv * dv;
    }
    float var = block_reduce(lvar, false, rbuf) * (1.0f / DD);
    float inv = rsqrtf(var + 1e-5f);
    for (int d = tid; d < DD; d += blockDim.x) {
        float val = (s[d] - mu) * inv * g[d] + b[d];
        outf[(size_t)t * DD + d] = val;
        __nv_bfloat16 h = __float2bfloat16(val);
        outh[(size_t)t * DD + d] = h;
        outl[(size_t)t * DD + d] = __float2bfloat16(val - __bfloat162float(h));
    }
}

__global__ void ln_kernel(const float* __restrict__ A,
                          const float* __restrict__ Bres,
                          const float* __restrict__ g,
                          const float* __restrict__ b,
                          float* __restrict__ outf,
                          __nv_bfloat16* __restrict__ outh,
                          __nv_bfloat16* __restrict__ outl) {
    __shared__ float s[DD];
    __shared__ float rbuf[8];
    int t = blockIdx.x;
    int tid = threadIdx.x;
    const float* ar = A + (size_t)t * DD;
    const float* br = Bres ? (Bres + (size_t)t * DD) : nullptr;
    float lsum = 0.f;
    for (int d = tid; d < DD; d += blockDim.x) {
        float v = ar[d];
        if (br) v += br[d];
        s[d] = v;
        lsum += v;
    }
    float mu = block_reduce(lsum, false, rbuf) * (1.0f / DD);
    float lvar = 0.f;
    for (int d = tid; d < DD; d += blockDim.x) {
        float dv = s[d] - mu;
        lvar += dv * dv;
    }
    float var = block_reduce(lvar, false, rbuf) * (1.0f / DD);
    float inv = rsqrtf(var + 1e-5f);
    for (int d = tid; d < DD; d += blockDim.x) {
        float val = (s[d] - mu) * inv * g[d] + b[d];
        if (outf) outf[(size_t)t * DD + d] = val;
        if (outh) {
            __nv_bfloat16 h = __float2bfloat16(val);
            outh[(size_t)t * DD + d] = h;
            outl[(size_t)t * DD + d] = __float2bfloat16(val - __bfloat162float(h));
        }
    }
}

__global__ void wtrans(const float* __restrict__ W,
                       __nv_bfloat16* __restrict__ oh,
                       __nv_bfloat16* __restrict__ ol,
                       int K, int N) {
    __shared__ float sm[32][33];
    int n0 = blockIdx.x * 32, k0 = blockIdx.y * 32;
    int tx = threadIdx.x & 31, ty = threadIdx.x >> 5;
    #pragma unroll
    for (int j = 0; j < 4; j++) {
        int kk = ty + j * 8;
        sm[kk][tx] = W[(size_t)(k0 + kk) * N + n0 + tx];
    }
    __syncthreads();
    #pragma unroll
    for (int j = 0; j < 4; j++) {
        int nn = ty + j * 8;
        float v = sm[tx][nn];
        __nv_bfloat16 h = __float2bfloat16(v);
        float r = v - __bfloat162float(h);
        size_t o = (size_t)(n0 + nn) * K + k0 + tx;
        oh[o] = h;
        ol[o] = __float2bfloat16(r);
    }
}

__global__ void wtrans_qkv(const float* __restrict__ Wq, const float* __restrict__ Wk,
                           const float* __restrict__ Wv,
                           __nv_bfloat16* __restrict__ oh, __nv_bfloat16* __restrict__ ol) {
    __shared__ float sm[32][33];
    int n0 = blockIdx.x * 32, k0 = blockIdx.y * 32;
    const float* W = (n0 < 768) ? Wq : (n0 < 1536) ? Wk : Wv;
    int nl0 = n0 % 768;
    int tx = threadIdx.x & 31, ty = threadIdx.x >> 5;
    #pragma unroll
    for (int j = 0; j < 4; j++) {
        int kk = ty + j * 8;
        sm[kk][tx] = W[(size_t)(k0 + kk) * 768 + nl0 + tx];
    }
    __syncthreads();
    #pragma unroll
    for (int j = 0; j < 4; j++) {
        int nn = ty + j * 8;
        float v = sm[tx][nn];
        __nv_bfloat16 h = __float2bfloat16(v);
        float r = v - __bfloat162float(h);
        size_t o = (size_t)(n0 + nn) * DD + k0 + tx;
        oh[o] = h;
        ol[o] = __float2bfloat16(r);
    }
}

__global__ void bias_cat(const float* __restrict__ bq, const float* __restrict__ bk,
                         const float* __restrict__ bv, float* __restrict__ out) {
    int i = blockIdx.x * blockDim.x + threadIdx.x;
    if (i >= LL * QKVS) return;
    int l = i / QKVS, c = i % QKVS;
    float v;
    if (c < 768)       v = bq[l * 768 + c];
    else if (c < 1536) v = bk[l * 768 + c - 768];
    else               v = bv[l * 768 + c - 1536];
    out[i] = v;
}

// ---------------- HMMA GEMM (unchanged from R9) ----------------
#define RS      72
#define TILE_B  (128 * RS * 2)
#define STAGE_B (2 * TILE_B)
#define GEMM_SMEM (3 * STAGE_B)

__global__ __launch_bounds__(256, 2)
void gemm_mma(const __nv_bfloat16* __restrict__ Agh, const __nv_bfloat16* __restrict__ Agl,
              const __nv_bfloat16* __restrict__ Bgh, const __nv_bfloat16* __restrict__ Bgl,
              const float* __restrict__ bias,
              float* __restrict__ Cf,
              __nv_bfloat16* __restrict__ Ch, __nv_bfloat16* __restrict__ Cl,
              int Nd, int K, int act, int qs_cols) {
    extern __shared__ __nv_bfloat16 smem[];
    uint32_t sb = smem_u32(smem);
    int tid = threadIdx.x;
    int m0 = blockIdx.y * 128, n0 = blockIdx.x * 128;
    int w = tid >> 5, l = tid & 31;
    int wm = w & 1, wn = w >> 1;
    int gid = l >> 2, tig = l & 3;

    uint32_t lane_a = (uint32_t)((wm * 64 + ((l >> 3) & 1) * 8 + (l & 7)) * RS + (l >> 4) * 8) * 2;
    uint32_t lane_b = (uint32_t)((wn * 32 + (l >> 4) * 8 + (l & 7)) * RS + ((l >> 3) & 1) * 8) * 2;

    float acc[4][4][4];
    #pragma unroll
    for (int i = 0; i < 4; i++)
        #pragma unroll
        for (int j = 0; j < 4; j++)
            #pragma unroll
            for (int r = 0; r < 4; r++) acc[i][j][r] = 0.f;

    int nchunk = K >> 5;

    auto load_chunk = [&](int c, int s) {
        int k0 = c << 5;
        uint32_t stg = sb + s * STAGE_B;
        #pragma unroll
        for (int i = 0; i < 2; i++) {
            int linear = tid + i * 256;
            int row = linear >> 2;
            int kc  = (linear & 3) << 3;
            uint32_t dhi = (uint32_t)(row * RS + kc) * 2;
            uint32_t dlo = (uint32_t)(row * RS + 32 + kc) * 2;
            size_t ga = (size_t)(m0 + row) * K + k0 + kc;
            cpa16(stg + dhi,          Agh + ga);
            cpa16(stg + dlo,          Agl + ga);
            size_t gb = (size_t)(n0 + row) * K + k0 + kc;
            cpa16(stg + TILE_B + dhi, Bgh + gb);
            cpa16(stg + TILE_B + dlo, Bgl + gb);
        }
    };

    load_chunk(0, 0); cpa_commit();
    load_chunk(1, 1); cpa_commit();

    for (int c = 0; c < nchunk; c++) {
        if (c + 1 < nchunk) cpa_wait1(); else cpa_wait0();
        __syncthreads();
        uint32_t base = sb + (c % 3) * STAGE_B;

        #pragma unroll
        for (int ks = 0; ks < 2; ks++) {
            uint32_t khi = (uint32_t)(ks * 16) * 2;
            uint32_t klo = (uint32_t)(32 + ks * 16) * 2;

            uint32_t aH[4][4], bH[4][2];
            #pragma unroll
            for (int i = 0; i < 4; i++)
                ldm_x4(aH[i], base + lane_a + (uint32_t)(i * 16 * RS) * 2 + khi);
            #pragma unroll
            for (int jj = 0; jj < 2; jj++) {
                uint32_t t[4];
                ldm_x4(t, base + TILE_B + lane_b + (uint32_t)(jj * 16 * RS) * 2 + khi);
                bH[2 * jj][0] = t[0]; bH[2 * jj][1] = t[1];
                bH[2 * jj + 1][0] = t[2]; bH[2 * jj + 1][1] = t[3];
            }
            #pragma unroll
            for (int i = 0; i < 4; i++)
                #pragma unroll
                for (int j = 0; j < 4; j++)
                    mma_bf16(acc[i][j], aH[i], bH[j]);

            uint32_t bL[4][2];
            #pragma unroll
            for (int jj = 0; jj < 2; jj++) {
                uint32_t t[4];
                ldm_x4(t, base + TILE_B + lane_b + (uint32_t)(jj * 16 * RS) * 2 + klo);
                bL[2 * jj][0] = t[0]; bL[2 * jj][1] = t[1];
                bL[2 * jj + 1][0] = t[2]; bL[2 * jj + 1][1] = t[3];
            }
            #pragma unroll
            for (int i = 0; i < 4; i++)
                #pragma unroll
                for (int j = 0; j < 4; j++)
                    mma_bf16(acc[i][j], aH[i], bL[j]);

            uint32_t aL[4][4];
            #pragma unroll
            for (int i = 0; i < 4; i++)
                ldm_x4(aL[i], base + lane_a + (uint32_t)(i * 16 * RS) * 2 + klo);
            #pragma unroll
            for (int i = 0; i < 4; i++)
                #pragma unroll
                for (int j = 0; j < 4; j++)
                    mma_bf16(acc[i][j], aL[i], bH[j]);
        }
        if (c + 2 < nchunk) load_chunk(c + 2, (c + 2) % 3);
        cpa_commit();
    }

    #pragma unroll
    for (int i = 0; i < 4; i++) {
        int row = m0 + wm * 64 + i * 16 + gid;
        #pragma unroll
        for (int j = 0; j < 4; j++) {
            int col = n0 + wn * 32 + j * 8 + tig * 2;
            float b0 = bias[col], b1 = bias[col + 1];
            float v0 = acc[i][j][0] + b0;
            float v1 = acc[i][j][1] + b1;
            float v2 = acc[i][j][2] + b0;
            float v3 = acc[i][j][3] + b1;
            if (col < qs_cols) { v0 *= 0.125f; v1 *= 0.125f; v2 *= 0.125f; v3 *= 0.125f; }
            if (act) {
                v0 = 0.5f * v0 * (1.0f + erff(v0 * 0.70710678118654752f));
                v1 = 0.5f * v1 * (1.0f + erff(v1 * 0.70710678118654752f));
                v2 = 0.5f * v2 * (1.0f + erff(v2 * 0.70710678118654752f));
                v3 = 0.5f * v3 * (1.0f + erff(v3 * 0.70710678118654752f));
            }
            if (Cf) {
                *(float2*)(Cf + (size_t)row * Nd + col)       = make_float2(v0, v1);
                *(float2*)(Cf + (size_t)(row + 8) * Nd + col) = make_float2(v2, v3);
            } else {
                __nv_bfloat162 h01 = __floats2bfloat162_rn(v0, v1);
                __nv_bfloat162 h23 = __floats2bfloat162_rn(v2, v3);
                __nv_bfloat162 l01 = __floats2bfloat162_rn(v0 - __bfloat162float(h01.x),
                                                           v1 - __bfloat162float(h01.y));
                __nv_bfloat162 l23 = __floats2bfloat162_rn(v2 - __bfloat162float(h23.x),
                                                           v3 - __bfloat162float(h23.y));
                *(uint32_t*)(Ch + (size_t)row * Nd + col)       = *(uint32_t*)&h01;
                *(uint32_t*)(Cl + (size_t)row * Nd + col)       = *(uint32_t*)&l01;
                *(uint32_t*)(Ch + (size_t)(row + 8) * Nd + col) = *(uint32_t*)&h23;
                *(uint32_t*)(Cl + (size_t)(row + 8) * Nd + col) = *(uint32_t*)&l23;
            }
        }
    }
}

// ---------------- key-block list ----------------
__global__ void build_klist(const int* __restrict__ rand_attn,
                            int* __restrict__ klist,
                            int* __restrict__ kcount) {
    int idx = blockIdx.x * blockDim.x + threadIdx.x;
    if (idx >= HH * MM) return;
    int h  = idx / MM;
    int qb = idx % MM;
    int* lst = klist + idx * 64;
    int c = 0;
    if (qb == 0 || qb == MM - 1) {
        for (int j = 0; j < MM; j++) lst[c++] = j;
    } else if (qb == 1) {
        lst[c++] = 0; lst[c++] = 1; lst[c++] = 2; lst[c++] = MM - 1;
        const int* rr = rand_attn + ((size_t)h * (MM - 2) + 0) * RR;
        for (int r = 0; r < RR; r++) lst[c++] = rr[r] | 256;
    } else if (qb == MM - 2) {
        lst[c++] = 0; lst[c++] = MM - 3; lst[c++] = MM - 2; lst[c++] = MM - 1;
        const int* rr = rand_attn + ((size_t)h * (MM - 2) + (MM - 3)) * RR;
        for (int r = 0; r < RR; r++) lst[c++] = rr[r] | 256;
    } else {
        lst[c++] = 0;
        lst[c++] = (qb - 1) | 256;
        lst[c++] = qb | 256;
        lst[c++] = (qb + 1) | 256;
        const int* rr = rand_attn + ((size_t)h * (MM - 2) + (qb - 1)) * RR;
        for (int r = 0; r < RR; r++) lst[c++] = rr[r] | 256;
        lst[c++] = MM - 1;
    }
    kcount[idx] = c;
}

// ---------------- HMMA flash attention with full-row splitting ----------------
#define ARS  72
#define AQH  0
#define AQL  9216
#define AK0  18432
#define AV0  55296
#define ASS  92160
#define AMQ  109568
#define AMK  109824
#define ARSC 110080
#define ARL  110336
#define AENT 110592
#define ATTN_SMEM_B 110848

__global__ __launch_bounds__(256, 2)
void attn_mma(const __nv_bfloat16* __restrict__ qkvh, const __nv_bfloat16* __restrict__ qkvl,
              const float* __restrict__ mask,
              const int* __restrict__ klist, const int* __restrict__ kcount,
              __nv_bfloat16* __restrict__ oh, __nv_bfloat16* __restrict__ ol,
              float* __restrict__ po, float* __restrict__ pmo, float* __restrict__ plo) {
    extern __shared__ char sm[];
    uint32_t sb = smem_u32(sm);
    float* Ss  = (float*)(sm + ASS);
    float* mq  = (float*)(sm + AMQ);
    float* mk  = (float*)(sm + AMK);
    float* rsc = (float*)(sm + ARSC);
    float* rl  = (float*)(sm + ARL);
    int*   ents= (int*)(sm + AENT);
    __nv_bfloat16* Ph = (__nv_bfloat16*)(sm + AQH);
    __nv_bfloat16* Pl = (__nv_bfloat16*)(sm + AQL);

    const __nv_bfloat16* qh = qkvh;
    const __nv_bfloat16* ql = qkvl;
    const __nv_bfloat16* kh = qkvh + 768;
    const __nv_bfloat16* kl = qkvl + 768;
    const __nv_bfloat16* vh = qkvh + 1536;
    const __nv_bfloat16* vl = qkvl + 1536;

    // ---- work item decode ----
    int item = blockIdx.x;
    int h, qb, bstart, bcnt, slot;
    if (item < 744) {
        h = item / 62;
        qb = 1 + item % 62;
        bstart = 0;
        slot = -1;
        bcnt = kcount[h * MM + qb];
    } else {
        int j = item - 744;
        h = j >> 4;
        int rest = j & 15;
        qb = (rest < 8) ? 0 : (MM - 1);
        int seg = rest & 7;
        bstart = seg * 8;
        bcnt = 8;
        slot = j;
    }
    int lid = h * MM + qb;

    int tid = threadIdx.x;
    int w = tid >> 5, l = tid & 31;
    int wm = w & 1, wn = w >> 1;
    int gid = l >> 2, tig = l & 3;
    int srow = tid >> 2, sseg = (tid & 3) << 4;

    uint32_t lane_qa = (uint32_t)((wm * 32 + ((l >> 3) & 1) * 8 + (l & 7)) * ARS + (l >> 4) * 8) * 2;
    uint32_t lane_kb = (uint32_t)((wn * 16 + (l >> 4) * 8 + (l & 7)) * ARS + ((l >> 3) & 1) * 8) * 2;
    uint32_t lane_vt = (uint32_t)((((l >> 3) & 1) * 8 + (l & 7)) * ARS + wn * 16 + (l >> 4) * 8) * 2;

    if (tid < 64) {
        ents[tid] = klist[lid * 64 + tid];
        mq[tid]   = mask[qb * 64 + tid];
    }

    auto load_kv = [&](int kb, int s) {
        uint32_t bk_ = sb + AK0 + s * 18432;
        uint32_t bv_ = sb + AV0 + s * 18432;
        #pragma unroll
        for (int i = 0; i < 2; i++) {
            int linear = tid + i * 256;
            int r = linear >> 3, c8 = (linear & 7) << 3;
            uint32_t doff = (uint32_t)(r * ARS + c8) * 2;
            size_t g = (size_t)(kb * 64 + r) * QKVS + h * DHH + c8;
            cpa16(bk_ + doff,        kh + g);
            cpa16(bk_ + 9216 + doff, kl + g);
            cpa16(bv_ + doff,        vh + g);
            cpa16(bv_ + 9216 + doff, vl + g);
        }
    };

    #pragma unroll
    for (int i = 0; i < 2; i++) {
        int linear = tid + i * 256;
        int r = linear >> 3, c8 = (linear & 7) << 3;
        uint32_t doff = (uint32_t)(r * ARS + c8) * 2;
        size_t g = (size_t)(qb * 64 + r) * QKVS + h * DHH + c8;
        cpa16(sb + AQH + doff, qh + g);
        cpa16(sb + AQL + doff, ql + g);
    }
    __syncthreads();
    load_kv(ents[bstart] & 0xff, 0);
    cpa_commit();
    cpa_wait0();
    __syncthreads();

    uint32_t qfh[2][4][4], qfl[2][4][4];
    #pragma unroll
    for (int i = 0; i < 2; i++)
        #pragma unroll
        for (int ksi = 0; ksi < 4; ksi++) {
            ldm_x4(qfh[i][ksi], sb + AQH + lane_qa + (uint32_t)(i * 16 * ARS + ksi * 16) * 2);
            ldm_x4(qfl[i][ksi], sb + AQL + lane_qa + (uint32_t)(i * 16 * ARS + ksi * 16) * 2);
        }

    float m_run = -1e30f, l_run = 0.f;
    float o[2][2][4];
    #pragma unroll
    for (int i = 0; i < 2; i++)
        #pragma unroll
        for (int j = 0; j < 2; j++)
            #pragma unroll
            for (int r = 0; r < 4; r++) o[i][j][r] = 0.f;

    for (int b = 0; b < bcnt; b++) {
        int e = ents[bstart + b], kb = e & 0xff, fl = e >> 8;
        if (b > 0) { cpa_wait0(); __syncthreads(); }
        if (b + 1 < bcnt) { load_kv(ents[bstart + b + 1] & 0xff, (b + 1) & 1); cpa_commit(); }
        if (tid < 64) mk[tid] = mask[kb * 64 + tid];

        uint32_t baseKh = sb + AK0 + (b & 1) * 18432;
        uint32_t baseKl = baseKh + 9216;
        uint32_t baseVh = sb + AV0 + (b & 1) * 18432;
        uint32_t baseVl = baseVh + 9216;

        float sa[2][2][4];
        #pragma unroll
        for (int i = 0; i < 2; i++)
            #pragma unroll
            for (int j = 0; j < 2; j++)
                #pragma unroll
                for (int r = 0; r < 4; r++) sa[i][j][r] = 0.f;
        #pragma unroll
        for (int ksi = 0; ksi < 4; ksi++) {
            uint32_t bH[2][2], bL[2][2], t[4];
            ldm_x4(t, baseKh + lane_kb + (uint32_t)(ksi * 16) * 2);
            bH[0][0] = t[0]; bH[0][1] = t[1]; bH[1][0] = t[2]; bH[1][1] = t[3];
            ldm_x4(t, baseKl + lane_kb + (uint32_t)(ksi * 16) * 2);
            bL[0][0] = t[0]; bL[0][1] = t[1]; bL[1][0] = t[2]; bL[1][1] = t[3];
            #pragma unroll
            for (int i = 0; i < 2; i++)
                #pragma unroll
                for (int j = 0; j < 2; j++) {
                    mma_bf16(sa[i][j], qfh[i][ksi], bH[j]);
                    mma_bf16(sa[i][j], qfh[i][ksi], bL[j]);
                    mma_bf16(sa[i][j], qfl[i][ksi], bH[j]);
                }
        }
        #pragma unroll
        for (int i = 0; i < 2; i++) {
            int r = wm * 32 + i * 16 + gid;
            #pragma unroll
            for (int j = 0; j < 2; j++) {
                int c = wn * 16 + j * 8 + tig * 2;
                Ss[r * 68 + c]           = sa[i][j][0];
                Ss[r * 68 + c + 1]       = sa[i][j][1];
                Ss[(r + 8) * 68 + c]     = sa[i][j][2];
                Ss[(r + 8) * 68 + c + 1] = sa[i][j][3];
            }
        }
        __syncthreads();

        float mqv = mq[srow];
        float sv[16];
        #pragma unroll
        for (int j = 0; j < 16; j += 4) {
            float4 f = *(float4*)(Ss + srow * 68 + sseg + j);
            sv[j] = f.x; sv[j+1] = f.y; sv[j+2] = f.z; sv[j+3] = f.w;
        }
        #pragma unroll
        for (int j = 0; j < 16; j++) {
            float mkv = mk[sseg + j];
            float eff = fl ? (mqv * mkv) : mkv;
            sv[j] += (1.0f - eff) * NEGV;
        }
        float lm = sv[0];
        #pragma unroll
        for (int j = 1; j < 16; j++) lm = fmaxf(lm, sv[j]);
        lm = fmaxf(lm, __shfl_xor_sync(0xffffffffu, lm, 1));
        lm = fmaxf(lm, __shfl_xor_sync(0xffffffffu, lm, 2));
        float m_new = fmaxf(m_run, lm);
        float sc = expf(m_run - m_new);
        float ls = 0.f;
        #pragma unroll
        for (int j = 0; j < 16; j += 2) {
            float p0 = expf(sv[j]     - m_new);
            float p1 = expf(sv[j + 1] - m_new);
            ls += p0 + p1;
            __nv_bfloat162 hh = __floats2bfloat162_rn(p0, p1);
            __nv_bfloat162 lv = __floats2bfloat162_rn(p0 - __bfloat162float(hh.x),
                                                      p1 - __bfloat162float(hh.y));
            *(uint32_t*)(Ph + srow * ARS + sseg + j) = *(uint32_t*)&hh;
            *(uint32_t*)(Pl + srow * ARS + sseg + j) = *(uint32_t*)&lv;
        }
        ls += __shfl_xor_sync(0xffffffffu, ls, 1);
        ls += __shfl_xor_sync(0xffffffffu, ls, 2);
        l_run = l_run * sc + ls;
        m_run = m_new;
        if ((tid & 3) == 0) rsc[srow] = sc;
        __syncthreads();

        #pragma unroll
        for (int i = 0; i < 2; i++) {
            float s0 = rsc[wm * 32 + i * 16 + gid];
            float s1 = rsc[wm * 32 + i * 16 + gid + 8];
            #pragma unroll
            for (int j = 0; j < 2; j++) {
                o[i][j][0] *= s0; o[i][j][1] *= s0;
                o[i][j][2] *= s1; o[i][j][3] *= s1;
            }
        }
        #pragma unroll
        for (int ksi = 0; ksi < 4; ksi++) {
            uint32_t aH[2][4], aL[2][4], bH[2][2], bL[2][2], t[4];
            #pragma unroll
            for (int i = 0; i < 2; i++) {
                ldm_x4(aH[i], sb + AQH + lane_qa + (uint32_t)(i * 16 * ARS + ksi * 16) * 2);
                ldm_x4(aL[i], sb + AQL + lane_qa + (uint32_t)(i * 16 * ARS + ksi * 16) * 2);
            }
            ldm_x4_t(t, baseVh + lane_vt + (uint32_t)(ksi * 16 * ARS) * 2);
            bH[0][0] = t[0]; bH[0][1] = t[1]; bH[1][0] = t[2]; bH[1][1] = t[3];
            ldm_x4_t(t, baseVl + lane_vt + (uint32_t)(ksi * 16 * ARS) * 2);
            bL[0][0] = t[0]; bL[0][1] = t[1]; bL[1][0] = t[2]; bL[1][1] = t[3];
            #pragma unroll
            for (int i = 0; i < 2; i++)
                #pragma unroll
                for (int j = 0; j < 2; j++) {
                    mma_bf16(o[i][j], aH[i], bH[j]);
                    mma_bf16(o[i][j], aH[i], bL[j]);
                    mma_bf16(o[i][j], aL[i], bH[j]);
                }
        }
        __syncthreads();
    }

    if ((tid & 3) == 0) { rl[srow] = l_run; rsc[srow] = m_run; }
    __syncthreads();

    if (slot >= 0) {
        // partial output: unnormalized o (fp32) + per-row m, l
        float* pob = po + (size_t)slot * 4096;
        #pragma unroll
        for (int i = 0; i < 2; i++) {
            int r0 = wm * 32 + i * 16 + gid;
            int r1 = r0 + 8;
            #pragma unroll
            for (int j = 0; j < 2; j++) {
                int c = wn * 16 + j * 8 + tig * 2;
                *(float2*)(pob + r0 * 64 + c) = make_float2(o[i][j][0], o[i][j][1]);
                *(float2*)(pob + r1 * 64 + c) = make_float2(o[i][j][2], o[i][j][3]);
            }
        }
        if (tid < 64) {
            pmo[slot * 64 + tid] = rsc[tid];
            plo[slot * 64 + tid] = rl[tid];
        }
        return;
    }

    #pragma unroll
    for (int i = 0; i < 2; i++) {
        int r0 = wm * 32 + i * 16 + gid;
        int r1 = r0 + 8;
        float iv0 = mq[r0] / rl[r0];
        float iv1 = mq[r1] / rl[r1];
        #pragma unroll
        for (int j = 0; j < 2; j++) {
            int c = wn * 16 + j * 8 + tig * 2;
            float v0 = o[i][j][0] * iv0, v1 = o[i][j][1] * iv0;
            float v2 = o[i][j][2] * iv1, v3 = o[i][j][3] * iv1;
            __nv_bfloat162 h01 = __floats2bfloat162_rn(v0, v1);
            __nv_bfloat162 h23 = __floats2bfloat162_rn(v2, v3);
            __nv_bfloat162 l01 = __floats2bfloat162_rn(v0 - __bfloat162float(h01.x),
                                                       v1 - __bfloat162float(h01.y));
            __nv_bfloat162 l23 = __floats2bfloat162_rn(v2 - __bfloat162float(h23.x),
                                                       v3 - __bfloat162float(h23.y));
            size_t g0 = (size_t)(qb * 64 + r0) * DD + h * DHH + c;
            size_t g1 = (size_t)(qb * 64 + r1) * DD + h * DHH + c;
            *(uint32_t*)(oh + g0) = *(uint32_t*)&h01;
            *(uint32_t*)(ol + g0) = *(uint32_t*)&l01;
            *(uint32_t*)(oh + g1) = *(uint32_t*)&h23;
            *(uint32_t*)(ol + g1) = *(uint32_t*)&l23;
        }
    }
}

// ---------------- combine partials for full rows ----------------
__global__ void attn_combine(const float* __restrict__ po, const float* __restrict__ pm,
                             const float* __restrict__ pl, const float* __restrict__ mask,
                             __nv_bfloat16* __restrict__ oh, __nv_bfloat16* __restrict__ ol) {
    int cta = blockIdx.x;            // 0..23
    int h = cta >> 1;
    int qb = (cta & 1) ? (MM - 1) : 0;
    int sbase = h * 16 + (cta & 1) * 8;
    int tid = threadIdx.x;
    int r = tid >> 2, seg = (tid & 3) << 4;

    float mv[8];
    float m = -1e30f;
    #pragma unroll
    for (int p = 0; p < 8; p++) { mv[p] = pm[(sbase + p) * 64 + r]; m = fmaxf(m, mv[p]); }
    float wgt[8];
    float lsum = 0.f;
    #pragma unroll
    for (int p = 0; p < 8; p++) {
        wgt[p] = expf(mv[p] - m);
        lsum += pl[(sbase + p) * 64 + r] * wgt[p];
    }
    float inv = mask[qb * 64 + r] / lsum;

    #pragma unroll
    for (int d = 0; d < 16; d += 2) {
        float o0 = 0.f, o1 = 0.f;
        #pragma unroll
        for (int p = 0; p < 8; p++) {
            const float* src = po + ((size_t)(sbase + p) * 4096 + r * 64 + seg + d);
            o0 += src[0] * wgt[p];
            o1 += src[1] * wgt[p];
        }
        float v0 = o0 * inv, v1 = o1 * inv;
        __nv_bfloat162 hh = __floats2bfloat162_rn(v0, v1);
        __nv_bfloat162 lv = __floats2bfloat162_rn(v0 - __bfloat162float(hh.x),
                                                  v1 - __bfloat162float(hh.y));
        size_t g = (size_t)(qb * 64 + r) * DD + h * DHH + seg + d;
        *(uint32_t*)(oh + g) = *(uint32_t*)&hh;
        *(uint32_t*)(ol + g) = *(uint32_t*)&lv;
    }
}

// ---------------- host orchestration ----------------
extern "C" void kernel_launch(void* const* d_in, const int* in_sizes, int n_in,
                              void* d_out, int out_size) {
    (void)in_sizes; (void)n_in; (void)out_size;
    const int*   ids      = (const int*)  d_in[0];
    const float* mask     = (const float*)d_in[1];
    const int*   rand_attn= (const int*)  d_in[2];
    const float* emb_word = (const float*)d_in[3];
    const float* emb_pos  = (const float*)d_in[4];
    const float* eln_g    = (const float*)d_in[5];
    const float* eln_b    = (const float*)d_in[6];
    const float* Wq = (const float*)d_in[7];  const float* bq = (const float*)d_in[8];
    const float* Wk = (const float*)d_in[9];  const float* bk = (const float*)d_in[10];
    const float* Wv = (const float*)d_in[11]; const float* bv = (const float*)d_in[12];
    const float* Wo = (const float*)d_in[13]; const float* bo = (const float*)d_in[14];
    const float* ln1g = (const float*)d_in[15]; const float* ln1b = (const float*)d_in[16];
    const float* W1 = (const float*)d_in[17]; const float* b1 = (const float*)d_in[18];
    const float* W2 = (const float*)d_in[19]; const float* b2 = (const float*)d_in[20];
    const float* ln2g = (const float*)d_in[21]; const float* ln2b = (const float*)d_in[22];
    float* outp = (float*)d_out;

    float *px, *pt, *pbqkv, *ppo, *ppm, *ppl;
    __nv_bfloat16 *xh, *xl, *pqkvh, *pqkvl, *pah, *pal, *pfh, *pfl, *pwh, *pwl;
    int *pklist, *pkc;
    cudaGetSymbolAddress((void**)&px,  g_x);
    cudaGetSymbolAddress((void**)&pt,  g_t);
    cudaGetSymbolAddress((void**)&xh,  g_xh);   cudaGetSymbolAddress((void**)&xl,  g_xl);
    cudaGetSymbolAddress((void**)&pqkvh, g_qkvh); cudaGetSymbolAddress((void**)&pqkvl, g_qkvl);
    cudaGetSymbolAddress((void**)&pah, g_ah);   cudaGetSymbolAddress((void**)&pal, g_al);
    cudaGetSymbolAddress((void**)&pfh, g_fh);   cudaGetSymbolAddress((void**)&pfl, g_fl);
    cudaGetSymbolAddress((void**)&pwh, g_wTh);  cudaGetSymbolAddress((void**)&pwl, g_wTl);
    cudaGetSymbolAddress((void**)&pbqkv, g_bqkv);
    cudaGetSymbolAddress((void**)&pklist, g_klist);
    cudaGetSymbolAddress((void**)&pkc,    g_kcount);
    cudaGetSymbolAddress((void**)&ppo, g_po);
    cudaGetSymbolAddress((void**)&ppm, g_pm);
    cudaGetSymbolAddress((void**)&ppl, g_pl);

    cudaFuncSetAttribute(gemm_mma, cudaFuncAttributeMaxDynamicSharedMemorySize, GEMM_SMEM);
    cudaFuncSetAttribute(attn_mma, cudaFuncAttributeMaxDynamicSharedMemorySize, ATTN_SMEM_B);

    const size_t OQ = 0, OO = 1769472, O1 = 2359296, O2 = 4718592;

    dim3 gQKV(QKVS / 128, NN / 128);
    dim3 gProj(DD / 128, NN / 128);
    dim3 gF1(FFD / 128, NN / 128);
    dim3 gT768(DD / 32, DD / 32);
    dim3 gTQKV(QKVS / 32, DD / 32);

    // launch order: #4 (ncu capture position) = layer-0 QKV gemm_mma
    embed_ln<<<NN, 256>>>(ids, emb_word, emb_pos, eln_g, eln_b, px, xh, xl);          // 1
    bias_cat<<<(LL * QKVS + 255) / 256, 256>>>(bq, bk, bv, pbqkv);                    // 2
    wtrans_qkv<<<gTQKV, 256>>>(Wq, Wk, Wv, pwh + OQ, pwl + OQ);                       // 3
    gemm_mma<<<gQKV, 256, GEMM_SMEM>>>(xh, xl, pwh + OQ, pwl + OQ,
                                       pbqkv, nullptr, pqkvh, pqkvl, QKVS, DD, 0, 768); // 4 <- profiled
    build_klist<<<(HH * MM + 127) / 128, 128>>>(rand_attn, pklist, pkc);

    wtrans<<<gT768, 256>>>(Wo, pwh + OO, pwl + OO, DD, DD);
    wtrans<<<dim3(FFD/32, DD/32), 256>>>(W1, pwh + O1, pwl + O1, DD, FFD);
    wtrans<<<dim3(DD/32, FFD/32), 256>>>(W2, pwh + O2, pwl + O2, FFD, DD);
    for (int i = 1; i < LL; i++) {
        size_t lo = (size_t)i * WPL;
        wtrans_qkv<<<gTQKV, 256>>>(Wq + (size_t)i*DD*DD, Wk + (size_t)i*DD*DD, Wv + (size_t)i*DD*DD,
                                   pwh + lo + OQ, pwl + lo + OQ);
        wtrans<<<gT768, 256>>>(Wo + (size_t)i*DD*DD, pwh + lo + OO, pwl + lo + OO, DD, DD);
        wtrans<<<dim3(FFD/32, DD/32), 256>>>(W1 + (size_t)i*DD*FFD, pwh + lo + O1, pwl + lo + O1, DD, FFD);
        wtrans<<<dim3(DD/32, FFD/32), 256>>>(W2 + (size_t)i*FFD*DD, pwh + lo + O2, pwl + lo + O2, FFD, DD);
    }

    for (int i = 0; i < LL; i++) {
        size_t lo = (size_t)i * WPL;
        if (i > 0)
            gemm_mma<<<gQKV, 256, GEMM_SMEM>>>(xh, xl, pwh + lo + OQ, pwl + lo + OQ,
                                               pbqkv + (size_t)i * QKVS, nullptr, pqkvh, pqkvl, QKVS, DD, 0, 768);
        attn_mma<<<ATTN_GRID, 256, ATTN_SMEM_B>>>(pqkvh, pqkvl, mask, pklist, pkc,
                                                  pah, pal, ppo, ppm, ppl);
        attn_combine<<<24, 256>>>(ppo, ppm, ppl, mask, pah, pal);
        gemm_mma<<<gProj, 256, GEMM_SMEM>>>(pah, pal, pwh + lo + OO, pwl + lo + OO,
                                            bo + (size_t)i*DD, pt, nullptr, nullptr, DD, DD, 0, 0);
        ln_kernel<<<NN, 256>>>(px, pt, ln1g + (size_t)i*DD, ln1b + (size_t)i*DD, px, xh, xl);
        gemm_mma<<<gF1, 256, GEMM_SMEM>>>(xh, xl, pwh + lo + O1, pwl + lo + O1,
                                          b1 + (size_t)i*FFD, nullptr, pfh, pfl, FFD, DD, 1, 0);
        gemm_mma<<<gProj, 256, GEMM_SMEM>>>(pfh, pfl, pwh + lo + O2, pwl + lo + O2,
                                            b2 + (size_t)i*DD, pt, nullptr, nullptr, DD, FFD, 0, 0);
        if (i == LL - 1)
            ln_kernel<<<NN, 256>>>(px, pt, ln2g + (size_t)i*DD, ln2b + (size_t)i*DD, outp, nullptr, nullptr);
        else
            ln_kernel<<<NN, 256>>>(px, pt, ln2g + (size_t)i*DD, ln2b + (size_t)i*DD, px, xh, xl);
    }
}

// round 11
// speedup vs baseline: 14.2057x; 1.0394x over previous
#include <cuda_runtime.h>
#include <cuda_bf16.h>
#include <math.h>
#include <stdint.h>

// ---------------- problem constants ----------------
#define NN   4096
#define HH   12
#define DHH  64
#define DD   768
#define LL   4
#define FFD  3072
#define MM   64
#define RR   3
#define NEGV (-10000.0f)
#define QKVS 2304
#define ATTN_GRID 936
#define NSLOT 192

// ---------------- device scratch ----------------
__device__ float g_x [NN * DD];
__device__ float g_t [NN * DD];
__device__ __nv_bfloat16 g_xh[NN * DD],  g_xl[NN * DD];
__device__ __nv_bfloat16 g_qkvh[NN * QKVS], g_qkvl[NN * QKVS];
__device__ __nv_bfloat16 g_ah[NN * DD],  g_al[NN * DD];
__device__ __nv_bfloat16 g_fh[NN * FFD], g_fl[NN * FFD];
__device__ float g_bqkv[LL * QKVS];
__device__ int   g_klist [HH * MM * 64];
__device__ int   g_kcount[HH * MM];
__device__ float g_po[NSLOT * 64 * 64];
__device__ float g_pm[NSLOT * 64];
__device__ float g_pl[NSLOT * 64];
#define WPL 7077888ULL
__device__ __nv_bfloat16 g_wTh[LL * WPL];
__device__ __nv_bfloat16 g_wTl[LL * WPL];

// ---------------- asm helpers ----------------
__device__ __forceinline__ uint32_t smem_u32(const void* p) {
    uint32_t a;
    asm("{ .reg .u64 t; cvta.to.shared.u64 t, %1; cvt.u32.u64 %0, t; }" : "=r"(a) : "l"(p));
    return a;
}
__device__ __forceinline__ void cpa16(uint32_t dst, const void* src) {
    asm volatile("cp.async.cg.shared.global [%0], [%1], 16;" :: "r"(dst), "l"(src));
}
__device__ __forceinline__ void cpa_commit() { asm volatile("cp.async.commit_group;" ::: "memory"); }
__device__ __forceinline__ void cpa_wait0()  { asm volatile("cp.async.wait_group 0;" ::: "memory"); }
__device__ __forceinline__ void cpa_wait1()  { asm volatile("cp.async.wait_group 1;" ::: "memory"); }

__device__ __forceinline__ void mma_bf16(float* c, const uint32_t* a, const uint32_t* b) {
    asm volatile(
        "mma.sync.aligned.m16n8k16.row.col.f32.bf16.bf16.f32 "
        "{%0,%1,%2,%3}, {%4,%5,%6,%7}, {%8,%9}, {%0,%1,%2,%3};"
        : "+f"(c[0]), "+f"(c[1]), "+f"(c[2]), "+f"(c[3])
        : "r"(a[0]), "r"(a[1]), "r"(a[2]), "r"(a[3]), "r"(b[0]), "r"(b[1]));
}
__device__ __forceinline__ void ldm_x4(uint32_t* r, uint32_t addr) {
    asm volatile("ldmatrix.sync.aligned.m8n8.x4.shared.b16 {%0,%1,%2,%3}, [%4];"
        : "=r"(r[0]), "=r"(r[1]), "=r"(r[2]), "=r"(r[3]) : "r"(addr));
}
__device__ __forceinline__ void ldm_x4_t(uint32_t* r, uint32_t addr) {
    asm volatile("ldmatrix.sync.aligned.m8n8.x4.trans.shared.b16 {%0,%1,%2,%3}, [%4];"
        : "=r"(r[0]), "=r"(r[1]), "=r"(r[2]), "=r"(r[3]) : "r"(addr));
}

// ---------------- warp-per-row layernorm family ----------------
// 8 warps per CTA, each warp owns one token row (768 floats = 24/lane).
__device__ __forceinline__ void ln_row_core(const float* __restrict__ ar,
                                            const float* __restrict__ br,
                                            const float* __restrict__ g,
                                            const float* __restrict__ b,
                                            float* __restrict__ outf,
                                            __nv_bfloat16* __restrict__ outh,
                                            __nv_bfloat16* __restrict__ outl,
                                            int lane) {
    float v[24];
    float sum = 0.f;
    #pragma unroll
    for (int j = 0; j < 6; j++) {
        int idx = (lane + j * 32) * 4;
        float4 f = *(const float4*)(ar + idx);
        if (br) {
            float4 r = *(const float4*)(br + idx);
            f.x += r.x; f.y += r.y; f.z += r.z; f.w += r.w;
        }
        v[j*4+0] = f.x; v[j*4+1] = f.y; v[j*4+2] = f.z; v[j*4+3] = f.w;
        sum += f.x + f.y + f.z + f.w;
    }
    #pragma unroll
    for (int o = 16; o; o >>= 1) sum += __shfl_xor_sync(0xffffffffu, sum, o);
    float mu = sum * (1.0f / DD);
    float var = 0.f;
    #pragma unroll
    for (int j = 0; j < 24; j++) { float dv = v[j] - mu; var += dv * dv; }
    #pragma unroll
    for (int o = 16; o; o >>= 1) var += __shfl_xor_sync(0xffffffffu, var, o);
    float inv = rsqrtf(var * (1.0f / DD) + 1e-5f);
    #pragma unroll
    for (int j = 0; j < 6; j++) {
        int idx = (lane + j * 32) * 4;
        float4 gg = *(const float4*)(g + idx);
        float4 bb = *(const float4*)(b + idx);
        float o0 = (v[j*4+0] - mu) * inv * gg.x + bb.x;
        float o1 = (v[j*4+1] - mu) * inv * gg.y + bb.y;
        float o2 = (v[j*4+2] - mu) * inv * gg.z + bb.z;
        float o3 = (v[j*4+3] - mu) * inv * gg.w + bb.w;
        if (outf) *(float4*)(outf + idx) = make_float4(o0, o1, o2, o3);
        if (outh) {
            __nv_bfloat162 h01 = __floats2bfloat162_rn(o0, o1);
            __nv_bfloat162 h23 = __floats2bfloat162_rn(o2, o3);
            __nv_bfloat162 l01 = __floats2bfloat162_rn(o0 - __bfloat162float(h01.x),
                                                       o1 - __bfloat162float(h01.y));
            __nv_bfloat162 l23 = __floats2bfloat162_rn(o2 - __bfloat162float(h23.x),
                                                       o3 - __bfloat162float(h23.y));
            *(uint32_t*)(outh + idx)     = *(uint32_t*)&h01;
            *(uint32_t*)(outh + idx + 2) = *(uint32_t*)&h23;
            *(uint32_t*)(outl + idx)     = *(uint32_t*)&l01;
            *(uint32_t*)(outl + idx + 2) = *(uint32_t*)&l23;
        }
    }
}

__global__ void embed_ln(const int* __restrict__ ids,
                         const float* __restrict__ ew,
                         const float* __restrict__ ep,
                         const float* __restrict__ g,
                         const float* __restrict__ b,
                         float* __restrict__ outf,
                         __nv_bfloat16* __restrict__ outh,
                         __nv_bfloat16* __restrict__ outl) {
    int warp = threadIdx.x >> 5, lane = threadIdx.x & 31;
    int t = blockIdx.x * 8 + warp;
    int id = ids[t];
    // embed sum into registers via ln_row_core's residual path:
    ln_row_core(ew + (size_t)id * DD, ep + (size_t)t * DD, g, b,
                outf + (size_t)t * DD, outh + (size_t)t * DD, outl + (size_t)t * DD, lane);
}

__global__ void ln_kernel(const float* __restrict__ A,
                          const float* __restrict__ Bres,
                          const float* __restrict__ g,
                          const float* __restrict__ b,
                          float* __restrict__ outf,
                          __nv_bfloat16* __restrict__ outh,
                          __nv_bfloat16* __restrict__ outl) {
    int warp = threadIdx.x >> 5, lane = threadIdx.x & 31;
    int t = blockIdx.x * 8 + warp;
    ln_row_core(A + (size_t)t * DD,
                Bres ? (Bres + (size_t)t * DD) : nullptr, g, b,
                outf ? (outf + (size_t)t * DD) : nullptr,
                outh ? (outh + (size_t)t * DD) : nullptr,
                outl ? (outl + (size_t)t * DD) : nullptr, lane);
}

// ---------------- batched weight transpose (z = layer) ----------------
__global__ void wtrans(const float* __restrict__ W,
                       __nv_bfloat16* __restrict__ oh,
                       __nv_bfloat16* __restrict__ ol,
                       int K, int N) {
    __shared__ float sm[32][33];
    int layer = blockIdx.z;
    W  += (size_t)layer * K * N;
    oh += (size_t)layer * WPL;
    ol += (size_t)layer * WPL;
    int n0 = blockIdx.x * 32, k0 = blockIdx.y * 32;
    int tx = threadIdx.x & 31, ty = threadIdx.x >> 5;
    #pragma unroll
    for (int j = 0; j < 4; j++) {
        int kk = ty + j * 8;
        sm[kk][tx] = W[(size_t)(k0 + kk) * N + n0 + tx];
    }
    __syncthreads();
    #pragma unroll
    for (int j = 0; j < 4; j++) {
        int nn = ty + j * 8;
        float v = sm[tx][nn];
        __nv_bfloat16 h = __float2bfloat16(v);
        float r = v - __bfloat162float(h);
        size_t o = (size_t)(n0 + nn) * K + k0 + tx;
        oh[o] = h;
        ol[o] = __float2bfloat16(r);
    }
}

__global__ void wtrans_qkv(const float* __restrict__ Wq, const float* __restrict__ Wk,
                           const float* __restrict__ Wv,
                           __nv_bfloat16* __restrict__ oh, __nv_bfloat16* __restrict__ ol) {
    __shared__ float sm[32][33];
    int layer = blockIdx.z;
    size_t wofs = (size_t)layer * DD * DD;
    oh += (size_t)layer * WPL;
    ol += (size_t)layer * WPL;
    int n0 = blockIdx.x * 32, k0 = blockIdx.y * 32;
    const float* W = ((n0 < 768) ? Wq : (n0 < 1536) ? Wk : Wv) + wofs;
    int nl0 = n0 % 768;
    int tx = threadIdx.x & 31, ty = threadIdx.x >> 5;
    #pragma unroll
    for (int j = 0; j < 4; j++) {
        int kk = ty + j * 8;
        sm[kk][tx] = W[(size_t)(k0 + kk) * 768 + nl0 + tx];
    }
    __syncthreads();
    #pragma unroll
    for (int j = 0; j < 4; j++) {
        int nn = ty + j * 8;
        float v = sm[tx][nn];
        __nv_bfloat16 h = __float2bfloat16(v);
        float r = v - __bfloat162float(h);
        size_t o = (size_t)(n0 + nn) * DD + k0 + tx;
        oh[o] = h;
        ol[o] = __float2bfloat16(r);
    }
}

__global__ void bias_cat(const float* __restrict__ bq, const float* __restrict__ bk,
                         const float* __restrict__ bv, float* __restrict__ out) {
    int i = blockIdx.x * blockDim.x + threadIdx.x;
    if (i >= LL * QKVS) return;
    int l = i / QKVS, c = i % QKVS;
    float v;
    if (c < 768)       v = bq[l * 768 + c];
    else if (c < 1536) v = bk[l * 768 + c - 768];
    else               v = bv[l * 768 + c - 1536];
    out[i] = v;
}

// ---------------- HMMA GEMM (unchanged from R9/R10) ----------------
#define RS      72
#define TILE_B  (128 * RS * 2)
#define STAGE_B (2 * TILE_B)
#define GEMM_SMEM (3 * STAGE_B)

__global__ __launch_bounds__(256, 2)
void gemm_mma(const __nv_bfloat16* __restrict__ Agh, const __nv_bfloat16* __restrict__ Agl,
              const __nv_bfloat16* __restrict__ Bgh, const __nv_bfloat16* __restrict__ Bgl,
              const float* __restrict__ bias,
              float* __restrict__ Cf,
              __nv_bfloat16* __restrict__ Ch, __nv_bfloat16* __restrict__ Cl,
              int Nd, int K, int act, int qs_cols) {
    extern __shared__ __nv_bfloat16 smem[];
    uint32_t sb = smem_u32(smem);
    int tid = threadIdx.x;
    int m0 = blockIdx.y * 128, n0 = blockIdx.x * 128;
    int w = tid >> 5, l = tid & 31;
    int wm = w & 1, wn = w >> 1;
    int gid = l >> 2, tig = l & 3;

    uint32_t lane_a = (uint32_t)((wm * 64 + ((l >> 3) & 1) * 8 + (l & 7)) * RS + (l >> 4) * 8) * 2;
    uint32_t lane_b = (uint32_t)((wn * 32 + (l >> 4) * 8 + (l & 7)) * RS + ((l >> 3) & 1) * 8) * 2;

    float acc[4][4][4];
    #pragma unroll
    for (int i = 0; i < 4; i++)
        #pragma unroll
        for (int j = 0; j < 4; j++)
            #pragma unroll
            for (int r = 0; r < 4; r++) acc[i][j][r] = 0.f;

    int nchunk = K >> 5;

    auto load_chunk = [&](int c, int s) {
        int k0 = c << 5;
        uint32_t stg = sb + s * STAGE_B;
        #pragma unroll
        for (int i = 0; i < 2; i++) {
            int linear = tid + i * 256;
            int row = linear >> 2;
            int kc  = (linear & 3) << 3;
            uint32_t dhi = (uint32_t)(row * RS + kc) * 2;
            uint32_t dlo = (uint32_t)(row * RS + 32 + kc) * 2;
            size_t ga = (size_t)(m0 + row) * K + k0 + kc;
            cpa16(stg + dhi,          Agh + ga);
            cpa16(stg + dlo,          Agl + ga);
            size_t gb = (size_t)(n0 + row) * K + k0 + kc;
            cpa16(stg + TILE_B + dhi, Bgh + gb);
            cpa16(stg + TILE_B + dlo, Bgl + gb);
        }
    };

    load_chunk(0, 0); cpa_commit();
    load_chunk(1, 1); cpa_commit();

    for (int c = 0; c < nchunk; c++) {
        if (c + 1 < nchunk) cpa_wait1(); else cpa_wait0();
        __syncthreads();
        uint32_t base = sb + (c % 3) * STAGE_B;

        #pragma unroll
        for (int ks = 0; ks < 2; ks++) {
            uint32_t khi = (uint32_t)(ks * 16) * 2;
            uint32_t klo = (uint32_t)(32 + ks * 16) * 2;

            uint32_t aH[4][4], bH[4][2];
            #pragma unroll
            for (int i = 0; i < 4; i++)
                ldm_x4(aH[i], base + lane_a + (uint32_t)(i * 16 * RS) * 2 + khi);
            #pragma unroll
            for (int jj = 0; jj < 2; jj++) {
                uint32_t t[4];
                ldm_x4(t, base + TILE_B + lane_b + (uint32_t)(jj * 16 * RS) * 2 + khi);
                bH[2 * jj][0] = t[0]; bH[2 * jj][1] = t[1];
                bH[2 * jj + 1][0] = t[2]; bH[2 * jj + 1][1] = t[3];
            }
            #pragma unroll
            for (int i = 0; i < 4; i++)
                #pragma unroll
                for (int j = 0; j < 4; j++)
                    mma_bf16(acc[i][j], aH[i], bH[j]);

            uint32_t bL[4][2];
            #pragma unroll
            for (int jj = 0; jj < 2; jj++) {
                uint32_t t[4];
                ldm_x4(t, base + TILE_B + lane_b + (uint32_t)(jj * 16 * RS) * 2 + klo);
                bL[2 * jj][0] = t[0]; bL[2 * jj][1] = t[1];
                bL[2 * jj + 1][0] = t[2]; bL[2 * jj + 1][1] = t[3];
            }
            #pragma unroll
            for (int i = 0; i < 4; i++)
                #pragma unroll
                for (int j = 0; j < 4; j++)
                    mma_bf16(acc[i][j], aH[i], bL[j]);

            uint32_t aL[4][4];
            #pragma unroll
            for (int i = 0; i < 4; i++)
                ldm_x4(aL[i], base + lane_a + (uint32_t)(i * 16 * RS) * 2 + klo);
            #pragma unroll
            for (int i = 0; i < 4; i++)
                #pragma unroll
                for (int j = 0; j < 4; j++)
                    mma_bf16(acc[i][j], aL[i], bH[j]);
        }
        if (c + 2 < nchunk) load_chunk(c + 2, (c + 2) % 3);
        cpa_commit();
    }

    #pragma unroll
    for (int i = 0; i < 4; i++) {
        int row = m0 + wm * 64 + i * 16 + gid;
        #pragma unroll
        for (int j = 0; j < 4; j++) {
            int col = n0 + wn * 32 + j * 8 + tig * 2;
            float b0 = bias[col], b1 = bias[col + 1];
            float v0 = acc[i][j][0] + b0;
            float v1 = acc[i][j][1] + b1;
            float v2 = acc[i][j][2] + b0;
            float v3 = acc[i][j][3] + b1;
            if (col < qs_cols) { v0 *= 0.125f; v1 *= 0.125f; v2 *= 0.125f; v3 *= 0.125f; }
            if (act) {
                v0 = 0.5f * v0 * (1.0f + erff(v0 * 0.70710678118654752f));
                v1 = 0.5f * v1 * (1.0f + erff(v1 * 0.70710678118654752f));
                v2 = 0.5f * v2 * (1.0f + erff(v2 * 0.70710678118654752f));
                v3 = 0.5f * v3 * (1.0f + erff(v3 * 0.70710678118654752f));
            }
            if (Cf) {
                *(float2*)(Cf + (size_t)row * Nd + col)       = make_float2(v0, v1);
                *(float2*)(Cf + (size_t)(row + 8) * Nd + col) = make_float2(v2, v3);
            } else {
                __nv_bfloat162 h01 = __floats2bfloat162_rn(v0, v1);
                __nv_bfloat162 h23 = __floats2bfloat162_rn(v2, v3);
                __nv_bfloat162 l01 = __floats2bfloat162_rn(v0 - __bfloat162float(h01.x),
                                                           v1 - __bfloat162float(h01.y));
                __nv_bfloat162 l23 = __floats2bfloat162_rn(v2 - __bfloat162float(h23.x),
                                                           v3 - __bfloat162float(h23.y));
                *(uint32_t*)(Ch + (size_t)row * Nd + col)       = *(uint32_t*)&h01;
                *(uint32_t*)(Cl + (size_t)row * Nd + col)       = *(uint32_t*)&l01;
                *(uint32_t*)(Ch + (size_t)(row + 8) * Nd + col) = *(uint32_t*)&h23;
                *(uint32_t*)(Cl + (size_t)(row + 8) * Nd + col) = *(uint32_t*)&l23;
            }
        }
    }
}

// ---------------- key-block list ----------------
__global__ void build_klist(const int* __restrict__ rand_attn,
                            int* __restrict__ klist,
                            int* __restrict__ kcount) {
    int idx = blockIdx.x * blockDim.x + threadIdx.x;
    if (idx >= HH * MM) return;
    int h  = idx / MM;
    int qb = idx % MM;
    int* lst = klist + idx * 64;
    int c = 0;
    if (qb == 0 || qb == MM - 1) {
        for (int j = 0; j < MM; j++) lst[c++] = j;
    } else if (qb == 1) {
        lst[c++] = 0; lst[c++] = 1; lst[c++] = 2; lst[c++] = MM - 1;
        const int* rr = rand_attn + ((size_t)h * (MM - 2) + 0) * RR;
        for (int r = 0; r < RR; r++) lst[c++] = rr[r] | 256;
    } else if (qb == MM - 2) {
        lst[c++] = 0; lst[c++] = MM - 3; lst[c++] = MM - 2; lst[c++] = MM - 1;
        const int* rr = rand_attn + ((size_t)h * (MM - 2) + (MM - 3)) * RR;
        for (int r = 0; r < RR; r++) lst[c++] = rr[r] | 256;
    } else {
        lst[c++] = 0;
        lst[c++] = (qb - 1) | 256;
        lst[c++] = qb | 256;
        lst[c++] = (qb + 1) | 256;
        const int* rr = rand_attn + ((size_t)h * (MM - 2) + (qb - 1)) * RR;
        for (int r = 0; r < RR; r++) lst[c++] = rr[r] | 256;
        lst[c++] = MM - 1;
    }
    kcount[idx] = c;
}

// ---------------- HMMA flash attention with full-row splitting (unchanged) -----
#define ARS  72
#define AQH  0
#define AQL  9216
#define AK0  18432
#define AV0  55296
#define ASS  92160
#define AMQ  109568
#define AMK  109824
#define ARSC 110080
#define ARL  110336
#define AENT 110592
#define ATTN_SMEM_B 110848

__global__ __launch_bounds__(256, 2)
void attn_mma(const __nv_bfloat16* __restrict__ qkvh, const __nv_bfloat16* __restrict__ qkvl,
              const float* __restrict__ mask,
              const int* __restrict__ klist, const int* __restrict__ kcount,
              __nv_bfloat16* __restrict__ oh, __nv_bfloat16* __restrict__ ol,
              float* __restrict__ po, float* __restrict__ pmo, float* __restrict__ plo) {
    extern __shared__ char sm[];
    uint32_t sb = smem_u32(sm);
    float* Ss  = (float*)(sm + ASS);
    float* mq  = (float*)(sm + AMQ);
    float* mk  = (float*)(sm + AMK);
    float* rsc = (float*)(sm + ARSC);
    float* rl  = (float*)(sm + ARL);
    int*   ents= (int*)(sm + AENT);
    __nv_bfloat16* Ph = (__nv_bfloat16*)(sm + AQH);
    __nv_bfloat16* Pl = (__nv_bfloat16*)(sm + AQL);

    const __nv_bfloat16* qh = qkvh;
    const __nv_bfloat16* ql = qkvl;
    const __nv_bfloat16* kh = qkvh + 768;
    const __nv_bfloat16* kl = qkvl + 768;
    const __nv_bfloat16* vh = qkvh + 1536;
    const __nv_bfloat16* vl = qkvl + 1536;

    int item = blockIdx.x;
    int h, qb, bstart, bcnt, slot;
    if (item < 744) {
        h = item / 62;
        qb = 1 + item % 62;
        bstart = 0;
        slot = -1;
        bcnt = kcount[h * MM + qb];
    } else {
        int j = item - 744;
        h = j >> 4;
        int rest = j & 15;
        qb = (rest < 8) ? 0 : (MM - 1);
        int seg = rest & 7;
        bstart = seg * 8;
        bcnt = 8;
        slot = j;
    }
    int lid = h * MM + qb;

    int tid = threadIdx.x;
    int w = tid >> 5, l = tid & 31;
    int wm = w & 1, wn = w >> 1;
    int gid = l >> 2, tig = l & 3;
    int srow = tid >> 2, sseg = (tid & 3) << 4;

    uint32_t lane_qa = (uint32_t)((wm * 32 + ((l >> 3) & 1) * 8 + (l & 7)) * ARS + (l >> 4) * 8) * 2;
    uint32_t lane_kb = (uint32_t)((wn * 16 + (l >> 4) * 8 + (l & 7)) * ARS + ((l >> 3) & 1) * 8) * 2;
    uint32_t lane_vt = (uint32_t)((((l >> 3) & 1) * 8 + (l & 7)) * ARS + wn * 16 + (l >> 4) * 8) * 2;

    if (tid < 64) {
        ents[tid] = klist[lid * 64 + tid];
        mq[tid]   = mask[qb * 64 + tid];
    }

    auto load_kv = [&](int kb, int s) {
        uint32_t bk_ = sb + AK0 + s * 18432;
        uint32_t bv_ = sb + AV0 + s * 18432;
        #pragma unroll
        for (int i = 0; i < 2; i++) {
            int linear = tid + i * 256;
            int r = linear >> 3, c8 = (linear & 7) << 3;
            uint32_t doff = (uint32_t)(r * ARS + c8) * 2;
            size_t g = (size_t)(kb * 64 + r) * QKVS + h * DHH + c8;
            cpa16(bk_ + doff,        kh + g);
            cpa16(bk_ + 9216 + doff, kl + g);
            cpa16(bv_ + doff,        vh + g);
            cpa16(bv_ + 9216 + doff, vl + g);
        }
    };

    #pragma unroll
    for (int i = 0; i < 2; i++) {
        int linear = tid + i * 256;
        int r = linear >> 3, c8 = (linear & 7) << 3;
        uint32_t doff = (uint32_t)(r * ARS + c8) * 2;
        size_t g = (size_t)(qb * 64 + r) * QKVS + h * DHH + c8;
        cpa16(sb + AQH + doff, qh + g);
        cpa16(sb + AQL + doff, ql + g);
    }
    __syncthreads();
    load_kv(ents[bstart] & 0xff, 0);
    cpa_commit();
    cpa_wait0();
    __syncthreads();

    uint32_t qfh[2][4][4], qfl[2][4][4];
    #pragma unroll
    for (int i = 0; i < 2; i++)
        #pragma unroll
        for (int ksi = 0; ksi < 4; ksi++) {
            ldm_x4(qfh[i][ksi], sb + AQH + lane_qa + (uint32_t)(i * 16 * ARS + ksi * 16) * 2);
            ldm_x4(qfl[i][ksi], sb + AQL + lane_qa + (uint32_t)(i * 16 * ARS + ksi * 16) * 2);
        }

    float m_run = -1e30f, l_run = 0.f;
    float o[2][2][4];
    #pragma unroll
    for (int i = 0; i < 2; i++)
        #pragma unroll
        for (int j = 0; j < 2; j++)
            #pragma unroll
            for (int r = 0; r < 4; r++) o[i][j][r] = 0.f;

    for (int b = 0; b < bcnt; b++) {
        int e = ents[bstart + b], kb = e & 0xff, fl = e >> 8;
        if (b > 0) { cpa_wait0(); __syncthreads(); }
        if (b + 1 < bcnt) { load_kv(ents[bstart + b + 1] & 0xff, (b + 1) & 1); cpa_commit(); }
        if (tid < 64) mk[tid] = mask[kb * 64 + tid];

        uint32_t baseKh = sb + AK0 + (b & 1) * 18432;
        uint32_t baseKl = baseKh + 9216;
        uint32_t baseVh = sb + AV0 + (b & 1) * 18432;
        uint32_t baseVl = baseVh + 9216;

        float sa[2][2][4];
        #pragma unroll
        for (int i = 0; i < 2; i++)
            #pragma unroll
            for (int j = 0; j < 2; j++)
                #pragma unroll
                for (int r = 0; r < 4; r++) sa[i][j][r] = 0.f;
        #pragma unroll
        for (int ksi = 0; ksi < 4; ksi++) {
            uint32_t bH[2][2], bL[2][2], t[4];
            ldm_x4(t, baseKh + lane_kb + (uint32_t)(ksi * 16) * 2);
            bH[0][0] = t[0]; bH[0][1] = t[1]; bH[1][0] = t[2]; bH[1][1] = t[3];
            ldm_x4(t, baseKl + lane_kb + (uint32_t)(ksi * 16) * 2);
            bL[0][0] = t[0]; bL[0][1] = t[1]; bL[1][0] = t[2]; bL[1][1] = t[3];
            #pragma unroll
            for (int i = 0; i < 2; i++)
                #pragma unroll
                for (int j = 0; j < 2; j++) {
                    mma_bf16(sa[i][j], qfh[i][ksi], bH[j]);
                    mma_bf16(sa[i][j], qfh[i][ksi], bL[j]);
                    mma_bf16(sa[i][j], qfl[i][ksi], bH[j]);
                }
        }
        #pragma unroll
        for (int i = 0; i < 2; i++) {
            int r = wm * 32 + i * 16 + gid;
            #pragma unroll
            for (int j = 0; j < 2; j++) {
                int c = wn * 16 + j * 8 + tig * 2;
                Ss[r * 68 + c]           = sa[i][j][0];
                Ss[r * 68 + c + 1]       = sa[i][j][1];
                Ss[(r + 8) * 68 + c]     = sa[i][j][2];
                Ss[(r + 8) * 68 + c + 1] = sa[i][j][3];
            }
        }
        __syncthreads();

        float mqv = mq[srow];
        float sv[16];
        #pragma unroll
        for (int j = 0; j < 16; j += 4) {
            float4 f = *(float4*)(Ss + srow * 68 + sseg + j);
            sv[j] = f.x; sv[j+1] = f.y; sv[j+2] = f.z; sv[j+3] = f.w;
        }
        #pragma unroll
        for (int j = 0; j < 16; j++) {
            float mkv = mk[sseg + j];
            float eff = fl ? (mqv * mkv) : mkv;
            sv[j] += (1.0f - eff) * NEGV;
        }
        float lm = sv[0];
        #pragma unroll
        for (int j = 1; j < 16; j++) lm = fmaxf(lm, sv[j]);
        lm = fmaxf(lm, __shfl_xor_sync(0xffffffffu, lm, 1));
        lm = fmaxf(lm, __shfl_xor_sync(0xffffffffu, lm, 2));
        float m_new = fmaxf(m_run, lm);
        float sc = expf(m_run - m_new);
        float ls = 0.f;
        #pragma unroll
        for (int j = 0; j < 16; j += 2) {
            float p0 = expf(sv[j]     - m_new);
            float p1 = expf(sv[j + 1] - m_new);
            ls += p0 + p1;
            __nv_bfloat162 hh = __floats2bfloat162_rn(p0, p1);
            __nv_bfloat162 lv = __floats2bfloat162_rn(p0 - __bfloat162float(hh.x),
                                                      p1 - __bfloat162float(hh.y));
            *(uint32_t*)(Ph + srow * ARS + sseg + j) = *(uint32_t*)&hh;
            *(uint32_t*)(Pl + srow * ARS + sseg + j) = *(uint32_t*)&lv;
        }
        ls += __shfl_xor_sync(0xffffffffu, ls, 1);
        ls += __shfl_xor_sync(0xffffffffu, ls, 2);
        l_run = l_run * sc + ls;
        m_run = m_new;
        if ((tid & 3) == 0) rsc[srow] = sc;
        __syncthreads();

        #pragma unroll
        for (int i = 0; i < 2; i++) {
            float s0 = rsc[wm * 32 + i * 16 + gid];
            float s1 = rsc[wm * 32 + i * 16 + gid + 8];
            #pragma unroll
            for (int j = 0; j < 2; j++) {
                o[i][j][0] *= s0; o[i][j][1] *= s0;
                o[i][j][2] *= s1; o[i][j][3] *= s1;
            }
        }
        #pragma unroll
        for (int ksi = 0; ksi < 4; ksi++) {
            uint32_t aH[2][4], aL[2][4], bH[2][2], bL[2][2], t[4];
            #pragma unroll
            for (int i = 0; i < 2; i++) {
                ldm_x4(aH[i], sb + AQH + lane_qa + (uint32_t)(i * 16 * ARS + ksi * 16) * 2);
                ldm_x4(aL[i], sb + AQL + lane_qa + (uint32_t)(i * 16 * ARS + ksi * 16) * 2);
            }
            ldm_x4_t(t, baseVh + lane_vt + (uint32_t)(ksi * 16 * ARS) * 2);
            bH[0][0] = t[0]; bH[0][1] = t[1]; bH[1][0] = t[2]; bH[1][1] = t[3];
            ldm_x4_t(t, baseVl + lane_vt + (uint32_t)(ksi * 16 * ARS) * 2);
            bL[0][0] = t[0]; bL[0][1] = t[1]; bL[1][0] = t[2]; bL[1][1] = t[3];
            #pragma unroll
            for (int i = 0; i < 2; i++)
                #pragma unroll
                for (int j = 0; j < 2; j++) {
                    mma_bf16(o[i][j], aH[i], bH[j]);
                    mma_bf16(o[i][j], aH[i], bL[j]);
                    mma_bf16(o[i][j], aL[i], bH[j]);
                }
        }
        __syncthreads();
    }

    if ((tid & 3) == 0) { rl[srow] = l_run; rsc[srow] = m_run; }
    __syncthreads();

    if (slot >= 0) {
        float* pob = po + (size_t)slot * 4096;
        #pragma unroll
        for (int i = 0; i < 2; i++) {
            int r0 = wm * 32 + i * 16 + gid;
            int r1 = r0 + 8;
            #pragma unroll
            for (int j = 0; j < 2; j++) {
                int c = wn * 16 + j * 8 + tig * 2;
                *(float2*)(pob + r0 * 64 + c) = make_float2(o[i][j][0], o[i][j][1]);
                *(float2*)(pob + r1 * 64 + c) = make_float2(o[i][j][2], o[i][j][3]);
            }
        }
        if (tid < 64) {
            pmo[slot * 64 + tid] = rsc[tid];
            plo[slot * 64 + tid] = rl[tid];
        }
        return;
    }

    #pragma unroll
    for (int i = 0; i < 2; i++) {
        int r0 = wm * 32 + i * 16 + gid;
        int r1 = r0 + 8;
        float iv0 = mq[r0] / rl[r0];
        float iv1 = mq[r1] / rl[r1];
        #pragma unroll
        for (int j = 0; j < 2; j++) {
            int c = wn * 16 + j * 8 + tig * 2;
            float v0 = o[i][j][0] * iv0, v1 = o[i][j][1] * iv0;
            float v2 = o[i][j][2] * iv1, v3 = o[i][j][3] * iv1;
            __nv_bfloat162 h01 = __floats2bfloat162_rn(v0, v1);
            __nv_bfloat162 h23 = __floats2bfloat162_rn(v2, v3);
            __nv_bfloat162 l01 = __floats2bfloat162_rn(v0 - __bfloat162float(h01.x),
                                                       v1 - __bfloat162float(h01.y));
            __nv_bfloat162 l23 = __floats2bfloat162_rn(v2 - __bfloat162float(h23.x),
                                                       v3 - __bfloat162float(h23.y));
            size_t g0 = (size_t)(qb * 64 + r0) * DD + h * DHH + c;
            size_t g1 = (size_t)(qb * 64 + r1) * DD + h * DHH + c;
            *(uint32_t*)(oh + g0) = *(uint32_t*)&h01;
            *(uint32_t*)(ol + g0) = *(uint32_t*)&l01;
            *(uint32_t*)(oh + g1) = *(uint32_t*)&h23;
            *(uint32_t*)(ol + g1) = *(uint32_t*)&l23;
        }
    }
}

// ---------------- combine partials for full rows ----------------
__global__ void attn_combine(const float* __restrict__ po, const float* __restrict__ pm,
                             const float* __restrict__ pl, const float* __restrict__ mask,
                             __nv_bfloat16* __restrict__ oh, __nv_bfloat16* __restrict__ ol) {
    int cta = blockIdx.x;
    int h = cta >> 1;
    int qb = (cta & 1) ? (MM - 1) : 0;
    int sbase = h * 16 + (cta & 1) * 8;
    int tid = threadIdx.x;
    int r = tid >> 2, seg = (tid & 3) << 4;

    float mv[8];
    float m = -1e30f;
    #pragma unroll
    for (int p = 0; p < 8; p++) { mv[p] = pm[(sbase + p) * 64 + r]; m = fmaxf(m, mv[p]); }
    float wgt[8];
    float lsum = 0.f;
    #pragma unroll
    for (int p = 0; p < 8; p++) {
        wgt[p] = expf(mv[p] - m);
        lsum += pl[(sbase + p) * 64 + r] * wgt[p];
    }
    float inv = mask[qb * 64 + r] / lsum;

    #pragma unroll
    for (int d = 0; d < 16; d += 2) {
        float o0 = 0.f, o1 = 0.f;
        #pragma unroll
        for (int p = 0; p < 8; p++) {
            const float* src = po + ((size_t)(sbase + p) * 4096 + r * 64 + seg + d);
            o0 += src[0] * wgt[p];
            o1 += src[1] * wgt[p];
        }
        float v0 = o0 * inv, v1 = o1 * inv;
        __nv_bfloat162 hh = __floats2bfloat162_rn(v0, v1);
        __nv_bfloat162 lv = __floats2bfloat162_rn(v0 - __bfloat162float(hh.x),
                                                  v1 - __bfloat162float(hh.y));
        size_t g = (size_t)(qb * 64 + r) * DD + h * DHH + seg + d;
        *(uint32_t*)(oh + g) = *(uint32_t*)&hh;
        *(uint32_t*)(ol + g) = *(uint32_t*)&lv;
    }
}

// ---------------- host orchestration ----------------
extern "C" void kernel_launch(void* const* d_in, const int* in_sizes, int n_in,
                              void* d_out, int out_size) {
    (void)in_sizes; (void)n_in; (void)out_size;
    const int*   ids      = (const int*)  d_in[0];
    const float* mask     = (const float*)d_in[1];
    const int*   rand_attn= (const int*)  d_in[2];
    const float* emb_word = (const float*)d_in[3];
    const float* emb_pos  = (const float*)d_in[4];
    const float* eln_g    = (const float*)d_in[5];
    const float* eln_b    = (const float*)d_in[6];
    const float* Wq = (const float*)d_in[7];  const float* bq = (const float*)d_in[8];
    const float* Wk = (const float*)d_in[9];  const float* bk = (const float*)d_in[10];
    const float* Wv = (const float*)d_in[11]; const float* bv = (const float*)d_in[12];
    const float* Wo = (const float*)d_in[13]; const float* bo = (const float*)d_in[14];
    const float* ln1g = (const float*)d_in[15]; const float* ln1b = (const float*)d_in[16];
    const float* W1 = (const float*)d_in[17]; const float* b1 = (const float*)d_in[18];
    const float* W2 = (const float*)d_in[19]; const float* b2 = (const float*)d_in[20];
    const float* ln2g = (const float*)d_in[21]; const float* ln2b = (const float*)d_in[22];
    float* outp = (float*)d_out;

    float *px, *pt, *pbqkv, *ppo, *ppm, *ppl;
    __nv_bfloat16 *xh, *xl, *pqkvh, *pqkvl, *pah, *pal, *pfh, *pfl, *pwh, *pwl;
    int *pklist, *pkc;
    cudaGetSymbolAddress((void**)&px,  g_x);
    cudaGetSymbolAddress((void**)&pt,  g_t);
    cudaGetSymbolAddress((void**)&xh,  g_xh);   cudaGetSymbolAddress((void**)&xl,  g_xl);
    cudaGetSymbolAddress((void**)&pqkvh, g_qkvh); cudaGetSymbolAddress((void**)&pqkvl, g_qkvl);
    cudaGetSymbolAddress((void**)&pah, g_ah);   cudaGetSymbolAddress((void**)&pal, g_al);
    cudaGetSymbolAddress((void**)&pfh, g_fh);   cudaGetSymbolAddress((void**)&pfl, g_fl);
    cudaGetSymbolAddress((void**)&pwh, g_wTh);  cudaGetSymbolAddress((void**)&pwl, g_wTl);
    cudaGetSymbolAddress((void**)&pbqkv, g_bqkv);
    cudaGetSymbolAddress((void**)&pklist, g_klist);
    cudaGetSymbolAddress((void**)&pkc,    g_kcount);
    cudaGetSymbolAddress((void**)&ppo, g_po);
    cudaGetSymbolAddress((void**)&ppm, g_pm);
    cudaGetSymbolAddress((void**)&ppl, g_pl);

    cudaFuncSetAttribute(gemm_mma, cudaFuncAttributeMaxDynamicSharedMemorySize, GEMM_SMEM);
    cudaFuncSetAttribute(attn_mma, cudaFuncAttributeMaxDynamicSharedMemorySize, ATTN_SMEM_B);

    const size_t OQ = 0, OO = 1769472, O1 = 2359296, O2 = 4718592;

    dim3 gQKV(QKVS / 128, NN / 128);
    dim3 gProj(DD / 128, NN / 128);
    dim3 gF1(FFD / 128, NN / 128);
    dim3 gLN(NN / 8);
    dim3 gTQKV(QKVS / 32, DD / 32, LL);

    // launch order: #4 (ncu capture position) = layer-0 QKV gemm_mma
    embed_ln<<<gLN, 256>>>(ids, emb_word, emb_pos, eln_g, eln_b, px, xh, xl);         // 1
    bias_cat<<<(LL * QKVS + 255) / 256, 256>>>(bq, bk, bv, pbqkv);                    // 2
    wtrans_qkv<<<gTQKV, 256>>>(Wq, Wk, Wv, pwh + OQ, pwl + OQ);                       // 3 (all layers)
    gemm_mma<<<gQKV, 256, GEMM_SMEM>>>(xh, xl, pwh + OQ, pwl + OQ,
                                       pbqkv, nullptr, pqkvh, pqkvl, QKVS, DD, 0, 768); // 4 <- profiled
    build_klist<<<(HH * MM + 127) / 128, 128>>>(rand_attn, pklist, pkc);

    wtrans<<<dim3(DD/32, DD/32, LL), 256>>>(Wo, pwh + OO, pwl + OO, DD, DD);
    wtrans<<<dim3(FFD/32, DD/32, LL), 256>>>(W1, pwh + O1, pwl + O1, DD, FFD);
    wtrans<<<dim3(DD/32, FFD/32, LL), 256>>>(W2, pwh + O2, pwl + O2, FFD, DD);

    for (int i = 0; i < LL; i++) {
        size_t lo = (size_t)i * WPL;
        if (i > 0)
            gemm_mma<<<gQKV, 256, GEMM_SMEM>>>(xh, xl, pwh + lo + OQ, pwl + lo + OQ,
                                               pbqkv + (size_t)i * QKVS, nullptr, pqkvh, pqkvl, QKVS, DD, 0, 768);
        attn_mma<<<ATTN_GRID, 256, ATTN_SMEM_B>>>(pqkvh, pqkvl, mask, pklist, pkc,
                                                  pah, pal, ppo, ppm, ppl);
        attn_combine<<<24, 256>>>(ppo, ppm, ppl, mask, pah, pal);
        gemm_mma<<<gProj, 256, GEMM_SMEM>>>(pah, pal, pwh + lo + OO, pwl + lo + OO,
                                            bo + (size_t)i*DD, pt, nullptr, nullptr, DD, DD, 0, 0);
        ln_kernel<<<gLN, 256>>>(px, pt, ln1g + (size_t)i*DD, ln1b + (size_t)i*DD, px, xh, xl);
        gemm_mma<<<gF1, 256, GEMM_SMEM>>>(xh, xl, pwh + lo + O1, pwl + lo + O1,
                                          b1 + (size_t)i*FFD, nullptr, pfh, pfl, FFD, DD, 1, 0);
        gemm_mma<<<gProj, 256, GEMM_SMEM>>>(pfh, pfl, pwh + lo + O2, pwl + lo + O2,
                                            b2 + (size_t)i*DD, pt, nullptr, nullptr, DD, FFD, 0, 0);
        if (i == LL - 1)
            ln_kernel<<<gLN, 256>>>(px, pt, ln2g + (size_t)i*DD, ln2b + (size_t)i*DD, outp, nullptr, nullptr);
        else
            ln_kernel<<<gLN, 256>>>(px, pt, ln2g + (size_t)i*DD, ln2b + (size_t)i*DD, px, xh, xl);
    }
}